// round 1
// baseline (speedup 1.0000x reference)
#include <cuda_runtime.h>
#include <math.h>

#define L_SEQ   32768
#define HDIM    256
#define PDIM    128
#define NLAYERS 4
#define NCHUNK  256
#define TCHUNK  128

// ---------------- scratch (static __device__, no allocation) ----------------
__device__ float  g_x [L_SEQ*HDIM];
__device__ float  g_h [L_SEQ*HDIM];
__device__ float  g_bu[L_SEQ*HDIM];
__device__ float  g_xs[L_SEQ*HDIM];
__device__ float  g_t1[L_SEQ*HDIM];
__device__ float  g_t2[L_SEQ*HDIM];
__device__ float  g_Wb[NLAYERS][HDIM*HDIM];
__device__ float  g_Wc[NLAYERS][HDIM*HDIM];
__device__ float2 g_lam [NLAYERS][PDIM];
__device__ float2 g_lamT[NLAYERS][PDIM];
__device__ float2 g_E [NCHUNK*PDIM];
__device__ float2 g_Hc[NCHUNK*PDIM];
__device__ float  g_x0[HDIM];

// ---------------- setup: latent expand + leaky_relu ----------------
__global__ void expand_kernel(const float* __restrict__ latent,
                              const float* __restrict__ W,
                              const float* __restrict__ b)
{
    int h = threadIdx.x;
    float s = 0.f;
    for (int l = 0; l < HDIM; l++) s += latent[l] * W[l*HDIM + h];
    s += b[h];
    g_x0[h] = s > 0.f ? s : 0.01f * s;
}

__global__ void broadcast_kernel()
{
    size_t n = (size_t)L_SEQ * HDIM;
    for (size_t i = (size_t)blockIdx.x*blockDim.x + threadIdx.x; i < n;
         i += (size_t)gridDim.x*blockDim.x)
        g_x[i] = g_x0[i & (HDIM-1)];
}

// ---------------- setup: per-layer derived parameters ----------------
// lam_bar = exp((Lre + i Lim)*step); lamT = lam_bar^128
// Wb[k][n]: n in [0,128)=re(p), [128,256)=im(p); k = input feature h
//   B_bar = (lam_bar-1)/Lambda * (Bre + i Bim)
// Wc[k][n]: k in [0,128)=re(p), [128,256)=im(p); n = output feature h
//   Wc[p][h] = 2*Cre[h][p], Wc[128+p][h] = -2*Cim[h][p]
__global__ void setup_params(const float* __restrict__ Lre, const float* __restrict__ Lim,
                             const float* __restrict__ Bre, const float* __restrict__ Bim,
                             const float* __restrict__ Cre, const float* __restrict__ Cim,
                             const float* __restrict__ log_step)
{
    int layer = blockIdx.x;
    int p = threadIdx.x;                 // 128 threads
    float step = expf(log_step[layer*PDIM + p]);
    float lr = Lre[layer*PDIM + p], li = Lim[layer*PDIM + p];
    float er  = expf(lr*step);
    float lbr = er * cosf(li*step);
    float lbi = er * sinf(li*step);
    g_lam[layer][p] = make_float2(lbr, lbi);
    // lam_bar^128 via 7 squarings
    float tr = lbr, ti = lbi;
    #pragma unroll
    for (int i = 0; i < 7; i++) { float nr = tr*tr - ti*ti; ti = 2.f*tr*ti; tr = nr; }
    g_lamT[layer][p] = make_float2(tr, ti);
    // f = (lam_bar - 1) / (lr + i li)
    float nr = lbr - 1.f, ni = lbi;
    float den = lr*lr + li*li;
    float fr = (nr*lr + ni*li) / den;
    float fi = (ni*lr - nr*li) / den;
    const float* brp = Bre + ((size_t)layer*PDIM + p)*HDIM;
    const float* bip = Bim + ((size_t)layer*PDIM + p)*HDIM;
    for (int h = 0; h < HDIM; h++) {
        float br = brp[h], bi = bip[h];
        g_Wb[layer][h*HDIM + p]        = fr*br - fi*bi;
        g_Wb[layer][h*HDIM + PDIM + p] = fr*bi + fi*br;
        g_Wc[layer][p*HDIM + h]          =  2.f * Cre[((size_t)layer*HDIM + h)*PDIM + p];
        g_Wc[layer][(PDIM + p)*HDIM + h] = -2.f * Cim[((size_t)layer*HDIM + h)*PDIM + p];
    }
}

// ---------------- LayerNorm (warp per row), optional gelu(tanh) ----------------
__global__ void ln_act_kernel(const float* __restrict__ X, float* __restrict__ Y,
                              const float* __restrict__ scale, const float* __restrict__ bias,
                              int gelu_flag)
{
    int row  = blockIdx.x * (blockDim.x >> 5) + (threadIdx.x >> 5);
    int lane = threadIdx.x & 31;
    const float* x = X + (size_t)row * HDIM;
    float v[8], s = 0.f, s2 = 0.f;
    #pragma unroll
    for (int i = 0; i < 8; i++) {
        float t = x[lane + 32*i];
        v[i] = t; s += t; s2 += t*t;
    }
    #pragma unroll
    for (int o = 16; o; o >>= 1) {
        s  += __shfl_xor_sync(0xffffffffu, s,  o);
        s2 += __shfl_xor_sync(0xffffffffu, s2, o);
    }
    float mu  = s  * (1.f/HDIM);
    float var = s2 * (1.f/HDIM) - mu*mu;
    float rs  = rsqrtf(var + 1e-6f);
    float* y = Y + (size_t)row * HDIM;
    #pragma unroll
    for (int i = 0; i < 8; i++) {
        int c = lane + 32*i;
        float n = (v[i] - mu) * rs * scale[c] + bias[c];
        if (gelu_flag) {
            float t = 0.7978845608028654f * (n + 0.044715f * n*n*n);
            n = 0.5f * n * (1.f + tanhf(t));
        }
        y[c] = n;
    }
}

// ---------------- chunked diagonal complex scan ----------------
__global__ void scanA_kernel(const float* __restrict__ Bu, int layer)
{
    int c = blockIdx.x, p = threadIdx.x;
    float2 lam = g_lam[layer][p];
    float xr = 0.f, xi = 0.f;
    const float* b = Bu + (size_t)c * TCHUNK * HDIM;
    for (int t = 0; t < TCHUNK; t++) {
        float br = b[t*HDIM + p], bi = b[t*HDIM + PDIM + p];
        float nr = lam.x*xr - lam.y*xi + br;
        float ni = lam.x*xi + lam.y*xr + bi;
        xr = nr; xi = ni;
    }
    g_E[c*PDIM + p] = make_float2(xr, xi);
}

__global__ void scanB_kernel(int layer)
{
    int p = threadIdx.x;
    float2 a = g_lamT[layer][p];
    float xr = 0.f, xi = 0.f;
    for (int c = 0; c < NCHUNK; c++) {
        g_Hc[c*PDIM + p] = make_float2(xr, xi);
        float2 e = g_E[c*PDIM + p];
        float nr = a.x*xr - a.y*xi + e.x;
        float ni = a.x*xi + a.y*xr + e.y;
        xr = nr; xi = ni;
    }
}

__global__ void scanC_kernel(const float* __restrict__ Bu, float* __restrict__ XS, int layer)
{
    int c = blockIdx.x, p = threadIdx.x;
    float2 lam = g_lam[layer][p];
    float2 h0  = g_Hc[c*PDIM + p];
    float xr = h0.x, xi = h0.y;
    const float* b = Bu + (size_t)c * TCHUNK * HDIM;
    float* o = XS + (size_t)c * TCHUNK * HDIM;
    for (int t = 0; t < TCHUNK; t++) {
        float br = b[t*HDIM + p], bi = b[t*HDIM + PDIM + p];
        float nr = lam.x*xr - lam.y*xi + br;
        float ni = lam.x*xi + lam.y*xr + bi;
        xr = nr; xi = ni;
        o[t*HDIM + p]        = xr;
        o[t*HDIM + PDIM + p] = xi;
    }
}

// ---------------- SGEMM: C[M,N] = A[M,K] @ B[K,N] (+bias) (+U.*Dv) ----------------
#define BM 128
#define BN 128
#define BK 8
__global__ __launch_bounds__(256) void sgemm_kernel(
    const float* __restrict__ A, const float* __restrict__ B, float* __restrict__ C,
    int M, int N, int K,
    const float* __restrict__ bias, const float* __restrict__ U, const float* __restrict__ Dv)
{
    __shared__ float As[BK][BM];
    __shared__ float Bs[BK][BN];
    int tid = threadIdx.x;
    int m0 = blockIdx.y * BM;
    int n0 = blockIdx.x * BN;
    int arow = tid >> 1, acol = (tid & 1) * 4;
    int brow = tid >> 5, bcol = (tid & 31) * 4;
    int tx = tid & 15, ty = tid >> 4;
    float acc[8][8] = {};
    for (int k0 = 0; k0 < K; k0 += BK) {
        float4 a4 = *(const float4*)(A + (size_t)(m0 + arow)*K + k0 + acol);
        As[acol+0][arow] = a4.x; As[acol+1][arow] = a4.y;
        As[acol+2][arow] = a4.z; As[acol+3][arow] = a4.w;
        float4 b4 = make_float4(0.f,0.f,0.f,0.f);
        if (n0 + bcol < N) b4 = *(const float4*)(B + (size_t)(k0 + brow)*N + n0 + bcol);
        *(float4*)(&Bs[brow][bcol]) = b4;
        __syncthreads();
        #pragma unroll
        for (int k = 0; k < BK; k++) {
            float4 a0 = *(const float4*)(&As[k][ty*8]);
            float4 a1 = *(const float4*)(&As[k][ty*8+4]);
            float4 b0 = *(const float4*)(&Bs[k][tx*8]);
            float4 b1 = *(const float4*)(&Bs[k][tx*8+4]);
            float ra[8] = {a0.x,a0.y,a0.z,a0.w,a1.x,a1.y,a1.z,a1.w};
            float rb[8] = {b0.x,b0.y,b0.z,b0.w,b1.x,b1.y,b1.z,b1.w};
            #pragma unroll
            for (int i = 0; i < 8; i++)
                #pragma unroll
                for (int j = 0; j < 8; j++)
                    acc[i][j] += ra[i]*rb[j];
        }
        __syncthreads();
    }
    #pragma unroll
    for (int i = 0; i < 8; i++) {
        int m = m0 + ty*8 + i;
        #pragma unroll
        for (int j = 0; j < 8; j++) {
            int n = n0 + tx*8 + j;
            if (n < N) {
                float v = acc[i][j];
                if (bias) v += bias[n];
                if (U)    v += U[(size_t)m*N + n] * Dv[n];
                C[(size_t)m*N + n] = v;
            }
        }
    }
}

// ---------------- GLU gate + residual add (in place into x) ----------------
__global__ void glu_add_kernel()
{
    size_t n = (size_t)L_SEQ * HDIM;
    for (size_t i = (size_t)blockIdx.x*blockDim.x + threadIdx.x; i < n;
         i += (size_t)gridDim.x*blockDim.x) {
        float t2 = g_t2[i];
        float sg = 1.f / (1.f + expf(-t2));
        g_x[i] += g_t1[i] * sg;
    }
}

// ---------------- host launch ----------------
extern "C" void kernel_launch(void* const* d_in, const int* in_sizes, int n_in,
                              void* d_out, int out_size)
{
    const float* latent     = (const float*)d_in[0];
    const float* W_expand   = (const float*)d_in[1];
    const float* b_expand   = (const float*)d_in[2];
    const float* norm_scale = (const float*)d_in[3];
    const float* norm_bias  = (const float*)d_in[4];
    const float* Lambda_re  = (const float*)d_in[5];
    const float* Lambda_im  = (const float*)d_in[6];
    const float* B_re       = (const float*)d_in[7];
    const float* B_im       = (const float*)d_in[8];
    const float* C_re       = (const float*)d_in[9];
    const float* C_im       = (const float*)d_in[10];
    const float* Dmat       = (const float*)d_in[11];
    const float* log_step   = (const float*)d_in[12];
    const float* W1         = (const float*)d_in[13];
    const float* b1         = (const float*)d_in[14];
    const float* W2         = (const float*)d_in[15];
    const float* b2         = (const float*)d_in[16];
    const float* W_out      = (const float*)d_in[17];
    const float* b_out      = (const float*)d_in[18];
    float* out = (float*)d_out;

    float *p_x, *p_h, *p_bu, *p_xs, *p_t1, *p_t2, *p_Wb, *p_Wc;
    cudaGetSymbolAddress((void**)&p_x,  g_x);
    cudaGetSymbolAddress((void**)&p_h,  g_h);
    cudaGetSymbolAddress((void**)&p_bu, g_bu);
    cudaGetSymbolAddress((void**)&p_xs, g_xs);
    cudaGetSymbolAddress((void**)&p_t1, g_t1);
    cudaGetSymbolAddress((void**)&p_t2, g_t2);
    cudaGetSymbolAddress((void**)&p_Wb, g_Wb);
    cudaGetSymbolAddress((void**)&p_Wc, g_Wc);

    // setup
    expand_kernel<<<1, HDIM>>>(latent, W_expand, b_expand);
    broadcast_kernel<<<1024, 256>>>();
    setup_params<<<NLAYERS, PDIM>>>(Lambda_re, Lambda_im, B_re, B_im, C_re, C_im, log_step);

    dim3 gemm_block(256);
    dim3 gemm_grid_full((HDIM + BN - 1)/BN, L_SEQ/BM);   // (2, 256)

    for (int i = 0; i < NLAYERS; i++) {
        const float* sc = norm_scale + i*HDIM;
        const float* bi = norm_bias  + i*HDIM;
        // 1. pre-norm: h = LN(x)
        ln_act_kernel<<<L_SEQ/8, 256>>>(p_x, p_h, sc, bi, 0);
        // 2. Bu = h @ Wb
        sgemm_kernel<<<gemm_grid_full, gemm_block>>>(p_h, p_Wb + (size_t)i*HDIM*HDIM, p_bu,
                                                     L_SEQ, HDIM, HDIM, nullptr, nullptr, nullptr);
        // 3. scan
        scanA_kernel<<<NCHUNK, PDIM>>>(p_bu, i);
        scanB_kernel<<<1, PDIM>>>(i);
        scanC_kernel<<<NCHUNK, PDIM>>>(p_bu, p_xs, i);
        // 4. y = xs @ Wc + h*D        -> t1
        sgemm_kernel<<<gemm_grid_full, gemm_block>>>(p_xs, p_Wc + (size_t)i*HDIM*HDIM, p_t1,
                                                     L_SEQ, HDIM, HDIM, nullptr, p_h, Dmat + i*HDIM);
        // 5. h = gelu(LN(y))
        ln_act_kernel<<<L_SEQ/8, 256>>>(p_t1, p_h, sc, bi, 1);
        // 6-7. GLU GEMMs
        sgemm_kernel<<<gemm_grid_full, gemm_block>>>(p_h, W1 + (size_t)i*HDIM*HDIM, p_t1,
                                                     L_SEQ, HDIM, HDIM, b1 + i*HDIM, nullptr, nullptr);
        sgemm_kernel<<<gemm_grid_full, gemm_block>>>(p_h, W2 + (size_t)i*HDIM*HDIM, p_t2,
                                                     L_SEQ, HDIM, HDIM, b2 + i*HDIM, nullptr, nullptr);
        // 8. x = x + t1 * sigmoid(t2)
        glu_add_kernel<<<1024, 256>>>();
    }
    // output head: out = x @ W_out + b_out   (N = 64)
    dim3 out_grid(1, L_SEQ/BM);
    sgemm_kernel<<<out_grid, gemm_block>>>(p_x, W_out, out, L_SEQ, 64, HDIM,
                                           b_out, nullptr, nullptr);
}

// round 3
// speedup vs baseline: 1.0480x; 1.0480x over previous
#include <cuda_runtime.h>
#include <math.h>

#define L_SEQ   32768
#define HDIM    256
#define PDIM    128
#define NLAYERS 4
#define NCHUNK  256
#define TCHUNK  128

// ---------------- scratch (static __device__, no allocation) ----------------
__device__ float  g_x [L_SEQ*HDIM];
__device__ float  g_h [L_SEQ*HDIM];
__device__ float  g_bu[L_SEQ*HDIM];
__device__ float  g_xs[L_SEQ*HDIM];
__device__ float  g_t1[L_SEQ*HDIM];
__device__ float  g_t2[L_SEQ*HDIM];
__device__ float  g_Wb[NLAYERS][HDIM*HDIM];
__device__ float  g_Wc[NLAYERS][HDIM*HDIM];
__device__ float2 g_lam [NLAYERS][PDIM];
__device__ float2 g_lamT[NLAYERS][PDIM];
__device__ float2 g_E [NCHUNK*PDIM];
__device__ float2 g_Hc[NCHUNK*PDIM];
__device__ float  g_x0[HDIM];

// ---------------- f32x2 packed helpers (sm_103a FFMA2 path) ----------------
__device__ __forceinline__ unsigned long long splat2(float x) {
    unsigned long long r;
    asm("mov.b64 %0, {%1, %1};" : "=l"(r) : "f"(x));
    return r;
}
__device__ __forceinline__ void fma2(unsigned long long& d,
                                     unsigned long long a, unsigned long long b) {
    asm("fma.rn.f32x2 %0, %1, %2, %0;" : "+l"(d) : "l"(a), "l"(b));
}
__device__ __forceinline__ void unpack2(unsigned long long v, float& lo, float& hi) {
    asm("mov.b64 {%0, %1}, %2;" : "=f"(lo), "=f"(hi) : "l"(v));
}

// ---------------- setup: latent expand + leaky_relu ----------------
__global__ void expand_kernel(const float* __restrict__ latent,
                              const float* __restrict__ W,
                              const float* __restrict__ b)
{
    int h = threadIdx.x;
    float s = 0.f;
    for (int l = 0; l < HDIM; l++) s += latent[l] * W[l*HDIM + h];
    s += b[h];
    g_x0[h] = s > 0.f ? s : 0.01f * s;
}

__global__ void broadcast_kernel()
{
    size_t n = (size_t)L_SEQ * HDIM / 4;
    const float4* src = (const float4*)g_x0;
    float4* dst = (float4*)g_x;
    for (size_t i = (size_t)blockIdx.x*blockDim.x + threadIdx.x; i < n;
         i += (size_t)gridDim.x*blockDim.x)
        dst[i] = src[i & (HDIM/4 - 1)];
}

// ---------------- setup: per-layer derived parameters ----------------
__global__ void setup_params(const float* __restrict__ Lre, const float* __restrict__ Lim,
                             const float* __restrict__ Bre, const float* __restrict__ Bim,
                             const float* __restrict__ Cre, const float* __restrict__ Cim,
                             const float* __restrict__ log_step)
{
    int layer = blockIdx.x;
    int p = threadIdx.x;                 // 128 threads
    float step = expf(log_step[layer*PDIM + p]);
    float lr = Lre[layer*PDIM + p], li = Lim[layer*PDIM + p];
    float er  = expf(lr*step);
    float lbr = er * cosf(li*step);
    float lbi = er * sinf(li*step);
    g_lam[layer][p] = make_float2(lbr, lbi);
    float tr = lbr, ti = lbi;
    #pragma unroll
    for (int i = 0; i < 7; i++) { float nr = tr*tr - ti*ti; ti = 2.f*tr*ti; tr = nr; }
    g_lamT[layer][p] = make_float2(tr, ti);
    float nr = lbr - 1.f, ni = lbi;
    float den = lr*lr + li*li;
    float fr = (nr*lr + ni*li) / den;
    float fi = (ni*lr - nr*li) / den;
    const float* brp = Bre + ((size_t)layer*PDIM + p)*HDIM;
    const float* bip = Bim + ((size_t)layer*PDIM + p)*HDIM;
    for (int h = 0; h < HDIM; h++) {
        float br = brp[h], bi = bip[h];
        g_Wb[layer][h*HDIM + p]        = fr*br - fi*bi;
        g_Wb[layer][h*HDIM + PDIM + p] = fr*bi + fi*br;
        g_Wc[layer][p*HDIM + h]          =  2.f * Cre[((size_t)layer*HDIM + h)*PDIM + p];
        g_Wc[layer][(PDIM + p)*HDIM + h] = -2.f * Cim[((size_t)layer*HDIM + h)*PDIM + p];
    }
}

// ---------------- LayerNorm (warp per row), optional gelu(tanh) ----------------
__global__ void ln_act_kernel(const float* __restrict__ X, float* __restrict__ Y,
                              const float* __restrict__ scale, const float* __restrict__ bias,
                              int gelu_flag)
{
    int row  = blockIdx.x * (blockDim.x >> 5) + (threadIdx.x >> 5);
    int lane = threadIdx.x & 31;
    const float* x = X + (size_t)row * HDIM;
    float v[8], s = 0.f, s2 = 0.f;
    #pragma unroll
    for (int i = 0; i < 8; i++) {
        float t = x[lane + 32*i];
        v[i] = t; s += t; s2 += t*t;
    }
    #pragma unroll
    for (int o = 16; o; o >>= 1) {
        s  += __shfl_xor_sync(0xffffffffu, s,  o);
        s2 += __shfl_xor_sync(0xffffffffu, s2, o);
    }
    float mu  = s  * (1.f/HDIM);
    float var = s2 * (1.f/HDIM) - mu*mu;
    float rs  = rsqrtf(var + 1e-6f);
    float* y = Y + (size_t)row * HDIM;
    #pragma unroll
    for (int i = 0; i < 8; i++) {
        int c = lane + 32*i;
        float n = (v[i] - mu) * rs * scale[c] + bias[c];
        if (gelu_flag) {
            float t = 0.7978845608028654f * (n + 0.044715f * n*n*n);
            n = 0.5f * n * (1.f + tanhf(t));
        }
        y[c] = n;
    }
}

// ---------------- chunked diagonal complex scan ----------------
__global__ void scanA_kernel(const float* __restrict__ Bu, int layer)
{
    int c = blockIdx.x, p = threadIdx.x;
    float2 lam = g_lam[layer][p];
    float xr = 0.f, xi = 0.f;
    const float* b = Bu + (size_t)c * TCHUNK * HDIM;
    for (int t = 0; t < TCHUNK; t++) {
        float br = b[t*HDIM + p], bi = b[t*HDIM + PDIM + p];
        float nr = lam.x*xr - lam.y*xi + br;
        float ni = lam.x*xi + lam.y*xr + bi;
        xr = nr; xi = ni;
    }
    g_E[c*PDIM + p] = make_float2(xr, xi);
}

__global__ void scanB_kernel(int layer)
{
    int p = threadIdx.x;
    float2 a = g_lamT[layer][p];
    float xr = 0.f, xi = 0.f;
    for (int c = 0; c < NCHUNK; c++) {
        g_Hc[c*PDIM + p] = make_float2(xr, xi);
        float2 e = g_E[c*PDIM + p];
        float nr = a.x*xr - a.y*xi + e.x;
        float ni = a.x*xi + a.y*xr + e.y;
        xr = nr; xi = ni;
    }
}

__global__ void scanC_kernel(const float* __restrict__ Bu, float* __restrict__ XS, int layer)
{
    int c = blockIdx.x, p = threadIdx.x;
    float2 lam = g_lam[layer][p];
    float2 h0  = g_Hc[c*PDIM + p];
    float xr = h0.x, xi = h0.y;
    const float* b = Bu + (size_t)c * TCHUNK * HDIM;
    float* o = XS + (size_t)c * TCHUNK * HDIM;
    for (int t = 0; t < TCHUNK; t++) {
        float br = b[t*HDIM + p], bi = b[t*HDIM + PDIM + p];
        float nr = lam.x*xr - lam.y*xi + br;
        float ni = lam.x*xi + lam.y*xr + bi;
        xr = nr; xi = ni;
        o[t*HDIM + p]        = xr;
        o[t*HDIM + PDIM + p] = xi;
    }
}

// ---------------- SGEMM (FFMA2 packed): C[M,N] = A @ B (+bias) (+U.*Dv) ----------------
#define BM 128
#define BN 128
#define BK 8
__global__ __launch_bounds__(256) void sgemm_kernel(
    const float* __restrict__ A, const float* __restrict__ B, float* __restrict__ C,
    int M, int N, int K,
    const float* __restrict__ bias, const float* __restrict__ U, const float* __restrict__ Dv)
{
    __shared__ __align__(16) float As[BK][BM];
    __shared__ __align__(16) float Bs[BK][BN];
    int tid = threadIdx.x;
    int m0 = blockIdx.y * BM;
    int n0 = blockIdx.x * BN;
    int arow = tid >> 1, acol = (tid & 1) * 4;
    int brow = tid >> 5, bcol = (tid & 31) * 4;
    int tx = tid & 15, ty = tid >> 4;

    // packed accumulators: acc2[i2][j] holds C rows (2*i2, 2*i2+1) at col j
    unsigned long long acc2[4][8];
    #pragma unroll
    for (int i = 0; i < 4; i++)
        #pragma unroll
        for (int j = 0; j < 8; j++) acc2[i][j] = 0ull;

    for (int k0 = 0; k0 < K; k0 += BK) {
        float4 a4 = *(const float4*)(A + (size_t)(m0 + arow)*K + k0 + acol);
        As[acol+0][arow] = a4.x; As[acol+1][arow] = a4.y;
        As[acol+2][arow] = a4.z; As[acol+3][arow] = a4.w;
        float4 b4 = make_float4(0.f,0.f,0.f,0.f);
        if (n0 + bcol < N) b4 = *(const float4*)(B + (size_t)(k0 + brow)*N + n0 + bcol);
        *(float4*)(&Bs[brow][bcol]) = b4;
        __syncthreads();
        #pragma unroll
        for (int k = 0; k < BK; k++) {
            // A pairs along M are contiguous -> free packed loads
            ulonglong2 a01 = *(const ulonglong2*)(&As[k][ty*8]);
            ulonglong2 a23 = *(const ulonglong2*)(&As[k][ty*8+4]);
            unsigned long long a2[4] = {a01.x, a01.y, a23.x, a23.y};
            float4 b0 = *(const float4*)(&Bs[k][tx*8]);
            float4 b1 = *(const float4*)(&Bs[k][tx*8+4]);
            unsigned long long bs[8];
            bs[0] = splat2(b0.x); bs[1] = splat2(b0.y);
            bs[2] = splat2(b0.z); bs[3] = splat2(b0.w);
            bs[4] = splat2(b1.x); bs[5] = splat2(b1.y);
            bs[6] = splat2(b1.z); bs[7] = splat2(b1.w);
            #pragma unroll
            for (int i = 0; i < 4; i++)
                #pragma unroll
                for (int j = 0; j < 8; j++)
                    fma2(acc2[i][j], a2[i], bs[j]);
        }
        __syncthreads();
    }
    #pragma unroll
    for (int i = 0; i < 4; i++) {
        int mA = m0 + ty*8 + 2*i;
        #pragma unroll
        for (int j = 0; j < 8; j++) {
            int n = n0 + tx*8 + j;
            if (n < N) {
                float vlo, vhi;
                unpack2(acc2[i][j], vlo, vhi);
                if (bias) { float bb = bias[n]; vlo += bb; vhi += bb; }
                if (U) {
                    float dv = Dv[n];
                    vlo += U[(size_t)mA*N + n]     * dv;
                    vhi += U[(size_t)(mA+1)*N + n] * dv;
                }
                C[(size_t)mA*N + n]     = vlo;
                C[(size_t)(mA+1)*N + n] = vhi;
            }
        }
    }
}

// ---------------- GLU gate + residual add (in place into x) ----------------
__global__ void glu_add_kernel()
{
    size_t n = (size_t)L_SEQ * HDIM / 4;
    float4* xp = (float4*)g_x;
    const float4* t1p = (const float4*)g_t1;
    const float4* t2p = (const float4*)g_t2;
    for (size_t i = (size_t)blockIdx.x*blockDim.x + threadIdx.x; i < n;
         i += (size_t)gridDim.x*blockDim.x) {
        float4 x4 = xp[i], a4 = t1p[i], b4 = t2p[i];
        x4.x += a4.x / (1.f + expf(-b4.x));
        x4.y += a4.y / (1.f + expf(-b4.y));
        x4.z += a4.z / (1.f + expf(-b4.z));
        x4.w += a4.w / (1.f + expf(-b4.w));
        xp[i] = x4;
    }
}

// ---------------- host launch ----------------
extern "C" void kernel_launch(void* const* d_in, const int* in_sizes, int n_in,
                              void* d_out, int out_size)
{
    const float* latent     = (const float*)d_in[0];
    const float* W_expand   = (const float*)d_in[1];
    const float* b_expand   = (const float*)d_in[2];
    const float* norm_scale = (const float*)d_in[3];
    const float* norm_bias  = (const float*)d_in[4];
    const float* Lambda_re  = (const float*)d_in[5];
    const float* Lambda_im  = (const float*)d_in[6];
    const float* B_re       = (const float*)d_in[7];
    const float* B_im       = (const float*)d_in[8];
    const float* C_re       = (const float*)d_in[9];
    const float* C_im       = (const float*)d_in[10];
    const float* Dmat       = (const float*)d_in[11];
    const float* log_step   = (const float*)d_in[12];
    const float* W1         = (const float*)d_in[13];
    const float* b1         = (const float*)d_in[14];
    const float* W2         = (const float*)d_in[15];
    const float* b2         = (const float*)d_in[16];
    const float* W_out      = (const float*)d_in[17];
    const float* b_out      = (const float*)d_in[18];
    float* out = (float*)d_out;

    float *p_x, *p_h, *p_bu, *p_xs, *p_t1, *p_t2, *p_Wb, *p_Wc;
    cudaGetSymbolAddress((void**)&p_x,  g_x);
    cudaGetSymbolAddress((void**)&p_h,  g_h);
    cudaGetSymbolAddress((void**)&p_bu, g_bu);
    cudaGetSymbolAddress((void**)&p_xs, g_xs);
    cudaGetSymbolAddress((void**)&p_t1, g_t1);
    cudaGetSymbolAddress((void**)&p_t2, g_t2);
    cudaGetSymbolAddress((void**)&p_Wb, g_Wb);
    cudaGetSymbolAddress((void**)&p_Wc, g_Wc);

    // setup
    expand_kernel<<<1, HDIM>>>(latent, W_expand, b_expand);
    broadcast_kernel<<<1024, 256>>>();
    setup_params<<<NLAYERS, PDIM>>>(Lambda_re, Lambda_im, B_re, B_im, C_re, C_im, log_step);

    dim3 gemm_block(256);
    dim3 gemm_grid_full((HDIM + BN - 1)/BN, L_SEQ/BM);   // (2, 256)

    for (int i = 0; i < NLAYERS; i++) {
        const float* sc = norm_scale + i*HDIM;
        const float* bi = norm_bias  + i*HDIM;
        // 1. pre-norm: h = LN(x)
        ln_act_kernel<<<L_SEQ/8, 256>>>(p_x, p_h, sc, bi, 0);
        // 2. Bu = h @ Wb
        sgemm_kernel<<<gemm_grid_full, gemm_block>>>(p_h, p_Wb + (size_t)i*HDIM*HDIM, p_bu,
                                                     L_SEQ, HDIM, HDIM, nullptr, nullptr, nullptr);
        // 3. scan
        scanA_kernel<<<NCHUNK, PDIM>>>(p_bu, i);
        scanB_kernel<<<1, PDIM>>>(i);
        scanC_kernel<<<NCHUNK, PDIM>>>(p_bu, p_xs, i);
        // 4. y = xs @ Wc + h*D        -> t1
        sgemm_kernel<<<gemm_grid_full, gemm_block>>>(p_xs, p_Wc + (size_t)i*HDIM*HDIM, p_t1,
                                                     L_SEQ, HDIM, HDIM, nullptr, p_h, Dmat + i*HDIM);
        // 5. h = gelu(LN(y))
        ln_act_kernel<<<L_SEQ/8, 256>>>(p_t1, p_h, sc, bi, 1);
        // 6-7. GLU GEMMs
        sgemm_kernel<<<gemm_grid_full, gemm_block>>>(p_h, W1 + (size_t)i*HDIM*HDIM, p_t1,
                                                     L_SEQ, HDIM, HDIM, b1 + i*HDIM, nullptr, nullptr);
        sgemm_kernel<<<gemm_grid_full, gemm_block>>>(p_h, W2 + (size_t)i*HDIM*HDIM, p_t2,
                                                     L_SEQ, HDIM, HDIM, b2 + i*HDIM, nullptr, nullptr);
        // 8. x = x + t1 * sigmoid(t2)
        glu_add_kernel<<<1024, 256>>>();
    }
    // output head: out = x @ W_out + b_out   (N = 64)
    dim3 out_grid(1, L_SEQ/BM);
    sgemm_kernel<<<out_grid, gemm_block>>>(p_x, W_out, out, L_SEQ, 64, HDIM,
                                           b_out, nullptr, nullptr);
}

// round 6
// speedup vs baseline: 1.8642x; 1.7789x over previous
#include <cuda_runtime.h>
#include <cuda_bf16.h>
#include <math.h>
#include <stdint.h>

#define L_SEQ   32768
#define HDIM    256
#define PDIM    128
#define NLAYERS 4
#define NCHUNK  256
#define TCHUNK  128

typedef __nv_bfloat16 bf16;

// ---------------- scratch (static __device__, no allocation) ----------------
__device__ float  g_x  [L_SEQ*HDIM];
__device__ float  g_bu [L_SEQ*HDIM];
__device__ float  g_t1 [L_SEQ*HDIM];
__device__ float  g_t2 [L_SEQ*HDIM];
__device__ bf16   g_h_hi [L_SEQ*HDIM];
__device__ bf16   g_h_lo [L_SEQ*HDIM];
__device__ bf16   g_xs_hi[L_SEQ*HDIM];
__device__ bf16   g_xs_lo[L_SEQ*HDIM];
__device__ bf16   g_x_hi [L_SEQ*HDIM];
__device__ bf16   g_x_lo [L_SEQ*HDIM];
// transposed + bf16-split weights: [N][K] layout, K contiguous
__device__ bf16   g_Wbt_hi[NLAYERS][HDIM*HDIM];
__device__ bf16   g_Wbt_lo[NLAYERS][HDIM*HDIM];
__device__ bf16   g_Wct_hi[NLAYERS][HDIM*HDIM];
__device__ bf16   g_Wct_lo[NLAYERS][HDIM*HDIM];
__device__ bf16   g_W1t_hi[NLAYERS][HDIM*HDIM];
__device__ bf16   g_W1t_lo[NLAYERS][HDIM*HDIM];
__device__ bf16   g_W2t_hi[NLAYERS][HDIM*HDIM];
__device__ bf16   g_W2t_lo[NLAYERS][HDIM*HDIM];
__device__ bf16   g_Wot_hi[128*HDIM];   // W_out^T zero-padded to 128 rows
__device__ bf16   g_Wot_lo[128*HDIM];
__device__ float2 g_lam [NLAYERS][PDIM];
__device__ float2 g_lamT[NLAYERS][PDIM];
__device__ float2 g_E [NCHUNK*PDIM];
__device__ float2 g_Hc[NCHUNK*PDIM];
__device__ float  g_x0[HDIM];

// ---------------- PTX helpers (arch-portable: ldmatrix + mma.sync) ----------------
__device__ __forceinline__ uint32_t smem_u32(const void* p) {
    uint32_t a;
    asm("{ .reg .u64 t; cvta.to.shared.u64 t, %1; cvt.u32.u64 %0, t; }" : "=r"(a) : "l"(p));
    return a;
}
__device__ __forceinline__ void ldm4(uint32_t* r, uint32_t addr) {
    asm volatile("ldmatrix.sync.aligned.m8n8.x4.shared.b16 {%0,%1,%2,%3}, [%4];"
                 : "=r"(r[0]), "=r"(r[1]), "=r"(r[2]), "=r"(r[3]) : "r"(addr));
}
__device__ __forceinline__ void mma16816(float* c, const uint32_t* a, const uint32_t* b) {
    asm volatile("mma.sync.aligned.m16n8k16.row.col.f32.bf16.bf16.f32 "
                 "{%0,%1,%2,%3}, {%4,%5,%6,%7}, {%8,%9}, {%0,%1,%2,%3};"
                 : "+f"(c[0]), "+f"(c[1]), "+f"(c[2]), "+f"(c[3])
                 : "r"(a[0]), "r"(a[1]), "r"(a[2]), "r"(a[3]), "r"(b[0]), "r"(b[1]));
}
__device__ __forceinline__ void split2(float x, bf16& hi, bf16& lo) {
    hi = __float2bfloat16_rn(x);
    lo = __float2bfloat16_rn(x - __bfloat162float(hi));
}

// ---------------- setup kernels ----------------
__global__ void expand_kernel(const float* __restrict__ latent,
                              const float* __restrict__ W,
                              const float* __restrict__ b)
{
    int h = threadIdx.x;
    float s = 0.f;
    for (int l = 0; l < HDIM; l++) s += latent[l] * W[l*HDIM + h];
    s += b[h];
    g_x0[h] = s > 0.f ? s : 0.01f * s;
}

__global__ void broadcast_kernel()
{
    size_t n = (size_t)L_SEQ * HDIM / 4;
    const float4* src = (const float4*)g_x0;
    float4* dst = (float4*)g_x;
    for (size_t i = (size_t)blockIdx.x*blockDim.x + threadIdx.x; i < n;
         i += (size_t)gridDim.x*blockDim.x)
        dst[i] = src[i & (HDIM/4 - 1)];
}

__global__ void setup_params(const float* __restrict__ Lre, const float* __restrict__ Lim,
                             const float* __restrict__ Bre, const float* __restrict__ Bim,
                             const float* __restrict__ Cre, const float* __restrict__ Cim,
                             const float* __restrict__ log_step)
{
    int layer = blockIdx.x;
    int p = threadIdx.x;                 // 128 threads
    float step = expf(log_step[layer*PDIM + p]);
    float lr = Lre[layer*PDIM + p], li = Lim[layer*PDIM + p];
    float er  = expf(lr*step);
    float lbr = er * cosf(li*step);
    float lbi = er * sinf(li*step);
    g_lam[layer][p] = make_float2(lbr, lbi);
    float tr = lbr, ti = lbi;
    #pragma unroll
    for (int i = 0; i < 7; i++) { float nr2 = tr*tr - ti*ti; ti = 2.f*tr*ti; tr = nr2; }
    g_lamT[layer][p] = make_float2(tr, ti);
    float nr = lbr - 1.f, ni = lbi;
    float den = lr*lr + li*li;
    float fr = (nr*lr + ni*li) / den;
    float fi = (ni*lr - nr*li) / den;
    const float* brp = Bre + ((size_t)layer*PDIM + p)*HDIM;
    const float* bip = Bim + ((size_t)layer*PDIM + p)*HDIM;
    for (int h = 0; h < HDIM; h++) {
        float br = brp[h], bi = bip[h];
        bf16 hi, lo;
        // Wbt[n][k]: n = p (re) or 128+p (im), k = h
        split2(fr*br - fi*bi, hi, lo);
        g_Wbt_hi[layer][p*HDIM + h] = hi;         g_Wbt_lo[layer][p*HDIM + h] = lo;
        split2(fr*bi + fi*br, hi, lo);
        g_Wbt_hi[layer][(PDIM+p)*HDIM + h] = hi;  g_Wbt_lo[layer][(PDIM+p)*HDIM + h] = lo;
        // Wct[n][k]: n = h, k = p (re part) / 128+p (im part)
        split2( 2.f * Cre[((size_t)layer*HDIM + h)*PDIM + p], hi, lo);
        g_Wct_hi[layer][h*HDIM + p] = hi;         g_Wct_lo[layer][h*HDIM + p] = lo;
        split2(-2.f * Cim[((size_t)layer*HDIM + h)*PDIM + p], hi, lo);
        g_Wct_hi[layer][h*HDIM + PDIM + p] = hi;  g_Wct_lo[layer][h*HDIM + PDIM + p] = lo;
    }
}

// W[K][N] fp32  ->  Wt[N][K] bf16 split
__global__ void convert_w(const float* __restrict__ W, bf16* __restrict__ Whi,
                          bf16* __restrict__ Wlo, int K, int N)
{
    int idx = blockIdx.x*blockDim.x + threadIdx.x;
    if (idx >= K*N) return;
    int n = idx / K, k = idx - n*K;
    bf16 hi, lo;
    split2(W[k*N + n], hi, lo);
    Whi[idx] = hi; Wlo[idx] = lo;
}

// W_out[K=256][64] -> [128][256] with rows 64..127 zero
__global__ void convert_wout(const float* __restrict__ W)
{
    int idx = blockIdx.x*blockDim.x + threadIdx.x;
    if (idx >= 128*HDIM) return;
    int n = idx >> 8, k = idx & 255;
    float v = (n < 64) ? W[k*64 + n] : 0.f;
    bf16 hi, lo;
    split2(v, hi, lo);
    g_Wot_hi[idx] = hi; g_Wot_lo[idx] = lo;
}

// ---------------- LayerNorm (warp per row) -> bf16 split, optional gelu ----------------
__global__ void ln_act_kernel(const float* __restrict__ X,
                              bf16* __restrict__ Yhi, bf16* __restrict__ Ylo,
                              const float* __restrict__ scale, const float* __restrict__ bias,
                              int gelu_flag)
{
    int row  = blockIdx.x * (blockDim.x >> 5) + (threadIdx.x >> 5);
    int lane = threadIdx.x & 31;
    const float* x = X + (size_t)row * HDIM;
    float v[8], s = 0.f, s2 = 0.f;
    #pragma unroll
    for (int i = 0; i < 8; i++) {
        float t = x[lane + 32*i];
        v[i] = t; s += t; s2 += t*t;
    }
    #pragma unroll
    for (int o = 16; o; o >>= 1) {
        s  += __shfl_xor_sync(0xffffffffu, s,  o);
        s2 += __shfl_xor_sync(0xffffffffu, s2, o);
    }
    float mu  = s  * (1.f/HDIM);
    float var = s2 * (1.f/HDIM) - mu*mu;
    float rs  = rsqrtf(var + 1e-6f);
    #pragma unroll
    for (int i = 0; i < 8; i++) {
        int c = lane + 32*i;
        float n = (v[i] - mu) * rs * scale[c] + bias[c];
        if (gelu_flag) {
            float t = 0.7978845608028654f * (n + 0.044715f * n*n*n);
            n = 0.5f * n * (1.f + tanhf(t));
        }
        bf16 hi, lo;
        split2(n, hi, lo);
        Yhi[(size_t)row*HDIM + c] = hi;
        Ylo[(size_t)row*HDIM + c] = lo;
    }
}

// ---------------- chunked diagonal complex scan ----------------
__global__ void scanA_kernel(const float* __restrict__ Bu, int layer)
{
    int c = blockIdx.x, p = threadIdx.x;
    float2 lam = g_lam[layer][p];
    float xr = 0.f, xi = 0.f;
    const float* b = Bu + (size_t)c * TCHUNK * HDIM;
    for (int t = 0; t < TCHUNK; t++) {
        float br = b[t*HDIM + p], bi = b[t*HDIM + PDIM + p];
        float nr = lam.x*xr - lam.y*xi + br;
        float ni = lam.x*xi + lam.y*xr + bi;
        xr = nr; xi = ni;
    }
    g_E[c*PDIM + p] = make_float2(xr, xi);
}

__global__ void scanB_kernel(int layer)
{
    int p = threadIdx.x;
    float2 a = g_lamT[layer][p];
    float xr = 0.f, xi = 0.f;
    for (int c = 0; c < NCHUNK; c++) {
        g_Hc[c*PDIM + p] = make_float2(xr, xi);
        float2 e = g_E[c*PDIM + p];
        float nr = a.x*xr - a.y*xi + e.x;
        float ni = a.x*xi + a.y*xr + e.y;
        xr = nr; xi = ni;
    }
}

__global__ void scanC_kernel(const float* __restrict__ Bu, int layer)
{
    int c = blockIdx.x, p = threadIdx.x;
    float2 lam = g_lam[layer][p];
    float2 h0  = g_Hc[c*PDIM + p];
    float xr = h0.x, xi = h0.y;
    const float* b = Bu + (size_t)c * TCHUNK * HDIM;
    size_t base = (size_t)c * TCHUNK * HDIM;
    for (int t = 0; t < TCHUNK; t++) {
        float br = b[t*HDIM + p], bi = b[t*HDIM + PDIM + p];
        float nr = lam.x*xr - lam.y*xi + br;
        float ni = lam.x*xi + lam.y*xr + bi;
        xr = nr; xi = ni;
        bf16 hi, lo;
        split2(xr, hi, lo);
        g_xs_hi[base + t*HDIM + p] = hi;        g_xs_lo[base + t*HDIM + p] = lo;
        split2(xi, hi, lo);
        g_xs_hi[base + t*HDIM + PDIM + p] = hi; g_xs_lo[base + t*HDIM + PDIM + p] = lo;
    }
}

// ---------------- mma.sync split-bf16 GEMM ----------------
// C[m0:m0+128, n0:n0+128] = A[m0:,K=256] * B^T[n0:,K=256]   (B stored [N][K])
// 3-pass split per mma step: Ahi*Bhi + Ahi*Blo + Alo*Bhi, fp32 accumulate.
#define SPAD 40   // smem row stride in bf16 elements (80B, 16B-aligned, conflict-light)

__global__ __launch_bounds__(256) void mma_gemm(
    const bf16* __restrict__ Ahi, const bf16* __restrict__ Alo,
    const bf16* __restrict__ Bhi, const bf16* __restrict__ Blo,
    float* __restrict__ C, int ldc, int nvalid,
    const float* __restrict__ bias,
    const bf16* __restrict__ Uhi, const bf16* __restrict__ Ulo,
    const float* __restrict__ Dv)
{
    __shared__ __align__(16) bf16 sAh[128*SPAD];
    __shared__ __align__(16) bf16 sAl[128*SPAD];
    __shared__ __align__(16) bf16 sBh[128*SPAD];
    __shared__ __align__(16) bf16 sBl[128*SPAD];

    int tid = threadIdx.x;
    int wid = tid >> 5, lane = tid & 31;
    int m0 = blockIdx.y * 128;
    int n0 = blockIdx.x * 128;
    int wm = (wid >> 2) * 64;    // warp M offset (0 or 64)
    int wn = (wid & 3) * 32;     // warp N offset (0,32,64,96)

    float acc[4][4][4];
    #pragma unroll
    for (int i = 0; i < 4; i++)
        #pragma unroll
        for (int j = 0; j < 4; j++)
            #pragma unroll
            for (int q = 0; q < 4; q++) acc[i][j][q] = 0.f;

    uint32_t aAh = smem_u32(sAh), aAl = smem_u32(sAl);
    uint32_t aBh = smem_u32(sBh), aBl = smem_u32(sBl);

    // ldmatrix lane address components
    int a_r = lane & 15;             // row within 16
    int a_c = (lane >> 4) * 8;       // k-half
    int b_q = lane >> 3, b_r = lane & 7;
    int b_n_add = (b_q >> 1) * 8 + b_r;   // n offset within 16-n pair
    int b_k_add = (b_q & 1) * 8;          // k-half

    for (int k0 = 0; k0 < HDIM; k0 += 32) {
        // stage 128x32 tiles (4 operands); 512 16B-chunks each, 2 per thread
        #pragma unroll
        for (int i = 0; i < 2; i++) {
            int idx = tid + i*256;
            int r = idx >> 2, cg = (idx & 3) * 8;
            size_t ga = (size_t)(m0 + r)*HDIM + k0 + cg;
            size_t gb = (size_t)(n0 + r)*HDIM + k0 + cg;
            int so = r*SPAD + cg;
            *(uint4*)(sAh + so) = *(const uint4*)(Ahi + ga);
            *(uint4*)(sAl + so) = *(const uint4*)(Alo + ga);
            *(uint4*)(sBh + so) = *(const uint4*)(Bhi + gb);
            *(uint4*)(sBl + so) = *(const uint4*)(Blo + gb);
        }
        __syncthreads();
        #pragma unroll
        for (int ks = 0; ks < 2; ks++) {
            uint32_t bh[2][4], bl[2][4];
            #pragma unroll
            for (int nf2 = 0; nf2 < 2; nf2++) {
                uint32_t boff = (uint32_t)(((wn + nf2*16 + b_n_add)*SPAD + ks*16 + b_k_add) * 2);
                ldm4(bh[nf2], aBh + boff);
                ldm4(bl[nf2], aBl + boff);
            }
            uint32_t ah[4][4], al[4][4];
            #pragma unroll
            for (int mf = 0; mf < 4; mf++) {
                uint32_t aoff = (uint32_t)(((wm + mf*16 + a_r)*SPAD + ks*16 + a_c) * 2);
                ldm4(ah[mf], aAh + aoff);
                ldm4(al[mf], aAl + aoff);
            }
            #pragma unroll
            for (int mf = 0; mf < 4; mf++)
                #pragma unroll
                for (int nf = 0; nf < 4; nf++) {
                    const uint32_t* ph = &bh[nf >> 1][(nf & 1)*2];
                    const uint32_t* pl = &bl[nf >> 1][(nf & 1)*2];
                    mma16816(acc[mf][nf], ah[mf], ph);
                    mma16816(acc[mf][nf], ah[mf], pl);
                    mma16816(acc[mf][nf], al[mf], ph);
                }
        }
        __syncthreads();
    }

    // epilogue: thread t -> rows (t/4, t/4+8), cols 2*(t%4)..+1 of each 16x8 frag
    int tr = lane >> 2, tc = (lane & 3) * 2;
    #pragma unroll
    for (int mf = 0; mf < 4; mf++) {
        #pragma unroll
        for (int nf = 0; nf < 4; nf++) {
            int col = n0 + wn + nf*8 + tc;
            if (col < nvalid) {
                #pragma unroll
                for (int hrow = 0; hrow < 2; hrow++) {
                    int m = m0 + wm + mf*16 + tr + hrow*8;
                    float v0 = acc[mf][nf][hrow*2+0];
                    float v1 = acc[mf][nf][hrow*2+1];
                    if (bias) { v0 += bias[col]; v1 += bias[col+1]; }
                    if (Uhi) {
                        size_t ub = (size_t)m*HDIM + col;
                        v0 += (__bfloat162float(Uhi[ub])   + __bfloat162float(Ulo[ub]))   * Dv[col];
                        v1 += (__bfloat162float(Uhi[ub+1]) + __bfloat162float(Ulo[ub+1])) * Dv[col+1];
                    }
                    *(float2*)(C + (size_t)m*ldc + col) = make_float2(v0, v1);
                }
            }
        }
    }
}

// ---------------- GLU gate + residual add (in place into x) ----------------
__global__ void glu_add_kernel(int emit_split)
{
    size_t n = (size_t)L_SEQ * HDIM / 4;
    float4* xp = (float4*)g_x;
    const float4* t1p = (const float4*)g_t1;
    const float4* t2p = (const float4*)g_t2;
    for (size_t i = (size_t)blockIdx.x*blockDim.x + threadIdx.x; i < n;
         i += (size_t)gridDim.x*blockDim.x) {
        float4 x4 = xp[i], a4 = t1p[i], b4 = t2p[i];
        x4.x += a4.x / (1.f + expf(-b4.x));
        x4.y += a4.y / (1.f + expf(-b4.y));
        x4.z += a4.z / (1.f + expf(-b4.z));
        x4.w += a4.w / (1.f + expf(-b4.w));
        xp[i] = x4;
        if (emit_split) {
            bf16 hi, lo;
            split2(x4.x, hi, lo); g_x_hi[i*4+0] = hi; g_x_lo[i*4+0] = lo;
            split2(x4.y, hi, lo); g_x_hi[i*4+1] = hi; g_x_lo[i*4+1] = lo;
            split2(x4.z, hi, lo); g_x_hi[i*4+2] = hi; g_x_lo[i*4+2] = lo;
            split2(x4.w, hi, lo); g_x_hi[i*4+3] = hi; g_x_lo[i*4+3] = lo;
        }
    }
}

// ---------------- host launch ----------------
extern "C" void kernel_launch(void* const* d_in, const int* in_sizes, int n_in,
                              void* d_out, int out_size)
{
    const float* latent     = (const float*)d_in[0];
    const float* W_expand   = (const float*)d_in[1];
    const float* b_expand   = (const float*)d_in[2];
    const float* norm_scale = (const float*)d_in[3];
    const float* norm_bias  = (const float*)d_in[4];
    const float* Lambda_re  = (const float*)d_in[5];
    const float* Lambda_im  = (const float*)d_in[6];
    const float* B_re       = (const float*)d_in[7];
    const float* B_im       = (const float*)d_in[8];
    const float* C_re       = (const float*)d_in[9];
    const float* C_im       = (const float*)d_in[10];
    const float* Dmat       = (const float*)d_in[11];
    const float* log_step   = (const float*)d_in[12];
    const float* W1         = (const float*)d_in[13];
    const float* b1         = (const float*)d_in[14];
    const float* W2         = (const float*)d_in[15];
    const float* b2         = (const float*)d_in[16];
    const float* W_out      = (const float*)d_in[17];
    const float* b_out      = (const float*)d_in[18];
    float* out = (float*)d_out;

    float *p_x, *p_bu, *p_t1, *p_t2;
    bf16 *p_hh, *p_hl, *p_xsh, *p_xsl, *p_xh, *p_xl;
    bf16 *p_Wbt_h, *p_Wbt_l, *p_Wct_h, *p_Wct_l, *p_W1t_h, *p_W1t_l, *p_W2t_h, *p_W2t_l, *p_Wot_h, *p_Wot_l;
    cudaGetSymbolAddress((void**)&p_x,  g_x);
    cudaGetSymbolAddress((void**)&p_bu, g_bu);
    cudaGetSymbolAddress((void**)&p_t1, g_t1);
    cudaGetSymbolAddress((void**)&p_t2, g_t2);
    cudaGetSymbolAddress((void**)&p_hh, g_h_hi);
    cudaGetSymbolAddress((void**)&p_hl, g_h_lo);
    cudaGetSymbolAddress((void**)&p_xsh, g_xs_hi);
    cudaGetSymbolAddress((void**)&p_xsl, g_xs_lo);
    cudaGetSymbolAddress((void**)&p_xh, g_x_hi);
    cudaGetSymbolAddress((void**)&p_xl, g_x_lo);
    cudaGetSymbolAddress((void**)&p_Wbt_h, g_Wbt_hi);
    cudaGetSymbolAddress((void**)&p_Wbt_l, g_Wbt_lo);
    cudaGetSymbolAddress((void**)&p_Wct_h, g_Wct_hi);
    cudaGetSymbolAddress((void**)&p_Wct_l, g_Wct_lo);
    cudaGetSymbolAddress((void**)&p_W1t_h, g_W1t_hi);
    cudaGetSymbolAddress((void**)&p_W1t_l, g_W1t_lo);
    cudaGetSymbolAddress((void**)&p_W2t_h, g_W2t_hi);
    cudaGetSymbolAddress((void**)&p_W2t_l, g_W2t_lo);
    cudaGetSymbolAddress((void**)&p_Wot_h, g_Wot_hi);
    cudaGetSymbolAddress((void**)&p_Wot_l, g_Wot_lo);

    // setup
    expand_kernel<<<1, HDIM>>>(latent, W_expand, b_expand);
    broadcast_kernel<<<1024, 256>>>();
    setup_params<<<NLAYERS, PDIM>>>(Lambda_re, Lambda_im, B_re, B_im, C_re, C_im, log_step);
    for (int i = 0; i < NLAYERS; i++) {
        convert_w<<<(HDIM*HDIM + 255)/256, 256>>>(W1 + (size_t)i*HDIM*HDIM,
                                                  p_W1t_h + (size_t)i*HDIM*HDIM,
                                                  p_W1t_l + (size_t)i*HDIM*HDIM, HDIM, HDIM);
        convert_w<<<(HDIM*HDIM + 255)/256, 256>>>(W2 + (size_t)i*HDIM*HDIM,
                                                  p_W2t_h + (size_t)i*HDIM*HDIM,
                                                  p_W2t_l + (size_t)i*HDIM*HDIM, HDIM, HDIM);
    }
    convert_wout<<<(128*HDIM + 255)/256, 256>>>(W_out);

    dim3 gblk(256);
    dim3 ggrid(2, L_SEQ/128);   // (N tiles, M tiles)

    for (int i = 0; i < NLAYERS; i++) {
        const float* sc = norm_scale + i*HDIM;
        const float* bi = norm_bias  + i*HDIM;
        size_t wo = (size_t)i*HDIM*HDIM;
        // 1. pre-norm: h = LN(x) -> bf16 split
        ln_act_kernel<<<L_SEQ/8, 256>>>(p_x, p_hh, p_hl, sc, bi, 0);
        // 2. Bu = h @ Wb
        mma_gemm<<<ggrid, gblk>>>(p_hh, p_hl, p_Wbt_h + wo, p_Wbt_l + wo,
                                  p_bu, HDIM, HDIM, nullptr, nullptr, nullptr, nullptr);
        // 3. scan -> xs bf16 split
        scanA_kernel<<<NCHUNK, PDIM>>>(p_bu, i);
        scanB_kernel<<<1, PDIM>>>(i);
        scanC_kernel<<<NCHUNK, PDIM>>>(p_bu, i);
        // 4. t1 = xs @ Wc + h*D
        mma_gemm<<<ggrid, gblk>>>(p_xsh, p_xsl, p_Wct_h + wo, p_Wct_l + wo,
                                  p_t1, HDIM, HDIM, nullptr, p_hh, p_hl, Dmat + i*HDIM);
        // 5. h = gelu(LN(t1)) -> bf16 split
        ln_act_kernel<<<L_SEQ/8, 256>>>(p_t1, p_hh, p_hl, sc, bi, 1);
        // 6-7. GLU GEMMs
        mma_gemm<<<ggrid, gblk>>>(p_hh, p_hl, p_W1t_h + wo, p_W1t_l + wo,
                                  p_t1, HDIM, HDIM, b1 + i*HDIM, nullptr, nullptr, nullptr);
        mma_gemm<<<ggrid, gblk>>>(p_hh, p_hl, p_W2t_h + wo, p_W2t_l + wo,
                                  p_t2, HDIM, HDIM, b2 + i*HDIM, nullptr, nullptr, nullptr);
        // 8. x = x + t1 * sigmoid(t2); last layer also emits x bf16 split for head
        glu_add_kernel<<<1024, 256>>>(i == NLAYERS-1 ? 1 : 0);
    }
    // output head: out = x @ W_out + b_out  (N=64, padded B to 128 rows)
    dim3 hgrid(1, L_SEQ/128);
    mma_gemm<<<hgrid, gblk>>>(p_xh, p_xl, p_Wot_h, p_Wot_l,
                              out, 64, 64, b_out, nullptr, nullptr, nullptr);
}

// round 9
// speedup vs baseline: 1.8859x; 1.0116x over previous
#include <cuda_runtime.h>
#include <cuda_bf16.h>
#include <math.h>
#include <stdint.h>

#define L_SEQ   32768
#define HDIM    256
#define PDIM    128
#define NLAYERS 4
#define NCHUNK  256
#define TCHUNK  128

typedef __nv_bfloat16 bf16;

// ---------------- scratch (static __device__, no allocation) ----------------
__device__ float  g_x  [L_SEQ*HDIM];
__device__ float  g_bu [L_SEQ*HDIM];
__device__ float  g_t1 [L_SEQ*HDIM];
__device__ bf16   g_h_hi [L_SEQ*HDIM];
__device__ bf16   g_h_lo [L_SEQ*HDIM];
__device__ bf16   g_xs_hi[L_SEQ*HDIM];
__device__ bf16   g_xs_lo[L_SEQ*HDIM];
__device__ bf16   g_x_hi [L_SEQ*HDIM];
__device__ bf16   g_x_lo [L_SEQ*HDIM];
// transposed + bf16-split weights: [N][K] layout, K contiguous
__device__ bf16   g_Wbt_hi[NLAYERS][HDIM*HDIM];
__device__ bf16   g_Wbt_lo[NLAYERS][HDIM*HDIM];
__device__ bf16   g_Wct_hi[NLAYERS][HDIM*HDIM];
__device__ bf16   g_Wct_lo[NLAYERS][HDIM*HDIM];
__device__ bf16   g_W1t_hi[NLAYERS][HDIM*HDIM];
__device__ bf16   g_W1t_lo[NLAYERS][HDIM*HDIM];
__device__ bf16   g_W2t_hi[NLAYERS][HDIM*HDIM];
__device__ bf16   g_W2t_lo[NLAYERS][HDIM*HDIM];
__device__ bf16   g_Wot_hi[128*HDIM];   // W_out^T zero-padded to 128 rows
__device__ bf16   g_Wot_lo[128*HDIM];
__device__ float2 g_lam [NLAYERS][PDIM];
__device__ float2 g_lamT[NLAYERS][PDIM];
__device__ float2 g_E [NCHUNK*PDIM];
__device__ float2 g_Hc[NCHUNK*PDIM];
__device__ float  g_x0[HDIM];

// ---------------- PTX helpers ----------------
__device__ __forceinline__ uint32_t smem_u32(const void* p) {
    uint32_t a;
    asm("{ .reg .u64 t; cvta.to.shared.u64 t, %1; cvt.u32.u64 %0, t; }" : "=r"(a) : "l"(p));
    return a;
}
__device__ __forceinline__ void ldm4(uint32_t* r, uint32_t addr) {
    asm volatile("ldmatrix.sync.aligned.m8n8.x4.shared.b16 {%0,%1,%2,%3}, [%4];"
                 : "=r"(r[0]), "=r"(r[1]), "=r"(r[2]), "=r"(r[3]) : "r"(addr));
}
__device__ __forceinline__ void mma16816(float* c, const uint32_t* a, const uint32_t* b) {
    asm volatile("mma.sync.aligned.m16n8k16.row.col.f32.bf16.bf16.f32 "
                 "{%0,%1,%2,%3}, {%4,%5,%6,%7}, {%8,%9}, {%0,%1,%2,%3};"
                 : "+f"(c[0]), "+f"(c[1]), "+f"(c[2]), "+f"(c[3])
                 : "r"(a[0]), "r"(a[1]), "r"(a[2]), "r"(a[3]), "r"(b[0]), "r"(b[1]));
}
__device__ __forceinline__ void cp16(uint32_t saddr, const void* gaddr) {
    asm volatile("cp.async.cg.shared.global [%0], [%1], 16;" :: "r"(saddr), "l"(gaddr));
}
#define CP_COMMIT() asm volatile("cp.async.commit_group;" ::: "memory")
#define CP_WAIT1()  asm volatile("cp.async.wait_group 1;" ::: "memory")
#define CP_WAIT0()  asm volatile("cp.async.wait_group 0;" ::: "memory")
__device__ __forceinline__ void split2(float x, bf16& hi, bf16& lo) {
    hi = __float2bfloat16_rn(x);
    lo = __float2bfloat16_rn(x - __bfloat162float(hi));
}

// ---------------- setup kernels ----------------
__global__ void expand_kernel(const float* __restrict__ latent,
                              const float* __restrict__ W,
                              const float* __restrict__ b)
{
    int h = threadIdx.x;
    float s = 0.f;
    for (int l = 0; l < HDIM; l++) s += latent[l] * W[l*HDIM + h];
    s += b[h];
    g_x0[h] = s > 0.f ? s : 0.01f * s;
}

__global__ void broadcast_kernel()
{
    size_t n = (size_t)L_SEQ * HDIM / 4;
    const float4* src = (const float4*)g_x0;
    float4* dst = (float4*)g_x;
    for (size_t i = (size_t)blockIdx.x*blockDim.x + threadIdx.x; i < n;
         i += (size_t)gridDim.x*blockDim.x)
        dst[i] = src[i & (HDIM/4 - 1)];
}

__global__ void setup_params(const float* __restrict__ Lre, const float* __restrict__ Lim,
                             const float* __restrict__ Bre, const float* __restrict__ Bim,
                             const float* __restrict__ Cre, const float* __restrict__ Cim,
                             const float* __restrict__ log_step)
{
    int layer = blockIdx.x;
    int p = threadIdx.x;                 // 128 threads
    float step = expf(log_step[layer*PDIM + p]);
    float lr = Lre[layer*PDIM + p], li = Lim[layer*PDIM + p];
    float er  = expf(lr*step);
    float lbr = er * cosf(li*step);
    float lbi = er * sinf(li*step);
    g_lam[layer][p] = make_float2(lbr, lbi);
    float tr = lbr, ti = lbi;
    #pragma unroll
    for (int i = 0; i < 7; i++) { float nr2 = tr*tr - ti*ti; ti = 2.f*tr*ti; tr = nr2; }
    g_lamT[layer][p] = make_float2(tr, ti);
    float nr = lbr - 1.f, ni = lbi;
    float den = lr*lr + li*li;
    float fr = (nr*lr + ni*li) / den;
    float fi = (ni*lr - nr*li) / den;
    const float* brp = Bre + ((size_t)layer*PDIM + p)*HDIM;
    const float* bip = Bim + ((size_t)layer*PDIM + p)*HDIM;
    for (int h = 0; h < HDIM; h++) {
        float br = brp[h], bi = bip[h];
        bf16 hi, lo;
        split2(fr*br - fi*bi, hi, lo);
        g_Wbt_hi[layer][p*HDIM + h] = hi;         g_Wbt_lo[layer][p*HDIM + h] = lo;
        split2(fr*bi + fi*br, hi, lo);
        g_Wbt_hi[layer][(PDIM+p)*HDIM + h] = hi;  g_Wbt_lo[layer][(PDIM+p)*HDIM + h] = lo;
        split2( 2.f * Cre[((size_t)layer*HDIM + h)*PDIM + p], hi, lo);
        g_Wct_hi[layer][h*HDIM + p] = hi;         g_Wct_lo[layer][h*HDIM + p] = lo;
        split2(-2.f * Cim[((size_t)layer*HDIM + h)*PDIM + p], hi, lo);
        g_Wct_hi[layer][h*HDIM + PDIM + p] = hi;  g_Wct_lo[layer][h*HDIM + PDIM + p] = lo;
    }
}

// W[K][N] fp32  ->  Wt[N][K] bf16 split
__global__ void convert_w(const float* __restrict__ W, bf16* __restrict__ Whi,
                          bf16* __restrict__ Wlo, int K, int N)
{
    int idx = blockIdx.x*blockDim.x + threadIdx.x;
    if (idx >= K*N) return;
    int n = idx / K, k = idx - n*K;
    bf16 hi, lo;
    split2(W[k*N + n], hi, lo);
    Whi[idx] = hi; Wlo[idx] = lo;
}

// W_out[K=256][64] -> [128][256] with rows 64..127 zero
__global__ void convert_wout(const float* __restrict__ W)
{
    int idx = blockIdx.x*blockDim.x + threadIdx.x;
    if (idx >= 128*HDIM) return;
    int n = idx >> 8, k = idx & 255;
    float v = (n < 64) ? W[k*64 + n] : 0.f;
    bf16 hi, lo;
    split2(v, hi, lo);
    g_Wot_hi[idx] = hi; g_Wot_lo[idx] = lo;
}

// ---------------- LayerNorm (warp per row) -> bf16 split, optional gelu ----------------
__global__ void ln_act_kernel(const float* __restrict__ X,
                              bf16* __restrict__ Yhi, bf16* __restrict__ Ylo,
                              const float* __restrict__ scale, const float* __restrict__ bias,
                              int gelu_flag)
{
    int row  = blockIdx.x * (blockDim.x >> 5) + (threadIdx.x >> 5);
    int lane = threadIdx.x & 31;
    const float* x = X + (size_t)row * HDIM;
    float v[8], s = 0.f, s2 = 0.f;
    #pragma unroll
    for (int i = 0; i < 8; i++) {
        float t = x[lane + 32*i];
        v[i] = t; s += t; s2 += t*t;
    }
    #pragma unroll
    for (int o = 16; o; o >>= 1) {
        s  += __shfl_xor_sync(0xffffffffu, s,  o);
        s2 += __shfl_xor_sync(0xffffffffu, s2, o);
    }
    float mu  = s  * (1.f/HDIM);
    float var = s2 * (1.f/HDIM) - mu*mu;
    float rs  = rsqrtf(var + 1e-6f);
    #pragma unroll
    for (int i = 0; i < 8; i++) {
        int c = lane + 32*i;
        float n = (v[i] - mu) * rs * scale[c] + bias[c];
        if (gelu_flag) {
            float t = 0.7978845608028654f * (n + 0.044715f * n*n*n);
            n = 0.5f * n * (1.f + tanhf(t));
        }
        bf16 hi, lo;
        split2(n, hi, lo);
        Yhi[(size_t)row*HDIM + c] = hi;
        Ylo[(size_t)row*HDIM + c] = lo;
    }
}

// ---------------- chunked diagonal complex scan ----------------
__global__ void scanA_kernel(const float* __restrict__ Bu, int layer)
{
    int c = blockIdx.x, p = threadIdx.x;
    float2 lam = g_lam[layer][p];
    float xr = 0.f, xi = 0.f;
    const float* b = Bu + (size_t)c * TCHUNK * HDIM;
    for (int t = 0; t < TCHUNK; t++) {
        float br = b[t*HDIM + p], bi = b[t*HDIM + PDIM + p];
        float nr = lam.x*xr - lam.y*xi + br;
        float ni = lam.x*xi + lam.y*xr + bi;
        xr = nr; xi = ni;
    }
    g_E[c*PDIM + p] = make_float2(xr, xi);
}

__global__ void scanB_kernel(int layer)
{
    int p = threadIdx.x;
    float2 a = g_lamT[layer][p];
    float xr = 0.f, xi = 0.f;
    for (int c = 0; c < NCHUNK; c++) {
        g_Hc[c*PDIM + p] = make_float2(xr, xi);
        float2 e = g_E[c*PDIM + p];
        float nr = a.x*xr - a.y*xi + e.x;
        float ni = a.x*xi + a.y*xr + e.y;
        xr = nr; xi = ni;
    }
}

__global__ void scanC_kernel(const float* __restrict__ Bu, int layer)
{
    int c = blockIdx.x, p = threadIdx.x;
    float2 lam = g_lam[layer][p];
    float2 h0  = g_Hc[c*PDIM + p];
    float xr = h0.x, xi = h0.y;
    const float* b = Bu + (size_t)c * TCHUNK * HDIM;
    size_t base = (size_t)c * TCHUNK * HDIM;
    for (int t = 0; t < TCHUNK; t++) {
        float br = b[t*HDIM + p], bi = b[t*HDIM + PDIM + p];
        float nr = lam.x*xr - lam.y*xi + br;
        float ni = lam.x*xi + lam.y*xr + bi;
        xr = nr; xi = ni;
        bf16 hi, lo;
        split2(xr, hi, lo);
        g_xs_hi[base + t*HDIM + p] = hi;        g_xs_lo[base + t*HDIM + p] = lo;
        split2(xi, hi, lo);
        g_xs_hi[base + t*HDIM + PDIM + p] = hi; g_xs_lo[base + t*HDIM + PDIM + p] = lo;
    }
}

// ---------------- mma.sync split-bf16 GEMM (cp.async double-buffered) ----------------
#define SPAD 40                       // smem row stride in bf16 (80B, 16B-aligned)
#define BUFSZ (128*SPAD*2)            // 10240 B per operand buffer
#define SMEM_G4 (8*BUFSZ)             // single GEMM: 4 ops x 2 bufs
#define SMEM_G6 (12*BUFSZ)            // GLU GEMM: 6 ops x 2 bufs

// fragment-loading lane address components
struct LaneAddr {
    int a_off;   // (row part)*SPAD + k-half, in elements
    int b_off;
};
__device__ __forceinline__ LaneAddr lane_addr(int lane, int wm, int wn) {
    LaneAddr la;
    int a_r = lane & 15, a_c = (lane >> 4) * 8;
    int b_q = lane >> 3, b_r = lane & 7;
    int b_n_add = (b_q >> 1) * 8 + b_r;
    int b_k_add = (b_q & 1) * 8;
    la.a_off = (wm + a_r)*SPAD + a_c;
    la.b_off = (wn + b_n_add)*SPAD + b_k_add;
    return la;
}

__global__ __launch_bounds__(256) void mma_gemm(
    const bf16* __restrict__ Ahi, const bf16* __restrict__ Alo,
    const bf16* __restrict__ Bhi, const bf16* __restrict__ Blo,
    float* __restrict__ C, int ldc, int nvalid,
    const float* __restrict__ bias,
    const bf16* __restrict__ Uhi, const bf16* __restrict__ Ulo,
    const float* __restrict__ Dv)
{
    extern __shared__ __align__(16) char smem[];
    uint32_t sb = smem_u32(smem);
    int tid = threadIdx.x;
    int wid = tid >> 5, lane = tid & 31;
    int m0 = blockIdx.y * 128;
    int n0 = blockIdx.x * 128;
    int wm = (wid >> 2) * 64;
    int wn = (wid & 3) * 32;

    float acc[4][4][4];
    #pragma unroll
    for (int i = 0; i < 4; i++)
        #pragma unroll
        for (int j = 0; j < 4; j++)
            #pragma unroll
            for (int q = 0; q < 4; q++) acc[i][j][q] = 0.f;

    // staging indices
    int s_r = tid >> 2, s_cg = (tid & 3) * 8;
    int s_r2 = s_r + 64;
    uint32_t so1 = (uint32_t)((s_r*SPAD + s_cg) * 2);
    uint32_t so2 = (uint32_t)((s_r2*SPAD + s_cg) * 2);

    #define STAGE4(k0, buf) do { \
        uint32_t bb = sb + (buf)*4*BUFSZ; \
        size_t ga1 = (size_t)(m0 + s_r)*HDIM + (k0) + s_cg; \
        size_t gb1 = (size_t)(n0 + s_r)*HDIM + (k0) + s_cg; \
        size_t ga2 = (size_t)(m0 + s_r2)*HDIM + (k0) + s_cg; \
        size_t gb2 = (size_t)(n0 + s_r2)*HDIM + (k0) + s_cg; \
        cp16(bb + 0*BUFSZ + so1, Ahi + ga1); cp16(bb + 0*BUFSZ + so2, Ahi + ga2); \
        cp16(bb + 1*BUFSZ + so1, Alo + ga1); cp16(bb + 1*BUFSZ + so2, Alo + ga2); \
        cp16(bb + 2*BUFSZ + so1, Bhi + gb1); cp16(bb + 2*BUFSZ + so2, Bhi + gb2); \
        cp16(bb + 3*BUFSZ + so1, Blo + gb1); cp16(bb + 3*BUFSZ + so2, Blo + gb2); \
        CP_COMMIT(); } while (0)

    LaneAddr la = lane_addr(lane, wm, wn);

    STAGE4(0, 0);
    for (int kc = 0; kc < 8; kc++) {
        if (kc < 7) STAGE4((kc+1)*32, (kc+1) & 1);
        if (kc < 7) CP_WAIT1(); else CP_WAIT0();
        __syncthreads();
        uint32_t bb = sb + (kc & 1)*4*BUFSZ;
        uint32_t aAh = bb, aAl = bb + BUFSZ, aBh = bb + 2*BUFSZ, aBl = bb + 3*BUFSZ;
        #pragma unroll
        for (int ks = 0; ks < 2; ks++) {
            uint32_t bh[2][4], bl[2][4];
            #pragma unroll
            for (int nf2 = 0; nf2 < 2; nf2++) {
                uint32_t boff = (uint32_t)((la.b_off + nf2*16*SPAD + ks*16) * 2);
                ldm4(bh[nf2], aBh + boff);
                ldm4(bl[nf2], aBl + boff);
            }
            uint32_t ah[4][4], al[4][4];
            #pragma unroll
            for (int mf = 0; mf < 4; mf++) {
                uint32_t aoff = (uint32_t)((la.a_off + mf*16*SPAD + ks*16) * 2);
                ldm4(ah[mf], aAh + aoff);
                ldm4(al[mf], aAl + aoff);
            }
            #pragma unroll
            for (int mf = 0; mf < 4; mf++)
                #pragma unroll
                for (int nf = 0; nf < 4; nf++) {
                    const uint32_t* ph = &bh[nf >> 1][(nf & 1)*2];
                    const uint32_t* pl = &bl[nf >> 1][(nf & 1)*2];
                    mma16816(acc[mf][nf], ah[mf], ph);
                    mma16816(acc[mf][nf], ah[mf], pl);
                    mma16816(acc[mf][nf], al[mf], ph);
                }
        }
        __syncthreads();
    }
    #undef STAGE4

    int tr = lane >> 2, tc = (lane & 3) * 2;
    #pragma unroll
    for (int mf = 0; mf < 4; mf++) {
        #pragma unroll
        for (int nf = 0; nf < 4; nf++) {
            int col = n0 + wn + nf*8 + tc;
            if (col < nvalid) {
                #pragma unroll
                for (int hrow = 0; hrow < 2; hrow++) {
                    int m = m0 + wm + mf*16 + tr + hrow*8;
                    float v0 = acc[mf][nf][hrow*2+0];
                    float v1 = acc[mf][nf][hrow*2+1];
                    if (bias) { v0 += bias[col]; v1 += bias[col+1]; }
                    if (Uhi) {
                        size_t ub = (size_t)m*HDIM + col;
                        v0 += (__bfloat162float(Uhi[ub])   + __bfloat162float(Ulo[ub]))   * Dv[col];
                        v1 += (__bfloat162float(Uhi[ub+1]) + __bfloat162float(Ulo[ub+1])) * Dv[col+1];
                    }
                    *(float2*)(C + (size_t)m*ldc + col) = make_float2(v0, v1);
                }
            }
        }
    }
}

// ---- fused GLU GEMM pair: x += (A@W1^T+b1) * sigmoid(A@W2^T+b2), optional bf16 split of x ----
__global__ __launch_bounds__(256) void mma_gemm_glu(
    const bf16* __restrict__ Ahi, const bf16* __restrict__ Alo,
    const bf16* __restrict__ B1hi, const bf16* __restrict__ B1lo,
    const bf16* __restrict__ B2hi, const bf16* __restrict__ B2lo,
    const float* __restrict__ b1, const float* __restrict__ b2,
    float* __restrict__ X, int emit_split)
{
    extern __shared__ __align__(16) char smem[];
    uint32_t sb = smem_u32(smem);
    int tid = threadIdx.x;
    int wid = tid >> 5, lane = tid & 31;
    int m0 = blockIdx.y * 128;
    int n0 = blockIdx.x * 128;
    int wm = (wid >> 2) * 64;
    int wn = (wid & 3) * 32;

    float acc1[4][4][4], acc2[4][4][4];
    #pragma unroll
    for (int i = 0; i < 4; i++)
        #pragma unroll
        for (int j = 0; j < 4; j++)
            #pragma unroll
            for (int q = 0; q < 4; q++) { acc1[i][j][q] = 0.f; acc2[i][j][q] = 0.f; }

    int s_r = tid >> 2, s_cg = (tid & 3) * 8;
    int s_r2 = s_r + 64;
    uint32_t so1 = (uint32_t)((s_r*SPAD + s_cg) * 2);
    uint32_t so2 = (uint32_t)((s_r2*SPAD + s_cg) * 2);

    #define STAGE6(k0, buf) do { \
        uint32_t bb = sb + (buf)*6*BUFSZ; \
        size_t ga1 = (size_t)(m0 + s_r)*HDIM + (k0) + s_cg; \
        size_t gb1 = (size_t)(n0 + s_r)*HDIM + (k0) + s_cg; \
        size_t ga2 = (size_t)(m0 + s_r2)*HDIM + (k0) + s_cg; \
        size_t gb2 = (size_t)(n0 + s_r2)*HDIM + (k0) + s_cg; \
        cp16(bb + 0*BUFSZ + so1, Ahi  + ga1); cp16(bb + 0*BUFSZ + so2, Ahi  + ga2); \
        cp16(bb + 1*BUFSZ + so1, Alo  + ga1); cp16(bb + 1*BUFSZ + so2, Alo  + ga2); \
        cp16(bb + 2*BUFSZ + so1, B1hi + gb1); cp16(bb + 2*BUFSZ + so2, B1hi + gb2); \
        cp16(bb + 3*BUFSZ + so1, B1lo + gb1); cp16(bb + 3*BUFSZ + so2, B1lo + gb2); \
        cp16(bb + 4*BUFSZ + so1, B2hi + gb1); cp16(bb + 4*BUFSZ + so2, B2hi + gb2); \
        cp16(bb + 5*BUFSZ + so1, B2lo + gb1); cp16(bb + 5*BUFSZ + so2, B2lo + gb2); \
        CP_COMMIT(); } while (0)

    LaneAddr la = lane_addr(lane, wm, wn);

    STAGE6(0, 0);
    for (int kc = 0; kc < 8; kc++) {
        if (kc < 7) STAGE6((kc+1)*32, (kc+1) & 1);
        if (kc < 7) CP_WAIT1(); else CP_WAIT0();
        __syncthreads();
        uint32_t bb = sb + (kc & 1)*6*BUFSZ;
        uint32_t aAh = bb, aAl = bb + BUFSZ;
        #pragma unroll
        for (int ks = 0; ks < 2; ks++) {
            uint32_t ah[4][4], al[4][4];
            #pragma unroll
            for (int mf = 0; mf < 4; mf++) {
                uint32_t aoff = (uint32_t)((la.a_off + mf*16*SPAD + ks*16) * 2);
                ldm4(ah[mf], aAh + aoff);
                ldm4(al[mf], aAl + aoff);
            }
            // matrix 1 then matrix 2 (keeps B-fragment registers low)
            #pragma unroll
            for (int mat = 0; mat < 2; mat++) {
                uint32_t aBh = bb + (2 + mat*2)*BUFSZ;
                uint32_t aBl = bb + (3 + mat*2)*BUFSZ;
                uint32_t bh[2][4], bl[2][4];
                #pragma unroll
                for (int nf2 = 0; nf2 < 2; nf2++) {
                    uint32_t boff = (uint32_t)((la.b_off + nf2*16*SPAD + ks*16) * 2);
                    ldm4(bh[nf2], aBh + boff);
                    ldm4(bl[nf2], aBl + boff);
                }
                #pragma unroll
                for (int mf = 0; mf < 4; mf++)
                    #pragma unroll
                    for (int nf = 0; nf < 4; nf++) {
                        const uint32_t* ph = &bh[nf >> 1][(nf & 1)*2];
                        const uint32_t* pl = &bl[nf >> 1][(nf & 1)*2];
                        float* a = mat ? acc2[mf][nf] : acc1[mf][nf];
                        mma16816(a, ah[mf], ph);
                        mma16816(a, ah[mf], pl);
                        mma16816(a, al[mf], ph);
                    }
            }
        }
        __syncthreads();
    }
    #undef STAGE6

    int tr = lane >> 2, tc = (lane & 3) * 2;
    #pragma unroll
    for (int mf = 0; mf < 4; mf++) {
        #pragma unroll
        for (int nf = 0; nf < 4; nf++) {
            int col = n0 + wn + nf*8 + tc;
            #pragma unroll
            for (int hrow = 0; hrow < 2; hrow++) {
                int m = m0 + wm + mf*16 + tr + hrow*8;
                size_t xi = (size_t)m*HDIM + col;
                float u0 = acc1[mf][nf][hrow*2+0] + b1[col];
                float u1 = acc1[mf][nf][hrow*2+1] + b1[col+1];
                float w0 = acc2[mf][nf][hrow*2+0] + b2[col];
                float w1 = acc2[mf][nf][hrow*2+1] + b2[col+1];
                float2 xv = *(float2*)(X + xi);
                xv.x += u0 / (1.f + expf(-w0));
                xv.y += u1 / (1.f + expf(-w1));
                *(float2*)(X + xi) = xv;
                if (emit_split) {
                    bf16 hi, lo;
                    split2(xv.x, hi, lo); g_x_hi[xi] = hi;   g_x_lo[xi] = lo;
                    split2(xv.y, hi, lo); g_x_hi[xi+1] = hi; g_x_lo[xi+1] = lo;
                }
            }
        }
    }
}

// ---------------- host launch ----------------
extern "C" void kernel_launch(void* const* d_in, const int* in_sizes, int n_in,
                              void* d_out, int out_size)
{
    const float* latent     = (const float*)d_in[0];
    const float* W_expand   = (const float*)d_in[1];
    const float* b_expand   = (const float*)d_in[2];
    const float* norm_scale = (const float*)d_in[3];
    const float* norm_bias  = (const float*)d_in[4];
    const float* Lambda_re  = (const float*)d_in[5];
    const float* Lambda_im  = (const float*)d_in[6];
    const float* B_re       = (const float*)d_in[7];
    const float* B_im       = (const float*)d_in[8];
    const float* C_re       = (const float*)d_in[9];
    const float* C_im       = (const float*)d_in[10];
    const float* Dmat       = (const float*)d_in[11];
    const float* log_step   = (const float*)d_in[12];
    const float* W1         = (const float*)d_in[13];
    const float* b1         = (const float*)d_in[14];
    const float* W2         = (const float*)d_in[15];
    const float* b2         = (const float*)d_in[16];
    const float* W_out      = (const float*)d_in[17];
    const float* b_out      = (const float*)d_in[18];
    float* out = (float*)d_out;

    cudaFuncSetAttribute(mma_gemm,     cudaFuncAttributeMaxDynamicSharedMemorySize, SMEM_G4);
    cudaFuncSetAttribute(mma_gemm_glu, cudaFuncAttributeMaxDynamicSharedMemorySize, SMEM_G6);

    float *p_x, *p_bu, *p_t1;
    bf16 *p_hh, *p_hl, *p_xsh, *p_xsl, *p_xh, *p_xl;
    bf16 *p_Wbt_h, *p_Wbt_l, *p_Wct_h, *p_Wct_l, *p_W1t_h, *p_W1t_l, *p_W2t_h, *p_W2t_l, *p_Wot_h, *p_Wot_l;
    cudaGetSymbolAddress((void**)&p_x,  g_x);
    cudaGetSymbolAddress((void**)&p_bu, g_bu);
    cudaGetSymbolAddress((void**)&p_t1, g_t1);
    cudaGetSymbolAddress((void**)&p_hh, g_h_hi);
    cudaGetSymbolAddress((void**)&p_hl, g_h_lo);
    cudaGetSymbolAddress((void**)&p_xsh, g_xs_hi);
    cudaGetSymbolAddress((void**)&p_xsl, g_xs_lo);
    cudaGetSymbolAddress((void**)&p_xh, g_x_hi);
    cudaGetSymbolAddress((void**)&p_xl, g_x_lo);
    cudaGetSymbolAddress((void**)&p_Wbt_h, g_Wbt_hi);
    cudaGetSymbolAddress((void**)&p_Wbt_l, g_Wbt_lo);
    cudaGetSymbolAddress((void**)&p_Wct_h, g_Wct_hi);
    cudaGetSymbolAddress((void**)&p_Wct_l, g_Wct_lo);
    cudaGetSymbolAddress((void**)&p_W1t_h, g_W1t_hi);
    cudaGetSymbolAddress((void**)&p_W1t_l, g_W1t_lo);
    cudaGetSymbolAddress((void**)&p_W2t_h, g_W2t_hi);
    cudaGetSymbolAddress((void**)&p_W2t_l, g_W2t_lo);
    cudaGetSymbolAddress((void**)&p_Wot_h, g_Wot_hi);
    cudaGetSymbolAddress((void**)&p_Wot_l, g_Wot_lo);

    // setup
    expand_kernel<<<1, HDIM>>>(latent, W_expand, b_expand);
    broadcast_kernel<<<1024, 256>>>();
    setup_params<<<NLAYERS, PDIM>>>(Lambda_re, Lambda_im, B_re, B_im, C_re, C_im, log_step);
    for (int i = 0; i < NLAYERS; i++) {
        convert_w<<<(HDIM*HDIM + 255)/256, 256>>>(W1 + (size_t)i*HDIM*HDIM,
                                                  p_W1t_h + (size_t)i*HDIM*HDIM,
                                                  p_W1t_l + (size_t)i*HDIM*HDIM, HDIM, HDIM);
        convert_w<<<(HDIM*HDIM + 255)/256, 256>>>(W2 + (size_t)i*HDIM*HDIM,
                                                  p_W2t_h + (size_t)i*HDIM*HDIM,
                                                  p_W2t_l + (size_t)i*HDIM*HDIM, HDIM, HDIM);
    }
    convert_wout<<<(128*HDIM + 255)/256, 256>>>(W_out);

    dim3 gblk(256);
    dim3 ggrid(2, L_SEQ/128);   // (N tiles, M tiles)

    for (int i = 0; i < NLAYERS; i++) {
        const float* sc = norm_scale + i*HDIM;
        const float* bi = norm_bias  + i*HDIM;
        size_t wo = (size_t)i*HDIM*HDIM;
        // 1. pre-norm: h = LN(x) -> bf16 split
        ln_act_kernel<<<L_SEQ/8, 256>>>(p_x, p_hh, p_hl, sc, bi, 0);
        // 2. Bu = h @ Wb
        mma_gemm<<<ggrid, gblk, SMEM_G4>>>(p_hh, p_hl, p_Wbt_h + wo, p_Wbt_l + wo,
                                           p_bu, HDIM, HDIM, nullptr, nullptr, nullptr, nullptr);
        // 3. scan -> xs bf16 split
        scanA_kernel<<<NCHUNK, PDIM>>>(p_bu, i);
        scanB_kernel<<<1, PDIM>>>(i);
        scanC_kernel<<<NCHUNK, PDIM>>>(p_bu, i);
        // 4. t1 = xs @ Wc + h*D
        mma_gemm<<<ggrid, gblk, SMEM_G4>>>(p_xsh, p_xsl, p_Wct_h + wo, p_Wct_l + wo,
                                           p_t1, HDIM, HDIM, nullptr, p_hh, p_hl, Dmat + i*HDIM);
        // 5. h = gelu(LN(t1)) -> bf16 split
        ln_act_kernel<<<L_SEQ/8, 256>>>(p_t1, p_hh, p_hl, sc, bi, 1);
        // 6. fused GLU pair + gate + residual (+ split emit on last layer)
        mma_gemm_glu<<<ggrid, gblk, SMEM_G6>>>(p_hh, p_hl,
                                               p_W1t_h + wo, p_W1t_l + wo,
                                               p_W2t_h + wo, p_W2t_l + wo,
                                               b1 + i*HDIM, b2 + i*HDIM,
                                               p_x, i == NLAYERS-1 ? 1 : 0);
    }
    // output head: out = x @ W_out + b_out  (N=64, padded B to 128 rows)
    dim3 hgrid(1, L_SEQ/128);
    mma_gemm<<<hgrid, gblk, SMEM_G4>>>(p_xh, p_xl, p_Wot_h, p_Wot_l,
                                       out, 64, 64, b_out, nullptr, nullptr, nullptr);
}

// round 10
// speedup vs baseline: 1.8923x; 1.0034x over previous
#include <cuda_runtime.h>
#include <cuda_bf16.h>
#include <math.h>
#include <stdint.h>

#define L_SEQ   32768
#define HDIM    256
#define PDIM    128
#define NLAYERS 4
#define NCHUNK  256
#define TCHUNK  128

typedef __nv_bfloat16 bf16;

// ---------------- scratch (static __device__, no allocation) ----------------
__device__ float  g_x  [L_SEQ*HDIM];
__device__ float  g_bu [L_SEQ*HDIM];
__device__ float  g_t1 [L_SEQ*HDIM];
__device__ bf16   g_h_hi [L_SEQ*HDIM];
__device__ bf16   g_h_lo [L_SEQ*HDIM];
__device__ bf16   g_xs_hi[L_SEQ*HDIM];
__device__ bf16   g_xs_lo[L_SEQ*HDIM];
__device__ bf16   g_x_hi [L_SEQ*HDIM];
__device__ bf16   g_x_lo [L_SEQ*HDIM];
// transposed + bf16-split weights: [N][K] layout, K contiguous
__device__ bf16   g_Wbt_hi[NLAYERS][HDIM*HDIM];
__device__ bf16   g_Wbt_lo[NLAYERS][HDIM*HDIM];
__device__ bf16   g_Wct_hi[NLAYERS][HDIM*HDIM];
__device__ bf16   g_Wct_lo[NLAYERS][HDIM*HDIM];
__device__ bf16   g_W1t_hi[NLAYERS][HDIM*HDIM];
__device__ bf16   g_W1t_lo[NLAYERS][HDIM*HDIM];
__device__ bf16   g_W2t_hi[NLAYERS][HDIM*HDIM];
__device__ bf16   g_W2t_lo[NLAYERS][HDIM*HDIM];
__device__ bf16   g_Wot_hi[128*HDIM];   // W_out^T zero-padded to 128 rows
__device__ bf16   g_Wot_lo[128*HDIM];
__device__ float2 g_lam [NLAYERS][PDIM];
__device__ float2 g_lamT[NLAYERS][PDIM];
__device__ float2 g_E [NCHUNK*PDIM];
__device__ float2 g_Hc[NCHUNK*PDIM];
__device__ float  g_x0[HDIM];

// ---------------- PTX helpers ----------------
__device__ __forceinline__ uint32_t smem_u32(const void* p) {
    uint32_t a;
    asm("{ .reg .u64 t; cvta.to.shared.u64 t, %1; cvt.u32.u64 %0, t; }" : "=r"(a) : "l"(p));
    return a;
}
__device__ __forceinline__ void ldm4(uint32_t* r, uint32_t addr) {
    asm volatile("ldmatrix.sync.aligned.m8n8.x4.shared.b16 {%0,%1,%2,%3}, [%4];"
                 : "=r"(r[0]), "=r"(r[1]), "=r"(r[2]), "=r"(r[3]) : "r"(addr));
}
__device__ __forceinline__ void mma16816(float* c, const uint32_t* a, const uint32_t* b) {
    asm volatile("mma.sync.aligned.m16n8k16.row.col.f32.bf16.bf16.f32 "
                 "{%0,%1,%2,%3}, {%4,%5,%6,%7}, {%8,%9}, {%0,%1,%2,%3};"
                 : "+f"(c[0]), "+f"(c[1]), "+f"(c[2]), "+f"(c[3])
                 : "r"(a[0]), "r"(a[1]), "r"(a[2]), "r"(a[3]), "r"(b[0]), "r"(b[1]));
}
__device__ __forceinline__ void cp16(uint32_t saddr, const void* gaddr) {
    asm volatile("cp.async.cg.shared.global [%0], [%1], 16;" :: "r"(saddr), "l"(gaddr));
}
#define CP_COMMIT() asm volatile("cp.async.commit_group;" ::: "memory")
#define CP_WAIT1()  asm volatile("cp.async.wait_group 1;" ::: "memory")
#define CP_WAIT0()  asm volatile("cp.async.wait_group 0;" ::: "memory")
__device__ __forceinline__ void split2(float x, bf16& hi, bf16& lo) {
    hi = __float2bfloat16_rn(x);
    lo = __float2bfloat16_rn(x - __bfloat162float(hi));
}

// ---------------- setup kernels ----------------
__global__ void expand_kernel(const float* __restrict__ latent,
                              const float* __restrict__ W,
                              const float* __restrict__ b)
{
    int h = threadIdx.x;
    float s = 0.f;
    for (int l = 0; l < HDIM; l++) s += latent[l] * W[l*HDIM + h];
    s += b[h];
    g_x0[h] = s > 0.f ? s : 0.01f * s;
}

__global__ void broadcast_kernel()
{
    size_t n = (size_t)L_SEQ * HDIM / 4;
    const float4* src = (const float4*)g_x0;
    float4* dst = (float4*)g_x;
    for (size_t i = (size_t)blockIdx.x*blockDim.x + threadIdx.x; i < n;
         i += (size_t)gridDim.x*blockDim.x)
        dst[i] = src[i & (HDIM/4 - 1)];
}

__global__ void setup_params(const float* __restrict__ Lre, const float* __restrict__ Lim,
                             const float* __restrict__ Bre, const float* __restrict__ Bim,
                             const float* __restrict__ Cre, const float* __restrict__ Cim,
                             const float* __restrict__ log_step)
{
    int layer = blockIdx.x;
    int p = threadIdx.x;                 // 128 threads
    float step = expf(log_step[layer*PDIM + p]);
    float lr = Lre[layer*PDIM + p], li = Lim[layer*PDIM + p];
    float er  = expf(lr*step);
    float lbr = er * cosf(li*step);
    float lbi = er * sinf(li*step);
    g_lam[layer][p] = make_float2(lbr, lbi);
    float tr = lbr, ti = lbi;
    #pragma unroll
    for (int i = 0; i < 7; i++) { float nr2 = tr*tr - ti*ti; ti = 2.f*tr*ti; tr = nr2; }
    g_lamT[layer][p] = make_float2(tr, ti);
    float nr = lbr - 1.f, ni = lbi;
    float den = lr*lr + li*li;
    float fr = (nr*lr + ni*li) / den;
    float fi = (ni*lr - nr*li) / den;
    const float* brp = Bre + ((size_t)layer*PDIM + p)*HDIM;
    const float* bip = Bim + ((size_t)layer*PDIM + p)*HDIM;
    for (int h = 0; h < HDIM; h++) {
        float br = brp[h], bi = bip[h];
        bf16 hi, lo;
        split2(fr*br - fi*bi, hi, lo);
        g_Wbt_hi[layer][p*HDIM + h] = hi;         g_Wbt_lo[layer][p*HDIM + h] = lo;
        split2(fr*bi + fi*br, hi, lo);
        g_Wbt_hi[layer][(PDIM+p)*HDIM + h] = hi;  g_Wbt_lo[layer][(PDIM+p)*HDIM + h] = lo;
        split2( 2.f * Cre[((size_t)layer*HDIM + h)*PDIM + p], hi, lo);
        g_Wct_hi[layer][h*HDIM + p] = hi;         g_Wct_lo[layer][h*HDIM + p] = lo;
        split2(-2.f * Cim[((size_t)layer*HDIM + h)*PDIM + p], hi, lo);
        g_Wct_hi[layer][h*HDIM + PDIM + p] = hi;  g_Wct_lo[layer][h*HDIM + PDIM + p] = lo;
    }
}

// one kernel converting W1, W2 (all layers) and W_out (transpose + bf16 split)
__global__ void convert_all(const float* __restrict__ W1, const float* __restrict__ W2,
                            const float* __restrict__ Wout)
{
    const int total1 = NLAYERS*HDIM*HDIM;
    const int total  = 2*total1 + 128*HDIM;
    for (int idx = blockIdx.x*blockDim.x + threadIdx.x; idx < total;
         idx += gridDim.x*blockDim.x) {
        bf16 hi, lo;
        if (idx < total1) {
            int l = idx / (HDIM*HDIM), r = idx - l*(HDIM*HDIM);
            int n = r / HDIM, k = r - n*HDIM;
            split2(W1[(size_t)l*HDIM*HDIM + k*HDIM + n], hi, lo);
            g_W1t_hi[l][r] = hi; g_W1t_lo[l][r] = lo;
        } else if (idx < 2*total1) {
            int j = idx - total1;
            int l = j / (HDIM*HDIM), r = j - l*(HDIM*HDIM);
            int n = r / HDIM, k = r - n*HDIM;
            split2(W2[(size_t)l*HDIM*HDIM + k*HDIM + n], hi, lo);
            g_W2t_hi[l][r] = hi; g_W2t_lo[l][r] = lo;
        } else {
            int j = idx - 2*total1;
            int n = j >> 8, k = j & 255;
            float v = (n < 64) ? Wout[k*64 + n] : 0.f;
            split2(v, hi, lo);
            g_Wot_hi[j] = hi; g_Wot_lo[j] = lo;
        }
    }
}

// ---------------- LayerNorm (warp per row) -> bf16 split, optional gelu ----------------
__global__ void ln_act_kernel(const float* __restrict__ X,
                              bf16* __restrict__ Yhi, bf16* __restrict__ Ylo,
                              const float* __restrict__ scale, const float* __restrict__ bias,
                              int gelu_flag)
{
    int row  = blockIdx.x * (blockDim.x >> 5) + (threadIdx.x >> 5);
    int lane = threadIdx.x & 31;
    const float* x = X + (size_t)row * HDIM;
    float v[8], s = 0.f, s2 = 0.f;
    #pragma unroll
    for (int i = 0; i < 8; i++) {
        float t = x[lane + 32*i];
        v[i] = t; s += t; s2 += t*t;
    }
    #pragma unroll
    for (int o = 16; o; o >>= 1) {
        s  += __shfl_xor_sync(0xffffffffu, s,  o);
        s2 += __shfl_xor_sync(0xffffffffu, s2, o);
    }
    float mu  = s  * (1.f/HDIM);
    float var = s2 * (1.f/HDIM) - mu*mu;
    float rs  = rsqrtf(var + 1e-6f);
    #pragma unroll
    for (int i = 0; i < 8; i++) {
        int c = lane + 32*i;
        float n = (v[i] - mu) * rs * scale[c] + bias[c];
        if (gelu_flag) {
            float t = 0.7978845608028654f * (n + 0.044715f * n*n*n);
            n = 0.5f * n * (1.f + tanhf(t));
        }
        bf16 hi, lo;
        split2(n, hi, lo);
        Yhi[(size_t)row*HDIM + c] = hi;
        Ylo[(size_t)row*HDIM + c] = lo;
    }
}

// ---------------- chunked diagonal complex scan ----------------
__global__ void scanA_kernel(const float* __restrict__ Bu, int layer)
{
    int c = blockIdx.x, p = threadIdx.x;
    float2 lam = g_lam[layer][p];
    float xr = 0.f, xi = 0.f;
    const float* b = Bu + (size_t)c * TCHUNK * HDIM;
    for (int t = 0; t < TCHUNK; t++) {
        float br = b[t*HDIM + p], bi = b[t*HDIM + PDIM + p];
        float nr = lam.x*xr - lam.y*xi + br;
        float ni = lam.x*xi + lam.y*xr + bi;
        xr = nr; xi = ni;
    }
    g_E[c*PDIM + p] = make_float2(xr, xi);
}

__global__ void scanB_kernel(int layer)
{
    int p = threadIdx.x;
    float2 a = g_lamT[layer][p];
    float xr = 0.f, xi = 0.f;
    for (int c = 0; c < NCHUNK; c++) {
        g_Hc[c*PDIM + p] = make_float2(xr, xi);
        float2 e = g_E[c*PDIM + p];
        float nr = a.x*xr - a.y*xi + e.x;
        float ni = a.x*xi + a.y*xr + e.y;
        xr = nr; xi = ni;
    }
}

__global__ void scanC_kernel(const float* __restrict__ Bu, int layer)
{
    int c = blockIdx.x, p = threadIdx.x;
    float2 lam = g_lam[layer][p];
    float2 h0  = g_Hc[c*PDIM + p];
    float xr = h0.x, xi = h0.y;
    const float* b = Bu + (size_t)c * TCHUNK * HDIM;
    size_t base = (size_t)c * TCHUNK * HDIM;
    for (int t = 0; t < TCHUNK; t++) {
        float br = b[t*HDIM + p], bi = b[t*HDIM + PDIM + p];
        float nr = lam.x*xr - lam.y*xi + br;
        float ni = lam.x*xi + lam.y*xr + bi;
        xr = nr; xi = ni;
        bf16 hi, lo;
        split2(xr, hi, lo);
        g_xs_hi[base + t*HDIM + p] = hi;        g_xs_lo[base + t*HDIM + p] = lo;
        split2(xi, hi, lo);
        g_xs_hi[base + t*HDIM + PDIM + p] = hi; g_xs_lo[base + t*HDIM + PDIM + p] = lo;
    }
}

// ---------------- mma.sync split-bf16 GEMM (cp.async double-buffered) ----------------
#define SPAD 40                       // smem row stride in bf16 (80B, 16B-aligned)
#define BUFSZ (128*SPAD*2)            // 10240 B per operand buffer
#define SMEM_G4 (8*BUFSZ)             // single GEMM: 4 ops x 2 bufs
#define SMEM_G6 (12*BUFSZ)            // GLU GEMM: 6 ops x 2 bufs

// fragment-loading lane address components
struct LaneAddr {
    int a_off;   // (row part)*SPAD + k-half, in elements
    int b_off;
};
__device__ __forceinline__ LaneAddr lane_addr(int lane, int wm, int wn) {
    LaneAddr la;
    int a_r = lane & 15, a_c = (lane >> 4) * 8;
    int b_q = lane >> 3, b_r = lane & 7;
    int b_n_add = (b_q >> 1) * 8 + b_r;
    int b_k_add = (b_q & 1) * 8;
    la.a_off = (wm + a_r)*SPAD + a_c;
    la.b_off = (wn + b_n_add)*SPAD + b_k_add;
    return la;
}

// 128 threads, 4 warps, warp tile 64x64, 2 CTAs/SM target
__global__ __launch_bounds__(128, 2) void mma_gemm(
    const bf16* __restrict__ Ahi, const bf16* __restrict__ Alo,
    const bf16* __restrict__ Bhi, const bf16* __restrict__ Blo,
    float* __restrict__ C, int ldc, int nvalid,
    const float* __restrict__ bias,
    const bf16* __restrict__ Uhi, const bf16* __restrict__ Ulo,
    const float* __restrict__ Dv)
{
    extern __shared__ __align__(16) char smem[];
    uint32_t sb = smem_u32(smem);
    int tid = threadIdx.x;
    int wid = tid >> 5, lane = tid & 31;
    int m0 = blockIdx.y * 128;
    int n0 = blockIdx.x * 128;
    int wm = (wid >> 1) * 64;    // warp M offset (0 or 64)
    int wn = (wid & 1) * 64;     // warp N offset (0 or 64)

    float acc[4][8][4];
    #pragma unroll
    for (int i = 0; i < 4; i++)
        #pragma unroll
        for (int j = 0; j < 8; j++)
            #pragma unroll
            for (int q = 0; q < 4; q++) acc[i][j][q] = 0.f;

    #define STAGE4(k0, buf) do { \
        uint32_t bb = sb + (buf)*4*BUFSZ; \
        _Pragma("unroll") \
        for (int i = 0; i < 4; i++) { \
            int idx = tid + i*128; \
            int r = idx >> 2, cg = (idx & 3) * 8; \
            uint32_t so = (uint32_t)((r*SPAD + cg) * 2); \
            size_t ga = (size_t)(m0 + r)*HDIM + (k0) + cg; \
            size_t gb = (size_t)(n0 + r)*HDIM + (k0) + cg; \
            cp16(bb + 0*BUFSZ + so, Ahi + ga); \
            cp16(bb + 1*BUFSZ + so, Alo + ga); \
            cp16(bb + 2*BUFSZ + so, Bhi + gb); \
            cp16(bb + 3*BUFSZ + so, Blo + gb); \
        } \
        CP_COMMIT(); } while (0)

    LaneAddr la = lane_addr(lane, wm, wn);

    STAGE4(0, 0);
    for (int kc = 0; kc < 8; kc++) {
        if (kc < 7) STAGE4((kc+1)*32, (kc+1) & 1);
        if (kc < 7) CP_WAIT1(); else CP_WAIT0();
        __syncthreads();
        uint32_t bb = sb + (kc & 1)*4*BUFSZ;
        uint32_t aAh = bb, aAl = bb + BUFSZ, aBh = bb + 2*BUFSZ, aBl = bb + 3*BUFSZ;
        #pragma unroll
        for (int ks = 0; ks < 2; ks++) {
            uint32_t bh[4][4], bl[4][4];
            #pragma unroll
            for (int nf2 = 0; nf2 < 4; nf2++) {
                uint32_t boff = (uint32_t)((la.b_off + nf2*16*SPAD + ks*16) * 2);
                ldm4(bh[nf2], aBh + boff);
                ldm4(bl[nf2], aBl + boff);
            }
            uint32_t ah[4][4], al[4][4];
            #pragma unroll
            for (int mf = 0; mf < 4; mf++) {
                uint32_t aoff = (uint32_t)((la.a_off + mf*16*SPAD + ks*16) * 2);
                ldm4(ah[mf], aAh + aoff);
                ldm4(al[mf], aAl + aoff);
            }
            #pragma unroll
            for (int mf = 0; mf < 4; mf++)
                #pragma unroll
                for (int nf = 0; nf < 8; nf++) {
                    const uint32_t* ph = &bh[nf >> 1][(nf & 1)*2];
                    const uint32_t* pl = &bl[nf >> 1][(nf & 1)*2];
                    mma16816(acc[mf][nf], ah[mf], ph);
                    mma16816(acc[mf][nf], ah[mf], pl);
                    mma16816(acc[mf][nf], al[mf], ph);
                }
        }
        __syncthreads();
    }
    #undef STAGE4

    int tr = lane >> 2, tc = (lane & 3) * 2;
    #pragma unroll
    for (int mf = 0; mf < 4; mf++) {
        #pragma unroll
        for (int nf = 0; nf < 8; nf++) {
            int col = n0 + wn + nf*8 + tc;
            if (col < nvalid) {
                #pragma unroll
                for (int hrow = 0; hrow < 2; hrow++) {
                    int m = m0 + wm + mf*16 + tr + hrow*8;
                    float v0 = acc[mf][nf][hrow*2+0];
                    float v1 = acc[mf][nf][hrow*2+1];
                    if (bias) { v0 += bias[col]; v1 += bias[col+1]; }
                    if (Uhi) {
                        size_t ub = (size_t)m*HDIM + col;
                        v0 += (__bfloat162float(Uhi[ub])   + __bfloat162float(Ulo[ub]))   * Dv[col];
                        v1 += (__bfloat162float(Uhi[ub+1]) + __bfloat162float(Ulo[ub+1])) * Dv[col+1];
                    }
                    *(float2*)(C + (size_t)m*ldc + col) = make_float2(v0, v1);
                }
            }
        }
    }
}

// ---- fused GLU GEMM pair: x += (A@W1^T+b1) * sigmoid(A@W2^T+b2), optional bf16 split of x ----
__global__ __launch_bounds__(256) void mma_gemm_glu(
    const bf16* __restrict__ Ahi, const bf16* __restrict__ Alo,
    const bf16* __restrict__ B1hi, const bf16* __restrict__ B1lo,
    const bf16* __restrict__ B2hi, const bf16* __restrict__ B2lo,
    const float* __restrict__ b1, const float* __restrict__ b2,
    float* __restrict__ X, int emit_split)
{
    extern __shared__ __align__(16) char smem[];
    uint32_t sb = smem_u32(smem);
    int tid = threadIdx.x;
    int wid = tid >> 5, lane = tid & 31;
    int m0 = blockIdx.y * 128;
    int n0 = blockIdx.x * 128;
    int wm = (wid >> 2) * 64;
    int wn = (wid & 3) * 32;

    float acc1[4][4][4], acc2[4][4][4];
    #pragma unroll
    for (int i = 0; i < 4; i++)
        #pragma unroll
        for (int j = 0; j < 4; j++)
            #pragma unroll
            for (int q = 0; q < 4; q++) { acc1[i][j][q] = 0.f; acc2[i][j][q] = 0.f; }

    int s_r = tid >> 2, s_cg = (tid & 3) * 8;
    int s_r2 = s_r + 64;
    uint32_t so1 = (uint32_t)((s_r*SPAD + s_cg) * 2);
    uint32_t so2 = (uint32_t)((s_r2*SPAD + s_cg) * 2);

    #define STAGE6(k0, buf) do { \
        uint32_t bb = sb + (buf)*6*BUFSZ; \
        size_t ga1 = (size_t)(m0 + s_r)*HDIM + (k0) + s_cg; \
        size_t gb1 = (size_t)(n0 + s_r)*HDIM + (k0) + s_cg; \
        size_t ga2 = (size_t)(m0 + s_r2)*HDIM + (k0) + s_cg; \
        size_t gb2 = (size_t)(n0 + s_r2)*HDIM + (k0) + s_cg; \
        cp16(bb + 0*BUFSZ + so1, Ahi  + ga1); cp16(bb + 0*BUFSZ + so2, Ahi  + ga2); \
        cp16(bb + 1*BUFSZ + so1, Alo  + ga1); cp16(bb + 1*BUFSZ + so2, Alo  + ga2); \
        cp16(bb + 2*BUFSZ + so1, B1hi + gb1); cp16(bb + 2*BUFSZ + so2, B1hi + gb2); \
        cp16(bb + 3*BUFSZ + so1, B1lo + gb1); cp16(bb + 3*BUFSZ + so2, B1lo + gb2); \
        cp16(bb + 4*BUFSZ + so1, B2hi + gb1); cp16(bb + 4*BUFSZ + so2, B2hi + gb2); \
        cp16(bb + 5*BUFSZ + so1, B2lo + gb1); cp16(bb + 5*BUFSZ + so2, B2lo + gb2); \
        CP_COMMIT(); } while (0)

    LaneAddr la = lane_addr(lane, wm, wn);

    STAGE6(0, 0);
    for (int kc = 0; kc < 8; kc++) {
        if (kc < 7) STAGE6((kc+1)*32, (kc+1) & 1);
        if (kc < 7) CP_WAIT1(); else CP_WAIT0();
        __syncthreads();
        uint32_t bb = sb + (kc & 1)*6*BUFSZ;
        uint32_t aAh = bb, aAl = bb + BUFSZ;
        #pragma unroll
        for (int ks = 0; ks < 2; ks++) {
            uint32_t ah[4][4], al[4][4];
            #pragma unroll
            for (int mf = 0; mf < 4; mf++) {
                uint32_t aoff = (uint32_t)((la.a_off + mf*16*SPAD + ks*16) * 2);
                ldm4(ah[mf], aAh + aoff);
                ldm4(al[mf], aAl + aoff);
            }
            // matrix 1 then matrix 2 (keeps B-fragment registers low)
            #pragma unroll
            for (int mat = 0; mat < 2; mat++) {
                uint32_t aBh = bb + (2 + mat*2)*BUFSZ;
                uint32_t aBl = bb + (3 + mat*2)*BUFSZ;
                uint32_t bh[2][4], bl[2][4];
                #pragma unroll
                for (int nf2 = 0; nf2 < 2; nf2++) {
                    uint32_t boff = (uint32_t)((la.b_off + nf2*16*SPAD + ks*16) * 2);
                    ldm4(bh[nf2], aBh + boff);
                    ldm4(bl[nf2], aBl + boff);
                }
                #pragma unroll
                for (int mf = 0; mf < 4; mf++)
                    #pragma unroll
                    for (int nf = 0; nf < 4; nf++) {
                        const uint32_t* ph = &bh[nf >> 1][(nf & 1)*2];
                        const uint32_t* pl = &bl[nf >> 1][(nf & 1)*2];
                        float* a = mat ? acc2[mf][nf] : acc1[mf][nf];
                        mma16816(a, ah[mf], ph);
                        mma16816(a, ah[mf], pl);
                        mma16816(a, al[mf], ph);
                    }
            }
        }
        __syncthreads();
    }
    #undef STAGE6

    int tr = lane >> 2, tc = (lane & 3) * 2;
    #pragma unroll
    for (int mf = 0; mf < 4; mf++) {
        #pragma unroll
        for (int nf = 0; nf < 4; nf++) {
            int col = n0 + wn + nf*8 + tc;
            #pragma unroll
            for (int hrow = 0; hrow < 2; hrow++) {
                int m = m0 + wm + mf*16 + tr + hrow*8;
                size_t xi = (size_t)m*HDIM + col;
                float u0 = acc1[mf][nf][hrow*2+0] + b1[col];
                float u1 = acc1[mf][nf][hrow*2+1] + b1[col+1];
                float w0 = acc2[mf][nf][hrow*2+0] + b2[col];
                float w1 = acc2[mf][nf][hrow*2+1] + b2[col+1];
                float2 xv = *(float2*)(X + xi);
                xv.x += u0 / (1.f + expf(-w0));
                xv.y += u1 / (1.f + expf(-w1));
                *(float2*)(X + xi) = xv;
                if (emit_split) {
                    bf16 hi, lo;
                    split2(xv.x, hi, lo); g_x_hi[xi] = hi;   g_x_lo[xi] = lo;
                    split2(xv.y, hi, lo); g_x_hi[xi+1] = hi; g_x_lo[xi+1] = lo;
                }
            }
        }
    }
}

// ---------------- host launch ----------------
extern "C" void kernel_launch(void* const* d_in, const int* in_sizes, int n_in,
                              void* d_out, int out_size)
{
    const float* latent     = (const float*)d_in[0];
    const float* W_expand   = (const float*)d_in[1];
    const float* b_expand   = (const float*)d_in[2];
    const float* norm_scale = (const float*)d_in[3];
    const float* norm_bias  = (const float*)d_in[4];
    const float* Lambda_re  = (const float*)d_in[5];
    const float* Lambda_im  = (const float*)d_in[6];
    const float* B_re       = (const float*)d_in[7];
    const float* B_im       = (const float*)d_in[8];
    const float* C_re       = (const float*)d_in[9];
    const float* C_im       = (const float*)d_in[10];
    const float* Dmat       = (const float*)d_in[11];
    const float* log_step   = (const float*)d_in[12];
    const float* W1         = (const float*)d_in[13];
    const float* b1         = (const float*)d_in[14];
    const float* W2         = (const float*)d_in[15];
    const float* b2         = (const float*)d_in[16];
    const float* W_out      = (const float*)d_in[17];
    const float* b_out      = (const float*)d_in[18];
    float* out = (float*)d_out;

    cudaFuncSetAttribute(mma_gemm,     cudaFuncAttributeMaxDynamicSharedMemorySize, SMEM_G4);
    cudaFuncSetAttribute(mma_gemm_glu, cudaFuncAttributeMaxDynamicSharedMemorySize, SMEM_G6);

    float *p_x, *p_bu, *p_t1;
    bf16 *p_hh, *p_hl, *p_xsh, *p_xsl, *p_xh, *p_xl;
    bf16 *p_Wbt_h, *p_Wbt_l, *p_Wct_h, *p_Wct_l, *p_W1t_h, *p_W1t_l, *p_W2t_h, *p_W2t_l, *p_Wot_h, *p_Wot_l;
    cudaGetSymbolAddress((void**)&p_x,  g_x);
    cudaGetSymbolAddress((void**)&p_bu, g_bu);
    cudaGetSymbolAddress((void**)&p_t1, g_t1);
    cudaGetSymbolAddress((void**)&p_hh, g_h_hi);
    cudaGetSymbolAddress((void**)&p_hl, g_h_lo);
    cudaGetSymbolAddress((void**)&p_xsh, g_xs_hi);
    cudaGetSymbolAddress((void**)&p_xsl, g_xs_lo);
    cudaGetSymbolAddress((void**)&p_xh, g_x_hi);
    cudaGetSymbolAddress((void**)&p_xl, g_x_lo);
    cudaGetSymbolAddress((void**)&p_Wbt_h, g_Wbt_hi);
    cudaGetSymbolAddress((void**)&p_Wbt_l, g_Wbt_lo);
    cudaGetSymbolAddress((void**)&p_Wct_h, g_Wct_hi);
    cudaGetSymbolAddress((void**)&p_Wct_l, g_Wct_lo);
    cudaGetSymbolAddress((void**)&p_W1t_h, g_W1t_hi);
    cudaGetSymbolAddress((void**)&p_W1t_l, g_W1t_lo);
    cudaGetSymbolAddress((void**)&p_W2t_h, g_W2t_hi);
    cudaGetSymbolAddress((void**)&p_W2t_l, g_W2t_lo);
    cudaGetSymbolAddress((void**)&p_Wot_h, g_Wot_hi);
    cudaGetSymbolAddress((void**)&p_Wot_l, g_Wot_lo);

    // setup: launches 1-4 (convert fused so launch #6 = first mma_gemm for ncu -s 5)
    expand_kernel<<<1, HDIM>>>(latent, W_expand, b_expand);
    broadcast_kernel<<<1024, 256>>>();
    setup_params<<<NLAYERS, PDIM>>>(Lambda_re, Lambda_im, B_re, B_im, C_re, C_im, log_step);
    convert_all<<<2176, 256>>>(W1, W2, W_out);

    dim3 gblk_g(128);    // plain GEMM: 4 warps
    dim3 gblk_u(256);    // GLU GEMM: 8 warps
    dim3 ggrid(2, L_SEQ/128);   // (N tiles, M tiles)

    for (int i = 0; i < NLAYERS; i++) {
        const float* sc = norm_scale + i*HDIM;
        const float* bi = norm_bias  + i*HDIM;
        size_t wo = (size_t)i*HDIM*HDIM;
        // 1. pre-norm: h = LN(x) -> bf16 split
        ln_act_kernel<<<L_SEQ/8, 256>>>(p_x, p_hh, p_hl, sc, bi, 0);
        // 2. Bu = h @ Wb
        mma_gemm<<<ggrid, gblk_g, SMEM_G4>>>(p_hh, p_hl, p_Wbt_h + wo, p_Wbt_l + wo,
                                             p_bu, HDIM, HDIM, nullptr, nullptr, nullptr, nullptr);
        // 3. scan -> xs bf16 split
        scanA_kernel<<<NCHUNK, PDIM>>>(p_bu, i);
        scanB_kernel<<<1, PDIM>>>(i);
        scanC_kernel<<<NCHUNK, PDIM>>>(p_bu, i);
        // 4. t1 = xs @ Wc + h*D
        mma_gemm<<<ggrid, gblk_g, SMEM_G4>>>(p_xsh, p_xsl, p_Wct_h + wo, p_Wct_l + wo,
                                             p_t1, HDIM, HDIM, nullptr, p_hh, p_hl, Dmat + i*HDIM);
        // 5. h = gelu(LN(t1)) -> bf16 split
        ln_act_kernel<<<L_SEQ/8, 256>>>(p_t1, p_hh, p_hl, sc, bi, 1);
        // 6. fused GLU pair + gate + residual (+ split emit on last layer)
        mma_gemm_glu<<<ggrid, gblk_u, SMEM_G6>>>(p_hh, p_hl,
                                                 p_W1t_h + wo, p_W1t_l + wo,
                                                 p_W2t_h + wo, p_W2t_l + wo,
                                                 b1 + i*HDIM, b2 + i*HDIM,
                                                 p_x, i == NLAYERS-1 ? 1 : 0);
    }
    // output head: out = x @ W_out + b_out  (N=64, padded B to 128 rows)
    dim3 hgrid(1, L_SEQ/128);
    mma_gemm<<<hgrid, gblk_g, SMEM_G4>>>(p_xh, p_xl, p_Wot_h, p_Wot_l,
                                         out, 64, 64, b_out, nullptr, nullptr, nullptr);
}

// round 11
// speedup vs baseline: 2.5976x; 1.3727x over previous
#include <cuda_runtime.h>
#include <cuda_bf16.h>
#include <math.h>
#include <stdint.h>

#define L_SEQ   32768
#define HDIM    256
#define PDIM    128
#define NLAYERS 4
#define NCHUNK  256
#define TCHUNK  128

// ---------------- scratch (static __device__, no allocation) ----------------
__device__ float  g_x  [L_SEQ*HDIM];
__device__ float  g_bu [L_SEQ*HDIM];
__device__ float  g_t1 [L_SEQ*HDIM];   // Wc output; last layer: rounded x for head
__device__ float  g_h  [L_SEQ*HDIM];   // LN output (tf32-rounded)
__device__ float  g_xs [L_SEQ*HDIM];   // scan output (tf32-rounded)
// transposed + tf32-rounded weights: [N][K] layout, K contiguous
__device__ float  g_Wbt[NLAYERS][HDIM*HDIM];
__device__ float  g_Wct[NLAYERS][HDIM*HDIM];
__device__ float  g_W1t[NLAYERS][HDIM*HDIM];
__device__ float  g_W2t[NLAYERS][HDIM*HDIM];
__device__ float  g_Wot[128*HDIM];     // W_out^T zero-padded to 128 rows
__device__ float2 g_lam [NLAYERS][PDIM];
__device__ float2 g_lamT[NLAYERS][PDIM];
__device__ float2 g_E [NCHUNK*PDIM];
__device__ float  g_x0[HDIM];

// ---------------- PTX helpers ----------------
__device__ __forceinline__ uint32_t smem_u32(const void* p) {
    uint32_t a;
    asm("{ .reg .u64 t; cvta.to.shared.u64 t, %1; cvt.u32.u64 %0, t; }" : "=r"(a) : "l"(p));
    return a;
}
__device__ __forceinline__ float tf32r(float x) {
    float y;
    asm("cvt.rna.tf32.f32 %0, %1;" : "=f"(y) : "f"(x));
    return y;
}
__device__ __forceinline__ void mma_tf32(float* c, const uint32_t* a, const uint32_t* b) {
    asm volatile("mma.sync.aligned.m16n8k8.row.col.f32.tf32.tf32.f32 "
                 "{%0,%1,%2,%3}, {%4,%5,%6,%7}, {%8,%9}, {%0,%1,%2,%3};"
                 : "+f"(c[0]), "+f"(c[1]), "+f"(c[2]), "+f"(c[3])
                 : "r"(a[0]), "r"(a[1]), "r"(a[2]), "r"(a[3]), "r"(b[0]), "r"(b[1]));
}
__device__ __forceinline__ void cp16(uint32_t saddr, const void* gaddr) {
    asm volatile("cp.async.cg.shared.global [%0], [%1], 16;" :: "r"(saddr), "l"(gaddr));
}
#define CP_COMMIT() asm volatile("cp.async.commit_group;" ::: "memory")
#define CP_WAIT1()  asm volatile("cp.async.wait_group 1;" ::: "memory")
#define CP_WAIT0()  asm volatile("cp.async.wait_group 0;" ::: "memory")

// ---------------- setup kernels ----------------
__global__ void expand_kernel(const float* __restrict__ latent,
                              const float* __restrict__ W,
                              const float* __restrict__ b)
{
    int h = threadIdx.x;
    float s = 0.f;
    for (int l = 0; l < HDIM; l++) s += latent[l] * W[l*HDIM + h];
    s += b[h];
    g_x0[h] = s > 0.f ? s : 0.01f * s;
}

__global__ void broadcast_kernel()
{
    size_t n = (size_t)L_SEQ * HDIM / 4;
    const float4* src = (const float4*)g_x0;
    float4* dst = (float4*)g_x;
    for (size_t i = (size_t)blockIdx.x*blockDim.x + threadIdx.x; i < n;
         i += (size_t)gridDim.x*blockDim.x)
        dst[i] = src[i & (HDIM/4 - 1)];
}

__global__ void setup_params(const float* __restrict__ Lre, const float* __restrict__ Lim,
                             const float* __restrict__ Bre, const float* __restrict__ Bim,
                             const float* __restrict__ Cre, const float* __restrict__ Cim,
                             const float* __restrict__ log_step)
{
    int layer = blockIdx.x;
    int p = threadIdx.x;                 // 128 threads
    float step = expf(log_step[layer*PDIM + p]);
    float lr = Lre[layer*PDIM + p], li = Lim[layer*PDIM + p];
    float er  = expf(lr*step);
    float lbr = er * cosf(li*step);
    float lbi = er * sinf(li*step);
    g_lam[layer][p] = make_float2(lbr, lbi);
    float tr = lbr, ti = lbi;
    #pragma unroll
    for (int i = 0; i < 7; i++) { float nr2 = tr*tr - ti*ti; ti = 2.f*tr*ti; tr = nr2; }
    g_lamT[layer][p] = make_float2(tr, ti);
    float nr = lbr - 1.f, ni = lbi;
    float den = lr*lr + li*li;
    float fr = (nr*lr + ni*li) / den;
    float fi = (ni*lr - nr*li) / den;
    const float* brp = Bre + ((size_t)layer*PDIM + p)*HDIM;
    const float* bip = Bim + ((size_t)layer*PDIM + p)*HDIM;
    for (int h = 0; h < HDIM; h++) {
        float br = brp[h], bi = bip[h];
        // Wbt[n][k]: n = p (re) or 128+p (im), k = h
        g_Wbt[layer][p*HDIM + h]        = tf32r(fr*br - fi*bi);
        g_Wbt[layer][(PDIM+p)*HDIM + h] = tf32r(fr*bi + fi*br);
        // Wct[n][k]: n = h, k = p (re) / 128+p (im)
        g_Wct[layer][h*HDIM + p]        = tf32r( 2.f * Cre[((size_t)layer*HDIM + h)*PDIM + p]);
        g_Wct[layer][h*HDIM + PDIM + p] = tf32r(-2.f * Cim[((size_t)layer*HDIM + h)*PDIM + p]);
    }
}

// one kernel converting W1, W2 (all layers) and W_out (transpose + tf32 round)
__global__ void convert_all(const float* __restrict__ W1, const float* __restrict__ W2,
                            const float* __restrict__ Wout)
{
    const int total1 = NLAYERS*HDIM*HDIM;
    const int total  = 2*total1 + 128*HDIM;
    for (int idx = blockIdx.x*blockDim.x + threadIdx.x; idx < total;
         idx += gridDim.x*blockDim.x) {
        if (idx < total1) {
            int l = idx / (HDIM*HDIM), r = idx - l*(HDIM*HDIM);
            int n = r / HDIM, k = r - n*HDIM;
            g_W1t[l][r] = tf32r(W1[(size_t)l*HDIM*HDIM + k*HDIM + n]);
        } else if (idx < 2*total1) {
            int j = idx - total1;
            int l = j / (HDIM*HDIM), r = j - l*(HDIM*HDIM);
            int n = r / HDIM, k = r - n*HDIM;
            g_W2t[l][r] = tf32r(W2[(size_t)l*HDIM*HDIM + k*HDIM + n]);
        } else {
            int j = idx - 2*total1;
            int n = j >> 8, k = j & 255;
            g_Wot[j] = (n < 64) ? tf32r(Wout[k*64 + n]) : 0.f;
        }
    }
}

// ---------------- LayerNorm (warp per row) -> tf32-rounded fp32, optional gelu ----------------
__global__ void ln_act_kernel(const float* __restrict__ X, float* __restrict__ Y,
                              const float* __restrict__ scale, const float* __restrict__ bias,
                              int gelu_flag)
{
    int row  = blockIdx.x * (blockDim.x >> 5) + (threadIdx.x >> 5);
    int lane = threadIdx.x & 31;
    const float* x = X + (size_t)row * HDIM;
    float v[8], s = 0.f, s2 = 0.f;
    #pragma unroll
    for (int i = 0; i < 8; i++) {
        float t = x[lane + 32*i];
        v[i] = t; s += t; s2 += t*t;
    }
    #pragma unroll
    for (int o = 16; o; o >>= 1) {
        s  += __shfl_xor_sync(0xffffffffu, s,  o);
        s2 += __shfl_xor_sync(0xffffffffu, s2, o);
    }
    float mu  = s  * (1.f/HDIM);
    float var = s2 * (1.f/HDIM) - mu*mu;
    float rs  = rsqrtf(var + 1e-6f);
    #pragma unroll
    for (int i = 0; i < 8; i++) {
        int c = lane + 32*i;
        float n = (v[i] - mu) * rs * scale[c] + bias[c];
        if (gelu_flag) {
            float t = 0.7978845608028654f * (n + 0.044715f * n*n*n);
            n = 0.5f * n * (1.f + tanhf(t));
        }
        Y[(size_t)row*HDIM + c] = tf32r(n);
    }
}

// ---------------- chunked diagonal complex scan ----------------
__global__ void scanA_kernel(const float* __restrict__ Bu, int layer)
{
    int c = blockIdx.x, p = threadIdx.x;
    float2 lam = g_lam[layer][p];
    float xr = 0.f, xi = 0.f;
    const float* b = Bu + (size_t)c * TCHUNK * HDIM;
    for (int t = 0; t < TCHUNK; t++) {
        float br = b[t*HDIM + p], bi = b[t*HDIM + PDIM + p];
        float nr = lam.x*xr - lam.y*xi + br;
        float ni = lam.x*xi + lam.y*xr + bi;
        xr = nr; xi = ni;
    }
    g_E[c*PDIM + p] = make_float2(xr, xi);
}

// scanC with inline chunk-prefix (replaces scanB): H_c = sum_{j<c} lamT^{c-1-j} E_j
__global__ void scanC_kernel(const float* __restrict__ Bu, float* __restrict__ XS, int layer)
{
    int c = blockIdx.x, p = threadIdx.x;
    float2 lamT = g_lamT[layer][p];
    float2 lam  = g_lam[layer][p];
    float xr = 0.f, xi = 0.f;
    for (int j = 0; j < c; j++) {
        float2 e = g_E[j*PDIM + p];
        float nr = lamT.x*xr - lamT.y*xi + e.x;
        float ni = lamT.x*xi + lamT.y*xr + e.y;
        xr = nr; xi = ni;
    }
    const float* b = Bu + (size_t)c * TCHUNK * HDIM;
    float* o = XS + (size_t)c * TCHUNK * HDIM;
    for (int t = 0; t < TCHUNK; t++) {
        float br = b[t*HDIM + p], bi = b[t*HDIM + PDIM + p];
        float nr = lam.x*xr - lam.y*xi + br;
        float ni = lam.x*xi + lam.y*xr + bi;
        xr = nr; xi = ni;
        o[t*HDIM + p]        = tf32r(xr);
        o[t*HDIM + PDIM + p] = tf32r(xi);
    }
}

// ---------------- tf32 mma GEMM (cp.async double-buffered) ----------------
#define SWW   36                       // smem row stride in words (144B, conflict-free)
#define ABUFW (128*SWW)                // 4608 words per operand buffer
#define ABUFB (ABUFW*4)                // 18432 bytes
#define SMEM_G4 (4*ABUFB)              // plain: [A,B] x 2 bufs = 73728
#define SMEM_G6 (6*ABUFB)              // GLU:  [A,B1,B2] x 2 bufs = 110592

// C[m0:m0+128, n0:n0+128] = A[m0:,K=256] * B^T[n0:,K=256]  (B stored [N][K])
// 128 threads, 4 warps, warp tile 64x64
__global__ __launch_bounds__(128) void mma_gemm(
    const float* __restrict__ A, const float* __restrict__ B,
    float* __restrict__ C, int ldc, int nvalid,
    const float* __restrict__ bias,
    const float* __restrict__ U, const float* __restrict__ Dv)
{
    extern __shared__ __align__(16) float smem[];
    uint32_t sb = smem_u32(smem);
    int tid = threadIdx.x;
    int wid = tid >> 5, lane = tid & 31;
    int m0 = blockIdx.y * 128;
    int n0 = blockIdx.x * 128;
    int wm = (wid >> 1) * 64;
    int wn = (wid & 1) * 64;

    float acc[4][8][4];
    #pragma unroll
    for (int i = 0; i < 4; i++)
        #pragma unroll
        for (int j = 0; j < 8; j++)
            #pragma unroll
            for (int q = 0; q < 4; q++) acc[i][j][q] = 0.f;

    #define STAGE(k0, buf) do { \
        uint32_t ab = sb + (buf)*2*ABUFB; \
        uint32_t bb = ab + ABUFB; \
        _Pragma("unroll") \
        for (int i = 0; i < 8; i++) { \
            int idx = tid + i*128; \
            int r = idx >> 3, cg = (idx & 7) * 4; \
            uint32_t so = (uint32_t)((r*SWW + cg) * 4); \
            cp16(ab + so, A + (size_t)(m0 + r)*HDIM + (k0) + cg); \
            cp16(bb + so, B + (size_t)(n0 + r)*HDIM + (k0) + cg); \
        } \
        CP_COMMIT(); } while (0)

    int ra = lane >> 2, ca = lane & 3;

    STAGE(0, 0);
    for (int kc = 0; kc < 8; kc++) {
        if (kc < 7) STAGE((kc+1)*32, (kc+1) & 1);
        if (kc < 7) CP_WAIT1(); else CP_WAIT0();
        __syncthreads();
        const float* As = smem + (kc & 1)*2*ABUFW;
        const float* Bs = As + ABUFW;
        #pragma unroll
        for (int ks = 0; ks < 4; ks++) {
            int kb = ks*8;
            uint32_t bfrag[8][2];
            #pragma unroll
            for (int nf = 0; nf < 8; nf++) {
                const float* pb = Bs + (wn + nf*8 + ra)*SWW + kb + ca;
                bfrag[nf][0] = __float_as_uint(pb[0]);
                bfrag[nf][1] = __float_as_uint(pb[4]);
            }
            uint32_t afrag[4][4];
            #pragma unroll
            for (int mf = 0; mf < 4; mf++) {
                const float* pa = As + (wm + mf*16 + ra)*SWW + kb + ca;
                afrag[mf][0] = __float_as_uint(pa[0]);
                afrag[mf][1] = __float_as_uint(pa[8*SWW]);
                afrag[mf][2] = __float_as_uint(pa[4]);
                afrag[mf][3] = __float_as_uint(pa[8*SWW + 4]);
            }
            #pragma unroll
            for (int mf = 0; mf < 4; mf++)
                #pragma unroll
                for (int nf = 0; nf < 8; nf++)
                    mma_tf32(acc[mf][nf], afrag[mf], bfrag[nf]);
        }
        __syncthreads();
    }
    #undef STAGE

    int tr = lane >> 2, tc = (lane & 3) * 2;
    #pragma unroll
    for (int mf = 0; mf < 4; mf++) {
        #pragma unroll
        for (int nf = 0; nf < 8; nf++) {
            int col = n0 + wn + nf*8 + tc;
            if (col < nvalid) {
                #pragma unroll
                for (int hrow = 0; hrow < 2; hrow++) {
                    int m = m0 + wm + mf*16 + tr + hrow*8;
                    float v0 = acc[mf][nf][hrow*2+0];
                    float v1 = acc[mf][nf][hrow*2+1];
                    if (bias) { v0 += bias[col]; v1 += bias[col+1]; }
                    if (U) {
                        size_t ub = (size_t)m*HDIM + col;
                        v0 += U[ub]   * Dv[col];
                        v1 += U[ub+1] * Dv[col+1];
                    }
                    *(float2*)(C + (size_t)m*ldc + col) = make_float2(v0, v1);
                }
            }
        }
    }
}

// ---- fused GLU GEMM pair: x += (A@W1^T+b1) * sigmoid(A@W2^T+b2); optional rounded copy ----
__global__ __launch_bounds__(256) void mma_gemm_glu(
    const float* __restrict__ A,
    const float* __restrict__ B1, const float* __restrict__ B2,
    const float* __restrict__ b1, const float* __restrict__ b2,
    float* __restrict__ X, float* __restrict__ Xr, int emit_round)
{
    extern __shared__ __align__(16) float smem[];
    uint32_t sb = smem_u32(smem);
    int tid = threadIdx.x;
    int wid = tid >> 5, lane = tid & 31;
    int m0 = blockIdx.y * 128;
    int n0 = blockIdx.x * 128;
    int wm = (wid >> 2) * 64;
    int wn = (wid & 3) * 32;

    float acc1[4][4][4], acc2[4][4][4];
    #pragma unroll
    for (int i = 0; i < 4; i++)
        #pragma unroll
        for (int j = 0; j < 4; j++)
            #pragma unroll
            for (int q = 0; q < 4; q++) { acc1[i][j][q] = 0.f; acc2[i][j][q] = 0.f; }

    #define STAGE6(k0, buf) do { \
        uint32_t ab  = sb + (buf)*3*ABUFB; \
        uint32_t bb1 = ab + ABUFB; \
        uint32_t bb2 = ab + 2*ABUFB; \
        _Pragma("unroll") \
        for (int i = 0; i < 4; i++) { \
            int idx = tid + i*256; \
            int r = idx >> 3, cg = (idx & 7) * 4; \
            uint32_t so = (uint32_t)((r*SWW + cg) * 4); \
            cp16(ab  + so, A  + (size_t)(m0 + r)*HDIM + (k0) + cg); \
            cp16(bb1 + so, B1 + (size_t)(n0 + r)*HDIM + (k0) + cg); \
            cp16(bb2 + so, B2 + (size_t)(n0 + r)*HDIM + (k0) + cg); \
        } \
        CP_COMMIT(); } while (0)

    int ra = lane >> 2, ca = lane & 3;

    STAGE6(0, 0);
    for (int kc = 0; kc < 8; kc++) {
        if (kc < 7) STAGE6((kc+1)*32, (kc+1) & 1);
        if (kc < 7) CP_WAIT1(); else CP_WAIT0();
        __syncthreads();
        const float* As = smem + (kc & 1)*3*ABUFW;
        #pragma unroll
        for (int ks = 0; ks < 4; ks++) {
            int kb = ks*8;
            uint32_t afrag[4][4];
            #pragma unroll
            for (int mf = 0; mf < 4; mf++) {
                const float* pa = As + (wm + mf*16 + ra)*SWW + kb + ca;
                afrag[mf][0] = __float_as_uint(pa[0]);
                afrag[mf][1] = __float_as_uint(pa[8*SWW]);
                afrag[mf][2] = __float_as_uint(pa[4]);
                afrag[mf][3] = __float_as_uint(pa[8*SWW + 4]);
            }
            #pragma unroll
            for (int mat = 0; mat < 2; mat++) {
                const float* Bs = As + (1 + mat)*ABUFW;
                uint32_t bfrag[4][2];
                #pragma unroll
                for (int nf = 0; nf < 4; nf++) {
                    const float* pb = Bs + (wn + nf*8 + ra)*SWW + kb + ca;
                    bfrag[nf][0] = __float_as_uint(pb[0]);
                    bfrag[nf][1] = __float_as_uint(pb[4]);
                }
                #pragma unroll
                for (int mf = 0; mf < 4; mf++)
                    #pragma unroll
                    for (int nf = 0; nf < 4; nf++)
                        mma_tf32(mat ? acc2[mf][nf] : acc1[mf][nf], afrag[mf], bfrag[nf]);
            }
        }
        __syncthreads();
    }
    #undef STAGE6

    int tr = lane >> 2, tc = (lane & 3) * 2;
    #pragma unroll
    for (int mf = 0; mf < 4; mf++) {
        #pragma unroll
        for (int nf = 0; nf < 4; nf++) {
            int col = n0 + wn + nf*8 + tc;
            #pragma unroll
            for (int hrow = 0; hrow < 2; hrow++) {
                int m = m0 + wm + mf*16 + tr + hrow*8;
                size_t xi = (size_t)m*HDIM + col;
                float u0 = acc1[mf][nf][hrow*2+0] + b1[col];
                float u1 = acc1[mf][nf][hrow*2+1] + b1[col+1];
                float w0 = acc2[mf][nf][hrow*2+0] + b2[col];
                float w1 = acc2[mf][nf][hrow*2+1] + b2[col+1];
                float2 xv = *(float2*)(X + xi);
                xv.x += u0 / (1.f + expf(-w0));
                xv.y += u1 / (1.f + expf(-w1));
                *(float2*)(X + xi) = xv;
                if (emit_round)
                    *(float2*)(Xr + xi) = make_float2(tf32r(xv.x), tf32r(xv.y));
            }
        }
    }
}

// ---------------- host launch ----------------
extern "C" void kernel_launch(void* const* d_in, const int* in_sizes, int n_in,
                              void* d_out, int out_size)
{
    const float* latent     = (const float*)d_in[0];
    const float* W_expand   = (const float*)d_in[1];
    const float* b_expand   = (const float*)d_in[2];
    const float* norm_scale = (const float*)d_in[3];
    const float* norm_bias  = (const float*)d_in[4];
    const float* Lambda_re  = (const float*)d_in[5];
    const float* Lambda_im  = (const float*)d_in[6];
    const float* B_re       = (const float*)d_in[7];
    const float* B_im       = (const float*)d_in[8];
    const float* C_re       = (const float*)d_in[9];
    const float* C_im       = (const float*)d_in[10];
    const float* Dmat       = (const float*)d_in[11];
    const float* log_step   = (const float*)d_in[12];
    const float* W1         = (const float*)d_in[13];
    const float* b1         = (const float*)d_in[14];
    const float* W2         = (const float*)d_in[15];
    const float* b2         = (const float*)d_in[16];
    const float* W_out      = (const float*)d_in[17];
    const float* b_out      = (const float*)d_in[18];
    float* out = (float*)d_out;

    cudaFuncSetAttribute(mma_gemm,     cudaFuncAttributeMaxDynamicSharedMemorySize, SMEM_G4);
    cudaFuncSetAttribute(mma_gemm_glu, cudaFuncAttributeMaxDynamicSharedMemorySize, SMEM_G6);

    float *p_x, *p_bu, *p_t1, *p_h, *p_xs;
    float *p_Wbt, *p_Wct, *p_W1t, *p_W2t, *p_Wot;
    cudaGetSymbolAddress((void**)&p_x,   g_x);
    cudaGetSymbolAddress((void**)&p_bu,  g_bu);
    cudaGetSymbolAddress((void**)&p_t1,  g_t1);
    cudaGetSymbolAddress((void**)&p_h,   g_h);
    cudaGetSymbolAddress((void**)&p_xs,  g_xs);
    cudaGetSymbolAddress((void**)&p_Wbt, g_Wbt);
    cudaGetSymbolAddress((void**)&p_Wct, g_Wct);
    cudaGetSymbolAddress((void**)&p_W1t, g_W1t);
    cudaGetSymbolAddress((void**)&p_W2t, g_W2t);
    cudaGetSymbolAddress((void**)&p_Wot, g_Wot);

    // setup
    expand_kernel<<<1, HDIM>>>(latent, W_expand, b_expand);
    broadcast_kernel<<<1024, 256>>>();
    setup_params<<<NLAYERS, PDIM>>>(Lambda_re, Lambda_im, B_re, B_im, C_re, C_im, log_step);
    convert_all<<<2176, 256>>>(W1, W2, W_out);

    dim3 gblk_g(128);    // plain GEMM: 4 warps
    dim3 gblk_u(256);    // GLU GEMM: 8 warps
    dim3 ggrid(2, L_SEQ/128);   // (N tiles, M tiles)

    for (int i = 0; i < NLAYERS; i++) {
        const float* sc = norm_scale + i*HDIM;
        const float* bi = norm_bias  + i*HDIM;
        size_t wo = (size_t)i*HDIM*HDIM;
        // 1. pre-norm: h = LN(x)  (tf32-rounded)
        ln_act_kernel<<<L_SEQ/8, 256>>>(p_x, p_h, sc, bi, 0);
        // 2. Bu = h @ Wb
        mma_gemm<<<ggrid, gblk_g, SMEM_G4>>>(p_h, p_Wbt + wo, p_bu, HDIM, HDIM,
                                             nullptr, nullptr, nullptr);
        // 3. scan (scanB folded into scanC prefix)
        scanA_kernel<<<NCHUNK, PDIM>>>(p_bu, i);
        scanC_kernel<<<NCHUNK, PDIM>>>(p_bu, p_xs, i);
        // 4. t1 = xs @ Wc + h*D
        mma_gemm<<<ggrid, gblk_g, SMEM_G4>>>(p_xs, p_Wct + wo, p_t1, HDIM, HDIM,
                                             nullptr, p_h, Dmat + i*HDIM);
        // 5. h = gelu(LN(t1))  (tf32-rounded)
        ln_act_kernel<<<L_SEQ/8, 256>>>(p_t1, p_h, sc, bi, 1);
        // 6. fused GLU pair + gate + residual (+ rounded x copy on last layer)
        mma_gemm_glu<<<ggrid, gblk_u, SMEM_G6>>>(p_h, p_W1t + wo, p_W2t + wo,
                                                 b1 + i*HDIM, b2 + i*HDIM,
                                                 p_x, p_t1, i == NLAYERS-1 ? 1 : 0);
    }
    // output head: out = x @ W_out + b_out  (N=64, padded B to 128 rows)
    dim3 hgrid(1, L_SEQ/128);
    mma_gemm<<<hgrid, gblk_g, SMEM_G4>>>(p_t1, p_Wot, out, 64, 64,
                                         b_out, nullptr, nullptr);
}

// round 13
// speedup vs baseline: 3.2659x; 1.2573x over previous
#include <cuda_runtime.h>
#include <cuda_fp16.h>
#include <math.h>
#include <stdint.h>

#define L_SEQ   32768
#define HDIM    256
#define PDIM    128
#define NLAYERS 4
#define NCHUNK  256
#define TCHUNK  128

// ---------------- scratch (static __device__, no allocation) ----------------
__device__ float  g_x  [L_SEQ*HDIM];
__device__ float  g_bu [L_SEQ*HDIM];
__device__ float  g_t1 [L_SEQ*HDIM];
__device__ __half g_h  [L_SEQ*HDIM];   // LN output (fp16)
__device__ __half g_xs [L_SEQ*HDIM];   // scan output (fp16, descaled)
__device__ __half g_xh [L_SEQ*HDIM];   // rounded x for head
// transposed fp16 weights: [N][K] layout, K contiguous
__device__ __half g_Wbt[NLAYERS][HDIM*HDIM];   // row-scaled by s_p
__device__ __half g_Wct[NLAYERS][HDIM*HDIM];
__device__ __half g_W1t[NLAYERS][HDIM*HDIM];
__device__ __half g_W2t[NLAYERS][HDIM*HDIM];
__device__ __half g_Wot[128*HDIM];     // W_out^T zero-padded to 128 rows
__device__ float2 g_lam [NLAYERS][PDIM];
__device__ float2 g_lamT[NLAYERS][PDIM];
__device__ float  g_sinv[NLAYERS][PDIM];   // 1/s_p (power of two)
__device__ float2 g_E [NCHUNK*PDIM];
__device__ float  g_x0[HDIM];

// ---------------- PTX helpers ----------------
__device__ __forceinline__ uint32_t smem_u32(const void* p) {
    uint32_t a;
    asm("{ .reg .u64 t; cvta.to.shared.u64 t, %1; cvt.u32.u64 %0, t; }" : "=r"(a) : "l"(p));
    return a;
}
__device__ __forceinline__ void ldm4(uint32_t* r, uint32_t addr) {
    asm volatile("ldmatrix.sync.aligned.m8n8.x4.shared.b16 {%0,%1,%2,%3}, [%4];"
                 : "=r"(r[0]), "=r"(r[1]), "=r"(r[2]), "=r"(r[3]) : "r"(addr));
}
__device__ __forceinline__ void mma_f16(float* c, const uint32_t* a, const uint32_t* b) {
    asm volatile("mma.sync.aligned.m16n8k16.row.col.f32.f16.f16.f32 "
                 "{%0,%1,%2,%3}, {%4,%5,%6,%7}, {%8,%9}, {%0,%1,%2,%3};"
                 : "+f"(c[0]), "+f"(c[1]), "+f"(c[2]), "+f"(c[3])
                 : "r"(a[0]), "r"(a[1]), "r"(a[2]), "r"(a[3]), "r"(b[0]), "r"(b[1]));
}
__device__ __forceinline__ void cp16(uint32_t saddr, const void* gaddr) {
    asm volatile("cp.async.cg.shared.global [%0], [%1], 16;" :: "r"(saddr), "l"(gaddr));
}
#define CP_COMMIT() asm volatile("cp.async.commit_group;" ::: "memory")
#define CP_WAIT1()  asm volatile("cp.async.wait_group 1;" ::: "memory")
#define CP_WAIT0()  asm volatile("cp.async.wait_group 0;" ::: "memory")

// ---------------- setup kernels ----------------
__global__ void expand_kernel(const float* __restrict__ latent,
                              const float* __restrict__ W,
                              const float* __restrict__ b)
{
    int h = threadIdx.x;
    float s = 0.f;
    for (int l = 0; l < HDIM; l++) s += latent[l] * W[l*HDIM + h];
    s += b[h];
    g_x0[h] = s > 0.f ? s : 0.01f * s;
}

__global__ void broadcast_kernel()
{
    size_t n = (size_t)L_SEQ * HDIM / 4;
    const float4* src = (const float4*)g_x0;
    float4* dst = (float4*)g_x;
    for (size_t i = (size_t)blockIdx.x*blockDim.x + threadIdx.x; i < n;
         i += (size_t)gridDim.x*blockDim.x)
        dst[i] = src[i & (HDIM/4 - 1)];
}

__global__ void setup_params(const float* __restrict__ Lre, const float* __restrict__ Lim,
                             const float* __restrict__ Bre, const float* __restrict__ Bim,
                             const float* __restrict__ Cre, const float* __restrict__ Cim,
                             const float* __restrict__ log_step)
{
    int layer = blockIdx.x;
    int p = threadIdx.x;                 // 128 threads
    float step = expf(log_step[layer*PDIM + p]);
    float lr = Lre[layer*PDIM + p], li = Lim[layer*PDIM + p];
    float er  = expf(lr*step);
    float lbr = er * cosf(li*step);
    float lbi = er * sinf(li*step);
    g_lam[layer][p] = make_float2(lbr, lbi);
    float tr = lbr, ti = lbi;
    #pragma unroll
    for (int i = 0; i < 7; i++) { float nr2 = tr*tr - ti*ti; ti = 2.f*tr*ti; tr = nr2; }
    g_lamT[layer][p] = make_float2(tr, ti);
    float nr = lbr - 1.f, ni = lbi;
    float den = lr*lr + li*li;
    float fr = (nr*lr + ni*li) / den;
    float fi = (ni*lr - nr*li) / den;
    // per-channel power-of-two scale keeping Wbt rows in fp16 normal range
    float fmag = sqrtf(fr*fr + fi*fi);
    float s = exp2f(rintf(-log2f(fmag)));   // exact power of two ~ 1/|f|
    g_sinv[layer][p] = 1.f / s;
    float frs = fr * s, fis = fi * s;
    const float* brp = Bre + ((size_t)layer*PDIM + p)*HDIM;
    const float* bip = Bim + ((size_t)layer*PDIM + p)*HDIM;
    for (int h = 0; h < HDIM; h++) {
        float br = brp[h], bi = bip[h];
        // Wbt[n][k]: n = p (re) or 128+p (im), k = h  (scaled by s)
        g_Wbt[layer][p*HDIM + h]        = __float2half_rn(frs*br - fis*bi);
        g_Wbt[layer][(PDIM+p)*HDIM + h] = __float2half_rn(frs*bi + fis*br);
        // Wct[n][k]: n = h, k = p (re) / 128+p (im)
        g_Wct[layer][h*HDIM + p]        = __float2half_rn( 2.f * Cre[((size_t)layer*HDIM + h)*PDIM + p]);
        g_Wct[layer][h*HDIM + PDIM + p] = __float2half_rn(-2.f * Cim[((size_t)layer*HDIM + h)*PDIM + p]);
    }
}

// one kernel converting W1, W2 (all layers) and W_out (transpose + fp16)
__global__ void convert_all(const float* __restrict__ W1, const float* __restrict__ W2,
                            const float* __restrict__ Wout)
{
    const int total1 = NLAYERS*HDIM*HDIM;
    const int total  = 2*total1 + 128*HDIM;
    for (int idx = blockIdx.x*blockDim.x + threadIdx.x; idx < total;
         idx += gridDim.x*blockDim.x) {
        if (idx < total1) {
            int l = idx / (HDIM*HDIM), r = idx - l*(HDIM*HDIM);
            int n = r / HDIM, k = r - n*HDIM;
            g_W1t[l][r] = __float2half_rn(W1[(size_t)l*HDIM*HDIM + k*HDIM + n]);
        } else if (idx < 2*total1) {
            int j = idx - total1;
            int l = j / (HDIM*HDIM), r = j - l*(HDIM*HDIM);
            int n = r / HDIM, k = r - n*HDIM;
            g_W2t[l][r] = __float2half_rn(W2[(size_t)l*HDIM*HDIM + k*HDIM + n]);
        } else {
            int j = idx - 2*total1;
            int n = j >> 8, k = j & 255;
            g_Wot[j] = (n < 64) ? __float2half_rn(Wout[k*64 + n]) : __float2half_rn(0.f);
        }
    }
}

// ---------------- LayerNorm (warp per row) -> fp16, optional gelu ----------------
__global__ void ln_act_kernel(const float* __restrict__ X, __half* __restrict__ Y,
                              const float* __restrict__ scale, const float* __restrict__ bias,
                              int gelu_flag)
{
    int row  = blockIdx.x * (blockDim.x >> 5) + (threadIdx.x >> 5);
    int lane = threadIdx.x & 31;
    const float* x = X + (size_t)row * HDIM;
    float v[8], s = 0.f, s2 = 0.f;
    #pragma unroll
    for (int i = 0; i < 8; i++) {
        float t = x[lane + 32*i];
        v[i] = t; s += t; s2 += t*t;
    }
    #pragma unroll
    for (int o = 16; o; o >>= 1) {
        s  += __shfl_xor_sync(0xffffffffu, s,  o);
        s2 += __shfl_xor_sync(0xffffffffu, s2, o);
    }
    float mu  = s  * (1.f/HDIM);
    float var = s2 * (1.f/HDIM) - mu*mu;
    float rs  = rsqrtf(var + 1e-6f);
    #pragma unroll
    for (int i = 0; i < 8; i++) {
        int c = lane + 32*i;
        float n = (v[i] - mu) * rs * scale[c] + bias[c];
        if (gelu_flag) {
            float t = 0.7978845608028654f * (n + 0.044715f * n*n*n);
            n = 0.5f * n * (1.f + tanhf(t));
        }
        Y[(size_t)row*HDIM + c] = __float2half_rn(n);
    }
}

// ---------------- chunked diagonal complex scan (on scaled Bu) ----------------
__global__ void scanA_kernel(const float* __restrict__ Bu, int layer)
{
    int c = blockIdx.x, p = threadIdx.x;
    float2 lam = g_lam[layer][p];
    float xr = 0.f, xi = 0.f;
    const float* b = Bu + (size_t)c * TCHUNK * HDIM;
    for (int t = 0; t < TCHUNK; t++) {
        float br = b[t*HDIM + p], bi = b[t*HDIM + PDIM + p];
        float nr = lam.x*xr - lam.y*xi + br;
        float ni = lam.x*xi + lam.y*xr + bi;
        xr = nr; xi = ni;
    }
    g_E[c*PDIM + p] = make_float2(xr, xi);
}

// scanC with inline chunk-prefix; output descaled by 1/s_p then fp16-rounded
__global__ void scanC_kernel(const float* __restrict__ Bu, __half* __restrict__ XS, int layer)
{
    int c = blockIdx.x, p = threadIdx.x;
    float2 lamT = g_lamT[layer][p];
    float2 lam  = g_lam[layer][p];
    float inv   = g_sinv[layer][p];
    float xr = 0.f, xi = 0.f;
    for (int j = 0; j < c; j++) {
        float2 e = g_E[j*PDIM + p];
        float nr = lamT.x*xr - lamT.y*xi + e.x;
        float ni = lamT.x*xi + lamT.y*xr + e.y;
        xr = nr; xi = ni;
    }
    const float* b = Bu + (size_t)c * TCHUNK * HDIM;
    __half* o = XS + (size_t)c * TCHUNK * HDIM;
    for (int t = 0; t < TCHUNK; t++) {
        float br = b[t*HDIM + p], bi = b[t*HDIM + PDIM + p];
        float nr = lam.x*xr - lam.y*xi + br;
        float ni = lam.x*xi + lam.y*xr + bi;
        xr = nr; xi = ni;
        o[t*HDIM + p]        = __float2half_rn(xr * inv);
        o[t*HDIM + PDIM + p] = __float2half_rn(xi * inv);
    }
}

// ---------------- fp16 mma GEMM (cp.async double-buffered) ----------------
#define SPAD 40                       // smem row stride in halves (80B, 16B-aligned)
#define BUFSZ (128*SPAD*2)            // 10240 B per operand buffer
#define SMEM_G4 (4*BUFSZ)             // plain: [A,B] x 2 bufs = 40960
#define SMEM_G6 (6*BUFSZ)             // GLU:  [A,B1,B2] x 2 bufs = 61440

struct LaneAddr { int a_off, b_off; };
__device__ __forceinline__ LaneAddr lane_addr(int lane, int wm, int wn) {
    LaneAddr la;
    int a_r = lane & 15, a_c = (lane >> 4) * 8;
    int b_q = lane >> 3, b_r = lane & 7;
    int b_n_add = (b_q >> 1) * 8 + b_r;
    int b_k_add = (b_q & 1) * 8;
    la.a_off = (wm + a_r)*SPAD + a_c;
    la.b_off = (wn + b_n_add)*SPAD + b_k_add;
    return la;
}

// C[m0:+128, n0:+128] = A[m0:,K=256] * B^T[n0:,K=256]  (B stored [N][K])
// 128 threads, 4 warps, warp tile 64x64
__global__ __launch_bounds__(128) void mma_gemm(
    const __half* __restrict__ A, const __half* __restrict__ B,
    float* __restrict__ C, int ldc, int nvalid,
    const float* __restrict__ bias,
    const __half* __restrict__ U, const float* __restrict__ Dv)
{
    extern __shared__ __align__(16) char smem[];
    uint32_t sb = smem_u32(smem);
    int tid = threadIdx.x;
    int wid = tid >> 5, lane = tid & 31;
    int m0 = blockIdx.y * 128;
    int n0 = blockIdx.x * 128;
    int wm = (wid >> 1) * 64;
    int wn = (wid & 1) * 64;

    float acc[4][8][4];
    #pragma unroll
    for (int i = 0; i < 4; i++)
        #pragma unroll
        for (int j = 0; j < 8; j++)
            #pragma unroll
            for (int q = 0; q < 4; q++) acc[i][j][q] = 0.f;

    #define STAGE(k0, buf) do { \
        uint32_t ab = sb + (buf)*2*BUFSZ; \
        uint32_t bb = ab + BUFSZ; \
        _Pragma("unroll") \
        for (int i = 0; i < 4; i++) { \
            int idx = tid + i*128; \
            int r = idx >> 2, cg = (idx & 3) * 8; \
            uint32_t so = (uint32_t)((r*SPAD + cg) * 2); \
            cp16(ab + so, A + (size_t)(m0 + r)*HDIM + (k0) + cg); \
            cp16(bb + so, B + (size_t)(n0 + r)*HDIM + (k0) + cg); \
        } \
        CP_COMMIT(); } while (0)

    LaneAddr la = lane_addr(lane, wm, wn);

    STAGE(0, 0);
    for (int kc = 0; kc < 8; kc++) {
        if (kc < 7) STAGE((kc+1)*32, (kc+1) & 1);
        if (kc < 7) CP_WAIT1(); else CP_WAIT0();
        __syncthreads();
        uint32_t bbuf = sb + (kc & 1)*2*BUFSZ;
        uint32_t aA = bbuf, aB = bbuf + BUFSZ;
        #pragma unroll
        for (int ks = 0; ks < 2; ks++) {
            uint32_t bh[4][4];
            #pragma unroll
            for (int nf2 = 0; nf2 < 4; nf2++) {
                uint32_t boff = (uint32_t)((la.b_off + nf2*16*SPAD + ks*16) * 2);
                ldm4(bh[nf2], aB + boff);
            }
            uint32_t ah[4][4];
            #pragma unroll
            for (int mf = 0; mf < 4; mf++) {
                uint32_t aoff = (uint32_t)((la.a_off + mf*16*SPAD + ks*16) * 2);
                ldm4(ah[mf], aA + aoff);
            }
            #pragma unroll
            for (int mf = 0; mf < 4; mf++)
                #pragma unroll
                for (int nf = 0; nf < 8; nf++)
                    mma_f16(acc[mf][nf], ah[mf], &bh[nf >> 1][(nf & 1)*2]);
        }
        __syncthreads();
    }
    #undef STAGE

    int tr = lane >> 2, tc = (lane & 3) * 2;
    #pragma unroll
    for (int mf = 0; mf < 4; mf++) {
        #pragma unroll
        for (int nf = 0; nf < 8; nf++) {
            int col = n0 + wn + nf*8 + tc;
            if (col < nvalid) {
                #pragma unroll
                for (int hrow = 0; hrow < 2; hrow++) {
                    int m = m0 + wm + mf*16 + tr + hrow*8;
                    float v0 = acc[mf][nf][hrow*2+0];
                    float v1 = acc[mf][nf][hrow*2+1];
                    if (bias) { v0 += bias[col]; v1 += bias[col+1]; }
                    if (U) {
                        size_t ub = (size_t)m*HDIM + col;
                        v0 += __half2float(U[ub])   * Dv[col];
                        v1 += __half2float(U[ub+1]) * Dv[col+1];
                    }
                    *(float2*)(C + (size_t)m*ldc + col) = make_float2(v0, v1);
                }
            }
        }
    }
}

// ---- fused GLU GEMM pair: x += (A@W1^T+b1) * sigmoid(A@W2^T+b2); optional fp16 copy ----
__global__ __launch_bounds__(256) void mma_gemm_glu(
    const __half* __restrict__ A,
    const __half* __restrict__ B1, const __half* __restrict__ B2,
    const float* __restrict__ b1, const float* __restrict__ b2,
    float* __restrict__ X, __half* __restrict__ Xr, int emit_round)
{
    extern __shared__ __align__(16) char smem[];
    uint32_t sb = smem_u32(smem);
    int tid = threadIdx.x;
    int wid = tid >> 5, lane = tid & 31;
    int m0 = blockIdx.y * 128;
    int n0 = blockIdx.x * 128;
    int wm = (wid >> 2) * 64;
    int wn = (wid & 3) * 32;

    float acc1[4][4][4], acc2[4][4][4];
    #pragma unroll
    for (int i = 0; i < 4; i++)
        #pragma unroll
        for (int j = 0; j < 4; j++)
            #pragma unroll
            for (int q = 0; q < 4; q++) { acc1[i][j][q] = 0.f; acc2[i][j][q] = 0.f; }

    #define STAGE6(k0, buf) do { \
        uint32_t ab  = sb + (buf)*3*BUFSZ; \
        uint32_t bb1 = ab + BUFSZ; \
        uint32_t bb2 = ab + 2*BUFSZ; \
        _Pragma("unroll") \
        for (int i = 0; i < 2; i++) { \
            int idx = tid + i*256; \
            int r = idx >> 2, cg = (idx & 3) * 8; \
            uint32_t so = (uint32_t)((r*SPAD + cg) * 2); \
            cp16(ab  + so, A  + (size_t)(m0 + r)*HDIM + (k0) + cg); \
            cp16(bb1 + so, B1 + (size_t)(n0 + r)*HDIM + (k0) + cg); \
            cp16(bb2 + so, B2 + (size_t)(n0 + r)*HDIM + (k0) + cg); \
        } \
        CP_COMMIT(); } while (0)

    LaneAddr la = lane_addr(lane, wm, wn);

    STAGE6(0, 0);
    for (int kc = 0; kc < 8; kc++) {
        if (kc < 7) STAGE6((kc+1)*32, (kc+1) & 1);
        if (kc < 7) CP_WAIT1(); else CP_WAIT0();
        __syncthreads();
        uint32_t ab = sb + (kc & 1)*3*BUFSZ;
        #pragma unroll
        for (int ks = 0; ks < 2; ks++) {
            uint32_t ah[4][4];
            #pragma unroll
            for (int mf = 0; mf < 4; mf++) {
                uint32_t aoff = (uint32_t)((la.a_off + mf*16*SPAD + ks*16) * 2);
                ldm4(ah[mf], ab + aoff);
            }
            #pragma unroll
            for (int mat = 0; mat < 2; mat++) {
                uint32_t aB = ab + (1 + mat)*BUFSZ;
                uint32_t bh[2][4];
                #pragma unroll
                for (int nf2 = 0; nf2 < 2; nf2++) {
                    uint32_t boff = (uint32_t)((la.b_off + nf2*16*SPAD + ks*16) * 2);
                    ldm4(bh[nf2], aB + boff);
                }
                #pragma unroll
                for (int mf = 0; mf < 4; mf++)
                    #pragma unroll
                    for (int nf = 0; nf < 4; nf++)
                        mma_f16(mat ? acc2[mf][nf] : acc1[mf][nf],
                                ah[mf], &bh[nf >> 1][(nf & 1)*2]);
            }
        }
        __syncthreads();
    }
    #undef STAGE6

    int tr = lane >> 2, tc = (lane & 3) * 2;
    #pragma unroll
    for (int mf = 0; mf < 4; mf++) {
        #pragma unroll
        for (int nf = 0; nf < 4; nf++) {
            int col = n0 + wn + nf*8 + tc;
            #pragma unroll
            for (int hrow = 0; hrow < 2; hrow++) {
                int m = m0 + wm + mf*16 + tr + hrow*8;
                size_t xi = (size_t)m*HDIM + col;
                float u0 = acc1[mf][nf][hrow*2+0] + b1[col];
                float u1 = acc1[mf][nf][hrow*2+1] + b1[col+1];
                float w0 = acc2[mf][nf][hrow*2+0] + b2[col];
                float w1 = acc2[mf][nf][hrow*2+1] + b2[col+1];
                float2 xv = *(float2*)(X + xi);
                xv.x += u0 / (1.f + expf(-w0));
                xv.y += u1 / (1.f + expf(-w1));
                *(float2*)(X + xi) = xv;
                if (emit_round) {
                    Xr[xi]   = __float2half_rn(xv.x);
                    Xr[xi+1] = __float2half_rn(xv.y);
                }
            }
        }
    }
}

// ---------------- host launch ----------------
extern "C" void kernel_launch(void* const* d_in, const int* in_sizes, int n_in,
                              void* d_out, int out_size)
{
    const float* latent     = (const float*)d_in[0];
    const float* W_expand   = (const float*)d_in[1];
    const float* b_expand   = (const float*)d_in[2];
    const float* norm_scale = (const float*)d_in[3];
    const float* norm_bias  = (const float*)d_in[4];
    const float* Lambda_re  = (const float*)d_in[5];
    const float* Lambda_im  = (const float*)d_in[6];
    const float* B_re       = (const float*)d_in[7];
    const float* B_im       = (const float*)d_in[8];
    const float* C_re       = (const float*)d_in[9];
    const float* C_im       = (const float*)d_in[10];
    const float* Dmat       = (const float*)d_in[11];
    const float* log_step   = (const float*)d_in[12];
    const float* W1         = (const float*)d_in[13];
    const float* b1         = (const float*)d_in[14];
    const float* W2         = (const float*)d_in[15];
    const float* b2         = (const float*)d_in[16];
    const float* W_out      = (const float*)d_in[17];
    const float* b_out      = (const float*)d_in[18];
    float* out = (float*)d_out;

    cudaFuncSetAttribute(mma_gemm,     cudaFuncAttributeMaxDynamicSharedMemorySize, SMEM_G4);
    cudaFuncSetAttribute(mma_gemm_glu, cudaFuncAttributeMaxDynamicSharedMemorySize, SMEM_G6);

    float *p_x, *p_bu, *p_t1;
    __half *p_h, *p_xs, *p_xh;
    __half *p_Wbt, *p_Wct, *p_W1t, *p_W2t, *p_Wot;
    cudaGetSymbolAddress((void**)&p_x,   g_x);
    cudaGetSymbolAddress((void**)&p_bu,  g_bu);
    cudaGetSymbolAddress((void**)&p_t1,  g_t1);
    cudaGetSymbolAddress((void**)&p_h,   g_h);
    cudaGetSymbolAddress((void**)&p_xs,  g_xs);
    cudaGetSymbolAddress((void**)&p_xh,  g_xh);
    cudaGetSymbolAddress((void**)&p_Wbt, g_Wbt);
    cudaGetSymbolAddress((void**)&p_Wct, g_Wct);
    cudaGetSymbolAddress((void**)&p_W1t, g_W1t);
    cudaGetSymbolAddress((void**)&p_W2t, g_W2t);
    cudaGetSymbolAddress((void**)&p_Wot, g_Wot);

    // setup
    expand_kernel<<<1, HDIM>>>(latent, W_expand, b_expand);
    broadcast_kernel<<<1024, 256>>>();
    setup_params<<<NLAYERS, PDIM>>>(Lambda_re, Lambda_im, B_re, B_im, C_re, C_im, log_step);
    convert_all<<<2176, 256>>>(W1, W2, W_out);

    dim3 gblk_g(128);    // plain GEMM: 4 warps
    dim3 gblk_u(256);    // GLU GEMM: 8 warps
    dim3 ggrid(2, L_SEQ/128);   // (N tiles, M tiles)

    for (int i = 0; i < NLAYERS; i++) {
        const float* sc = norm_scale + i*HDIM;
        const float* bi = norm_bias  + i*HDIM;
        size_t wo = (size_t)i*HDIM*HDIM;
        // 1. pre-norm: h = LN(x) -> fp16
        ln_act_kernel<<<L_SEQ/8, 256>>>(p_x, p_h, sc, bi, 0);
        // 2. Bu' = h @ Wb'  (row-scaled)
        mma_gemm<<<ggrid, gblk_g, SMEM_G4>>>(p_h, p_Wbt + wo, p_bu, HDIM, HDIM,
                                             nullptr, nullptr, nullptr);
        // 3. scan on scaled Bu; output descaled fp16
        scanA_kernel<<<NCHUNK, PDIM>>>(p_bu, i);
        scanC_kernel<<<NCHUNK, PDIM>>>(p_bu, p_xs, i);
        // 4. t1 = xs @ Wc + h*D
        mma_gemm<<<ggrid, gblk_g, SMEM_G4>>>(p_xs, p_Wct + wo, p_t1, HDIM, HDIM,
                                             nullptr, p_h, Dmat + i*HDIM);
        // 5. h = gelu(LN(t1)) -> fp16
        ln_act_kernel<<<L_SEQ/8, 256>>>(p_t1, p_h, sc, bi, 1);
        // 6. fused GLU pair + gate + residual (+ fp16 x copy on last layer)
        mma_gemm_glu<<<ggrid, gblk_u, SMEM_G6>>>(p_h, p_W1t + wo, p_W2t + wo,
                                                 b1 + i*HDIM, b2 + i*HDIM,
                                                 p_x, p_xh, i == NLAYERS-1 ? 1 : 0);
    }
    // output head: out = x @ W_out + b_out  (N=64, padded B to 128 rows)
    dim3 hgrid(1, L_SEQ/128);
    mma_gemm<<<hgrid, gblk_g, SMEM_G4>>>(p_xh, p_Wot, out, 64, 64,
                                         b_out, nullptr, nullptr);
}

// round 14
// speedup vs baseline: 3.3332x; 1.0206x over previous
#include <cuda_runtime.h>
#include <cuda_fp16.h>
#include <math.h>
#include <stdint.h>

#define L_SEQ   32768
#define HDIM    256
#define PDIM    128
#define NLAYERS 4
#define NCHUNK  256
#define TCHUNK  128

// ---------------- scratch (static __device__, no allocation) ----------------
__device__ float  g_x  [L_SEQ*HDIM];
__device__ float  g_bu [L_SEQ*HDIM];
__device__ float  g_t1 [L_SEQ*HDIM];
__device__ __half g_h  [L_SEQ*HDIM];   // LN output (fp16)
__device__ __half g_xs [L_SEQ*HDIM];   // scan output (fp16, descaled)
__device__ __half g_xh [L_SEQ*HDIM];   // rounded x for head
// transposed fp16 weights: [N][K] layout, K contiguous
__device__ __half g_Wbt[NLAYERS][HDIM*HDIM];   // row-scaled by s_p
__device__ __half g_Wct[NLAYERS][HDIM*HDIM];
__device__ __half g_W1t[NLAYERS][HDIM*HDIM];
__device__ __half g_W2t[NLAYERS][HDIM*HDIM];
__device__ __half g_Wot[128*HDIM];     // W_out^T zero-padded to 128 rows
__device__ float2 g_lam [NLAYERS][PDIM];
__device__ float2 g_lamT[NLAYERS][PDIM];
__device__ float  g_sinv[NLAYERS][PDIM];   // 1/s_p (power of two)
__device__ float2 g_E [NCHUNK*PDIM];
__device__ float  g_x0[HDIM];

// ---------------- PTX helpers ----------------
__device__ __forceinline__ uint32_t smem_u32(const void* p) {
    uint32_t a;
    asm("{ .reg .u64 t; cvta.to.shared.u64 t, %1; cvt.u32.u64 %0, t; }" : "=r"(a) : "l"(p));
    return a;
}
__device__ __forceinline__ void ldm4(uint32_t* r, uint32_t addr) {
    asm volatile("ldmatrix.sync.aligned.m8n8.x4.shared.b16 {%0,%1,%2,%3}, [%4];"
                 : "=r"(r[0]), "=r"(r[1]), "=r"(r[2]), "=r"(r[3]) : "r"(addr));
}
__device__ __forceinline__ void mma_f16(float* c, const uint32_t* a, const uint32_t* b) {
    asm volatile("mma.sync.aligned.m16n8k16.row.col.f32.f16.f16.f32 "
                 "{%0,%1,%2,%3}, {%4,%5,%6,%7}, {%8,%9}, {%0,%1,%2,%3};"
                 : "+f"(c[0]), "+f"(c[1]), "+f"(c[2]), "+f"(c[3])
                 : "r"(a[0]), "r"(a[1]), "r"(a[2]), "r"(a[3]), "r"(b[0]), "r"(b[1]));
}
__device__ __forceinline__ void cp16(uint32_t saddr, const void* gaddr) {
    asm volatile("cp.async.cg.shared.global [%0], [%1], 16;" :: "r"(saddr), "l"(gaddr));
}
#define CP_COMMIT() asm volatile("cp.async.commit_group;" ::: "memory")
#define CP_WAIT1()  asm volatile("cp.async.wait_group 1;" ::: "memory")
#define CP_WAIT0()  asm volatile("cp.async.wait_group 0;" ::: "memory")

// ---------------- setup kernels ----------------
__global__ void expand_kernel(const float* __restrict__ latent,
                              const float* __restrict__ W,
                              const float* __restrict__ b)
{
    int h = threadIdx.x;
    float s = 0.f;
    for (int l = 0; l < HDIM; l++) s += latent[l] * W[l*HDIM + h];
    s += b[h];
    g_x0[h] = s > 0.f ? s : 0.01f * s;
}

__global__ void broadcast_kernel()
{
    size_t n = (size_t)L_SEQ * HDIM / 4;
    const float4* src = (const float4*)g_x0;
    float4* dst = (float4*)g_x;
    for (size_t i = (size_t)blockIdx.x*blockDim.x + threadIdx.x; i < n;
         i += (size_t)gridDim.x*blockDim.x)
        dst[i] = src[i & (HDIM/4 - 1)];
}

__global__ void setup_params(const float* __restrict__ Lre, const float* __restrict__ Lim,
                             const float* __restrict__ Bre, const float* __restrict__ Bim,
                             const float* __restrict__ Cre, const float* __restrict__ Cim,
                             const float* __restrict__ log_step)
{
    int layer = blockIdx.x;
    int p = threadIdx.x;                 // 128 threads
    float step = expf(log_step[layer*PDIM + p]);
    float lr = Lre[layer*PDIM + p], li = Lim[layer*PDIM + p];
    float er  = expf(lr*step);
    float lbr = er * cosf(li*step);
    float lbi = er * sinf(li*step);
    g_lam[layer][p] = make_float2(lbr, lbi);
    float tr = lbr, ti = lbi;
    #pragma unroll
    for (int i = 0; i < 7; i++) { float nr2 = tr*tr - ti*ti; ti = 2.f*tr*ti; tr = nr2; }
    g_lamT[layer][p] = make_float2(tr, ti);
    float nr = lbr - 1.f, ni = lbi;
    float den = lr*lr + li*li;
    float fr = (nr*lr + ni*li) / den;
    float fi = (ni*lr - nr*li) / den;
    // per-channel power-of-two scale keeping Wbt rows in fp16 normal range
    float fmag = sqrtf(fr*fr + fi*fi);
    float s = exp2f(rintf(-log2f(fmag)));   // exact power of two ~ 1/|f|
    g_sinv[layer][p] = 1.f / s;
    float frs = fr * s, fis = fi * s;
    const float* brp = Bre + ((size_t)layer*PDIM + p)*HDIM;
    const float* bip = Bim + ((size_t)layer*PDIM + p)*HDIM;
    for (int h = 0; h < HDIM; h++) {
        float br = brp[h], bi = bip[h];
        g_Wbt[layer][p*HDIM + h]        = __float2half_rn(frs*br - fis*bi);
        g_Wbt[layer][(PDIM+p)*HDIM + h] = __float2half_rn(frs*bi + fis*br);
        g_Wct[layer][h*HDIM + p]        = __float2half_rn( 2.f * Cre[((size_t)layer*HDIM + h)*PDIM + p]);
        g_Wct[layer][h*HDIM + PDIM + p] = __float2half_rn(-2.f * Cim[((size_t)layer*HDIM + h)*PDIM + p]);
    }
}

// one kernel converting W1, W2 (all layers) and W_out (transpose + fp16)
__global__ void convert_all(const float* __restrict__ W1, const float* __restrict__ W2,
                            const float* __restrict__ Wout)
{
    const int total1 = NLAYERS*HDIM*HDIM;
    const int total  = 2*total1 + 128*HDIM;
    for (int idx = blockIdx.x*blockDim.x + threadIdx.x; idx < total;
         idx += gridDim.x*blockDim.x) {
        if (idx < total1) {
            int l = idx / (HDIM*HDIM), r = idx - l*(HDIM*HDIM);
            int n = r / HDIM, k = r - n*HDIM;
            g_W1t[l][r] = __float2half_rn(W1[(size_t)l*HDIM*HDIM + k*HDIM + n]);
        } else if (idx < 2*total1) {
            int j = idx - total1;
            int l = j / (HDIM*HDIM), r = j - l*(HDIM*HDIM);
            int n = r / HDIM, k = r - n*HDIM;
            g_W2t[l][r] = __float2half_rn(W2[(size_t)l*HDIM*HDIM + k*HDIM + n]);
        } else {
            int j = idx - 2*total1;
            int n = j >> 8, k = j & 255;
            g_Wot[j] = (n < 64) ? __float2half_rn(Wout[k*64 + n]) : __float2half_rn(0.f);
        }
    }
}

// ---------------- LayerNorm (warp per row, float4 loads) -> fp16, optional gelu ----------------
__global__ void ln_act_kernel(const float* __restrict__ X, __half* __restrict__ Y,
                              const float* __restrict__ scale, const float* __restrict__ bias,
                              int gelu_flag)
{
    int row  = blockIdx.x * (blockDim.x >> 5) + (threadIdx.x >> 5);
    int lane = threadIdx.x & 31;
    int c0 = lane * 8;
    const float* x = X + (size_t)row * HDIM;
    float4 a = *(const float4*)(x + c0);
    float4 b = *(const float4*)(x + c0 + 4);
    float v[8] = {a.x, a.y, a.z, a.w, b.x, b.y, b.z, b.w};
    float s = 0.f, s2 = 0.f;
    #pragma unroll
    for (int i = 0; i < 8; i++) { s += v[i]; s2 += v[i]*v[i]; }
    #pragma unroll
    for (int o = 16; o; o >>= 1) {
        s  += __shfl_xor_sync(0xffffffffu, s,  o);
        s2 += __shfl_xor_sync(0xffffffffu, s2, o);
    }
    float mu  = s  * (1.f/HDIM);
    float var = s2 * (1.f/HDIM) - mu*mu;
    float rs  = rsqrtf(var + 1e-6f);
    float4 sc0 = *(const float4*)(scale + c0);
    float4 sc1 = *(const float4*)(scale + c0 + 4);
    float4 bi0 = *(const float4*)(bias + c0);
    float4 bi1 = *(const float4*)(bias + c0 + 4);
    float scv[8] = {sc0.x, sc0.y, sc0.z, sc0.w, sc1.x, sc1.y, sc1.z, sc1.w};
    float biv[8] = {bi0.x, bi0.y, bi0.z, bi0.w, bi1.x, bi1.y, bi1.z, bi1.w};
    __half out[8];
    #pragma unroll
    for (int i = 0; i < 8; i++) {
        float n = (v[i] - mu) * rs * scv[i] + biv[i];
        if (gelu_flag) {
            float t = 0.7978845608028654f * (n + 0.044715f * n*n*n);
            n = 0.5f * n * (1.f + tanhf(t));
        }
        out[i] = __float2half_rn(n);
    }
    *(uint4*)(Y + (size_t)row*HDIM + c0) = *(uint4*)out;
}

// ---------------- chunked diagonal complex scan (on scaled Bu) ----------------
__global__ void scanA_kernel(const float* __restrict__ Bu, int layer)
{
    int c = blockIdx.x, p = threadIdx.x;
    float2 lam = g_lam[layer][p];
    float xr = 0.f, xi = 0.f;
    const float* b = Bu + (size_t)c * TCHUNK * HDIM;
    for (int t = 0; t < TCHUNK; t++) {
        float br = b[t*HDIM + p], bi = b[t*HDIM + PDIM + p];
        float nr = lam.x*xr - lam.y*xi + br;
        float ni = lam.x*xi + lam.y*xr + bi;
        xr = nr; xi = ni;
    }
    g_E[c*PDIM + p] = make_float2(xr, xi);
}

// scanC with inline chunk-prefix; output descaled by 1/s_p then fp16-rounded
__global__ void scanC_kernel(const float* __restrict__ Bu, __half* __restrict__ XS, int layer)
{
    int c = blockIdx.x, p = threadIdx.x;
    float2 lamT = g_lamT[layer][p];
    float2 lam  = g_lam[layer][p];
    float inv   = g_sinv[layer][p];
    float xr = 0.f, xi = 0.f;
    for (int j = 0; j < c; j++) {
        float2 e = g_E[j*PDIM + p];
        float nr = lamT.x*xr - lamT.y*xi + e.x;
        float ni = lamT.x*xi + lamT.y*xr + e.y;
        xr = nr; xi = ni;
    }
    const float* b = Bu + (size_t)c * TCHUNK * HDIM;
    __half* o = XS + (size_t)c * TCHUNK * HDIM;
    for (int t = 0; t < TCHUNK; t++) {
        float br = b[t*HDIM + p], bi = b[t*HDIM + PDIM + p];
        float nr = lam.x*xr - lam.y*xi + br;
        float ni = lam.x*xi + lam.y*xr + bi;
        xr = nr; xi = ni;
        o[t*HDIM + p]        = __float2half_rn(xr * inv);
        o[t*HDIM + PDIM + p] = __float2half_rn(xi * inv);
    }
}

// ---------------- fp16 mma GEMM (cp.async double-buffered) ----------------
#define SPAD 40                       // smem row stride in halves (80B, 16B-aligned)
#define BUFSZ (128*SPAD*2)            // 10240 B per operand buffer
#define SMEM_G4 (4*BUFSZ)             // plain: [A,B] x 2 bufs = 40960
#define SMEM_G6 (6*BUFSZ)             // GLU:  [A,B1,B2] x 2 bufs = 61440

struct LaneAddr { int a_off, b_off; };
__device__ __forceinline__ LaneAddr lane_addr(int lane, int wm, int wn) {
    LaneAddr la;
    int a_r = lane & 15, a_c = (lane >> 4) * 8;
    int b_q = lane >> 3, b_r = lane & 7;
    int b_n_add = (b_q >> 1) * 8 + b_r;
    int b_k_add = (b_q & 1) * 8;
    la.a_off = (wm + a_r)*SPAD + a_c;
    la.b_off = (wn + b_n_add)*SPAD + b_k_add;
    return la;
}

// C[m0:+128, n0:+128] = A[m0:,K=256] * B^T[n0:,K=256]  (B stored [N][K])
// 256 threads, 8 warps (2M x 4N), warp tile 64x32, 2 CTAs/SM
__global__ __launch_bounds__(256, 2) void mma_gemm(
    const __half* __restrict__ A, const __half* __restrict__ B,
    float* __restrict__ C, int ldc, int nvalid,
    const float* __restrict__ bias,
    const __half* __restrict__ U, const float* __restrict__ Dv)
{
    extern __shared__ __align__(16) char smem[];
    uint32_t sb = smem_u32(smem);
    int tid = threadIdx.x;
    int wid = tid >> 5, lane = tid & 31;
    int m0 = blockIdx.y * 128;
    int n0 = blockIdx.x * 128;
    int wm = (wid >> 2) * 64;    // 0 or 64
    int wn = (wid & 3) * 32;     // 0,32,64,96

    float acc[4][4][4];
    #pragma unroll
    for (int i = 0; i < 4; i++)
        #pragma unroll
        for (int j = 0; j < 4; j++)
            #pragma unroll
            for (int q = 0; q < 4; q++) acc[i][j][q] = 0.f;

    #define STAGE(k0, buf) do { \
        uint32_t ab = sb + (buf)*2*BUFSZ; \
        uint32_t bb = ab + BUFSZ; \
        _Pragma("unroll") \
        for (int i = 0; i < 2; i++) { \
            int idx = tid + i*256; \
            int r = idx >> 2, cg = (idx & 3) * 8; \
            uint32_t so = (uint32_t)((r*SPAD + cg) * 2); \
            cp16(ab + so, A + (size_t)(m0 + r)*HDIM + (k0) + cg); \
            cp16(bb + so, B + (size_t)(n0 + r)*HDIM + (k0) + cg); \
        } \
        CP_COMMIT(); } while (0)

    LaneAddr la = lane_addr(lane, wm, wn);

    STAGE(0, 0);
    for (int kc = 0; kc < 8; kc++) {
        if (kc < 7) STAGE((kc+1)*32, (kc+1) & 1);
        if (kc < 7) CP_WAIT1(); else CP_WAIT0();
        __syncthreads();
        uint32_t bbuf = sb + (kc & 1)*2*BUFSZ;
        uint32_t aA = bbuf, aB = bbuf + BUFSZ;
        #pragma unroll
        for (int ks = 0; ks < 2; ks++) {
            uint32_t bh[2][4];
            #pragma unroll
            for (int nf2 = 0; nf2 < 2; nf2++) {
                uint32_t boff = (uint32_t)((la.b_off + nf2*16*SPAD + ks*16) * 2);
                ldm4(bh[nf2], aB + boff);
            }
            uint32_t ah[4][4];
            #pragma unroll
            for (int mf = 0; mf < 4; mf++) {
                uint32_t aoff = (uint32_t)((la.a_off + mf*16*SPAD + ks*16) * 2);
                ldm4(ah[mf], aA + aoff);
            }
            #pragma unroll
            for (int mf = 0; mf < 4; mf++)
                #pragma unroll
                for (int nf = 0; nf < 4; nf++)
                    mma_f16(acc[mf][nf], ah[mf], &bh[nf >> 1][(nf & 1)*2]);
        }
        __syncthreads();
    }
    #undef STAGE

    int tr = lane >> 2, tc = (lane & 3) * 2;
    #pragma unroll
    for (int mf = 0; mf < 4; mf++) {
        #pragma unroll
        for (int nf = 0; nf < 4; nf++) {
            int col = n0 + wn + nf*8 + tc;
            if (col < nvalid) {
                #pragma unroll
                for (int hrow = 0; hrow < 2; hrow++) {
                    int m = m0 + wm + mf*16 + tr + hrow*8;
                    float v0 = acc[mf][nf][hrow*2+0];
                    float v1 = acc[mf][nf][hrow*2+1];
                    if (bias) { v0 += bias[col]; v1 += bias[col+1]; }
                    if (U) {
                        size_t ub = (size_t)m*HDIM + col;
                        v0 += __half2float(U[ub])   * Dv[col];
                        v1 += __half2float(U[ub+1]) * Dv[col+1];
                    }
                    *(float2*)(C + (size_t)m*ldc + col) = make_float2(v0, v1);
                }
            }
        }
    }
}

// ---- fused GLU GEMM pair: x += (A@W1^T+b1) * sigmoid(A@W2^T+b2); optional fp16 copy ----
__global__ __launch_bounds__(256) void mma_gemm_glu(
    const __half* __restrict__ A,
    const __half* __restrict__ B1, const __half* __restrict__ B2,
    const float* __restrict__ b1, const float* __restrict__ b2,
    float* __restrict__ X, __half* __restrict__ Xr, int emit_round)
{
    extern __shared__ __align__(16) char smem[];
    uint32_t sb = smem_u32(smem);
    int tid = threadIdx.x;
    int wid = tid >> 5, lane = tid & 31;
    int m0 = blockIdx.y * 128;
    int n0 = blockIdx.x * 128;
    int wm = (wid >> 2) * 64;
    int wn = (wid & 3) * 32;

    float acc1[4][4][4], acc2[4][4][4];
    #pragma unroll
    for (int i = 0; i < 4; i++)
        #pragma unroll
        for (int j = 0; j < 4; j++)
            #pragma unroll
            for (int q = 0; q < 4; q++) { acc1[i][j][q] = 0.f; acc2[i][j][q] = 0.f; }

    #define STAGE6(k0, buf) do { \
        uint32_t ab  = sb + (buf)*3*BUFSZ; \
        uint32_t bb1 = ab + BUFSZ; \
        uint32_t bb2 = ab + 2*BUFSZ; \
        _Pragma("unroll") \
        for (int i = 0; i < 2; i++) { \
            int idx = tid + i*256; \
            int r = idx >> 2, cg = (idx & 3) * 8; \
            uint32_t so = (uint32_t)((r*SPAD + cg) * 2); \
            cp16(ab  + so, A  + (size_t)(m0 + r)*HDIM + (k0) + cg); \
            cp16(bb1 + so, B1 + (size_t)(n0 + r)*HDIM + (k0) + cg); \
            cp16(bb2 + so, B2 + (size_t)(n0 + r)*HDIM + (k0) + cg); \
        } \
        CP_COMMIT(); } while (0)

    LaneAddr la = lane_addr(lane, wm, wn);

    STAGE6(0, 0);
    for (int kc = 0; kc < 8; kc++) {
        if (kc < 7) STAGE6((kc+1)*32, (kc+1) & 1);
        if (kc < 7) CP_WAIT1(); else CP_WAIT0();
        __syncthreads();
        uint32_t ab = sb + (kc & 1)*3*BUFSZ;
        #pragma unroll
        for (int ks = 0; ks < 2; ks++) {
            uint32_t ah[4][4];
            #pragma unroll
            for (int mf = 0; mf < 4; mf++) {
                uint32_t aoff = (uint32_t)((la.a_off + mf*16*SPAD + ks*16) * 2);
                ldm4(ah[mf], ab + aoff);
            }
            #pragma unroll
            for (int mat = 0; mat < 2; mat++) {
                uint32_t aB = ab + (1 + mat)*BUFSZ;
                uint32_t bh[2][4];
                #pragma unroll
                for (int nf2 = 0; nf2 < 2; nf2++) {
                    uint32_t boff = (uint32_t)((la.b_off + nf2*16*SPAD + ks*16) * 2);
                    ldm4(bh[nf2], aB + boff);
                }
                #pragma unroll
                for (int mf = 0; mf < 4; mf++)
                    #pragma unroll
                    for (int nf = 0; nf < 4; nf++)
                        mma_f16(mat ? acc2[mf][nf] : acc1[mf][nf],
                                ah[mf], &bh[nf >> 1][(nf & 1)*2]);
            }
        }
        __syncthreads();
    }
    #undef STAGE6

    int tr = lane >> 2, tc = (lane & 3) * 2;
    #pragma unroll
    for (int mf = 0; mf < 4; mf++) {
        #pragma unroll
        for (int nf = 0; nf < 4; nf++) {
            int col = n0 + wn + nf*8 + tc;
            #pragma unroll
            for (int hrow = 0; hrow < 2; hrow++) {
                int m = m0 + wm + mf*16 + tr + hrow*8;
                size_t xi = (size_t)m*HDIM + col;
                float u0 = acc1[mf][nf][hrow*2+0] + b1[col];
                float u1 = acc1[mf][nf][hrow*2+1] + b1[col+1];
                float w0 = acc2[mf][nf][hrow*2+0] + b2[col];
                float w1 = acc2[mf][nf][hrow*2+1] + b2[col+1];
                float2 xv = *(float2*)(X + xi);
                xv.x += u0 / (1.f + expf(-w0));
                xv.y += u1 / (1.f + expf(-w1));
                *(float2*)(X + xi) = xv;
                if (emit_round) {
                    Xr[xi]   = __float2half_rn(xv.x);
                    Xr[xi+1] = __float2half_rn(xv.y);
                }
            }
        }
    }
}

// ---------------- host launch ----------------
extern "C" void kernel_launch(void* const* d_in, const int* in_sizes, int n_in,
                              void* d_out, int out_size)
{
    const float* latent     = (const float*)d_in[0];
    const float* W_expand   = (const float*)d_in[1];
    const float* b_expand   = (const float*)d_in[2];
    const float* norm_scale = (const float*)d_in[3];
    const float* norm_bias  = (const float*)d_in[4];
    const float* Lambda_re  = (const float*)d_in[5];
    const float* Lambda_im  = (const float*)d_in[6];
    const float* B_re       = (const float*)d_in[7];
    const float* B_im       = (const float*)d_in[8];
    const float* C_re       = (const float*)d_in[9];
    const float* C_im       = (const float*)d_in[10];
    const float* Dmat       = (const float*)d_in[11];
    const float* log_step   = (const float*)d_in[12];
    const float* W1         = (const float*)d_in[13];
    const float* b1         = (const float*)d_in[14];
    const float* W2         = (const float*)d_in[15];
    const float* b2         = (const float*)d_in[16];
    const float* W_out      = (const float*)d_in[17];
    const float* b_out      = (const float*)d_in[18];
    float* out = (float*)d_out;

    cudaFuncSetAttribute(mma_gemm,     cudaFuncAttributeMaxDynamicSharedMemorySize, SMEM_G4);
    cudaFuncSetAttribute(mma_gemm_glu, cudaFuncAttributeMaxDynamicSharedMemorySize, SMEM_G6);

    float *p_x, *p_bu, *p_t1;
    __half *p_h, *p_xs, *p_xh;
    __half *p_Wbt, *p_Wct, *p_W1t, *p_W2t, *p_Wot;
    cudaGetSymbolAddress((void**)&p_x,   g_x);
    cudaGetSymbolAddress((void**)&p_bu,  g_bu);
    cudaGetSymbolAddress((void**)&p_t1,  g_t1);
    cudaGetSymbolAddress((void**)&p_h,   g_h);
    cudaGetSymbolAddress((void**)&p_xs,  g_xs);
    cudaGetSymbolAddress((void**)&p_xh,  g_xh);
    cudaGetSymbolAddress((void**)&p_Wbt, g_Wbt);
    cudaGetSymbolAddress((void**)&p_Wct, g_Wct);
    cudaGetSymbolAddress((void**)&p_W1t, g_W1t);
    cudaGetSymbolAddress((void**)&p_W2t, g_W2t);
    cudaGetSymbolAddress((void**)&p_Wot, g_Wot);

    // setup
    expand_kernel<<<1, HDIM>>>(latent, W_expand, b_expand);
    broadcast_kernel<<<1024, 256>>>();
    setup_params<<<NLAYERS, PDIM>>>(Lambda_re, Lambda_im, B_re, B_im, C_re, C_im, log_step);
    convert_all<<<2176, 256>>>(W1, W2, W_out);

    dim3 gblk(256);
    dim3 ggrid(2, L_SEQ/128);   // (N tiles, M tiles)

    for (int i = 0; i < NLAYERS; i++) {
        const float* sc = norm_scale + i*HDIM;
        const float* bi = norm_bias  + i*HDIM;
        size_t wo = (size_t)i*HDIM*HDIM;
        // 1. pre-norm: h = LN(x) -> fp16
        ln_act_kernel<<<L_SEQ/8, 256>>>(p_x, p_h, sc, bi, 0);
        // 2. Bu' = h @ Wb'  (row-scaled)
        mma_gemm<<<ggrid, gblk, SMEM_G4>>>(p_h, p_Wbt + wo, p_bu, HDIM, HDIM,
                                           nullptr, nullptr, nullptr);
        // 3. scan on scaled Bu; output descaled fp16
        scanA_kernel<<<NCHUNK, PDIM>>>(p_bu, i);
        scanC_kernel<<<NCHUNK, PDIM>>>(p_bu, p_xs, i);
        // 4. t1 = xs @ Wc + h*D
        mma_gemm<<<ggrid, gblk, SMEM_G4>>>(p_xs, p_Wct + wo, p_t1, HDIM, HDIM,
                                           nullptr, p_h, Dmat + i*HDIM);
        // 5. h = gelu(LN(t1)) -> fp16
        ln_act_kernel<<<L_SEQ/8, 256>>>(p_t1, p_h, sc, bi, 1);
        // 6. fused GLU pair + gate + residual (+ fp16 x copy on last layer)
        mma_gemm_glu<<<ggrid, gblk, SMEM_G6>>>(p_h, p_W1t + wo, p_W2t + wo,
                                               b1 + i*HDIM, b2 + i*HDIM,
                                               p_x, p_xh, i == NLAYERS-1 ? 1 : 0);
    }
    // output head: out = x @ W_out + b_out  (N=64, padded B to 128 rows)
    dim3 hgrid(1, L_SEQ/128);
    mma_gemm<<<hgrid, gblk, SMEM_G4>>>(p_xh, p_Wot, out, 64, 64,
                                       b_out, nullptr, nullptr);
}

// round 16
// speedup vs baseline: 3.3361x; 1.0009x over previous
#include <cuda_runtime.h>
#include <cuda_fp16.h>
#include <math.h>
#include <stdint.h>

#define L_SEQ   32768
#define HDIM    256
#define PDIM    128
#define NLAYERS 4
#define NCHUNK  256
#define TCHUNK  128

// ---------------- scratch (static __device__, no allocation) ----------------
__device__ float  g_x  [L_SEQ*HDIM];
__device__ float  g_bu [L_SEQ*HDIM];
__device__ __half g_h  [L_SEQ*HDIM];   // LN output (fp16)
__device__ __half g_xs [L_SEQ*HDIM];   // scan output (fp16, descaled)
__device__ __half g_xh [L_SEQ*HDIM];   // rounded x for head
// transposed fp16 weights: [N][K] layout, K contiguous
__device__ __half g_Wbt[NLAYERS][HDIM*HDIM];   // row-scaled by s_p
__device__ __half g_Wct[NLAYERS][HDIM*HDIM];
__device__ __half g_W1t[NLAYERS][HDIM*HDIM];
__device__ __half g_W2t[NLAYERS][HDIM*HDIM];
__device__ __half g_Wot[128*HDIM];     // W_out^T zero-padded to 128 rows
__device__ float2 g_lam [NLAYERS][PDIM];
__device__ float2 g_lamT[NLAYERS][PDIM];
__device__ float  g_sinv[NLAYERS][PDIM];   // 1/s_p (power of two)
__device__ float2 g_E [NCHUNK*PDIM];
__device__ float  g_x0[HDIM];

// ---------------- PTX helpers ----------------
__device__ __forceinline__ uint32_t smem_u32(const void* p) {
    uint32_t a;
    asm("{ .reg .u64 t; cvta.to.shared.u64 t, %1; cvt.u32.u64 %0, t; }" : "=r"(a) : "l"(p));
    return a;
}
__device__ __forceinline__ void ldm4(uint32_t* r, uint32_t addr) {
    asm volatile("ldmatrix.sync.aligned.m8n8.x4.shared.b16 {%0,%1,%2,%3}, [%4];"
                 : "=r"(r[0]), "=r"(r[1]), "=r"(r[2]), "=r"(r[3]) : "r"(addr));
}
__device__ __forceinline__ void mma_f16(float* c, const uint32_t* a, const uint32_t* b) {
    asm volatile("mma.sync.aligned.m16n8k16.row.col.f32.f16.f16.f32 "
                 "{%0,%1,%2,%3}, {%4,%5,%6,%7}, {%8,%9}, {%0,%1,%2,%3};"
                 : "+f"(c[0]), "+f"(c[1]), "+f"(c[2]), "+f"(c[3])
                 : "r"(a[0]), "r"(a[1]), "r"(a[2]), "r"(a[3]), "r"(b[0]), "r"(b[1]));
}
__device__ __forceinline__ void cp16(uint32_t saddr, const void* gaddr) {
    asm volatile("cp.async.cg.shared.global [%0], [%1], 16;" :: "r"(saddr), "l"(gaddr));
}
#define CP_COMMIT() asm volatile("cp.async.commit_group;" ::: "memory")
#define CP_WAIT1()  asm volatile("cp.async.wait_group 1;" ::: "memory")
#define CP_WAIT0()  asm volatile("cp.async.wait_group 0;" ::: "memory")

__device__ __forceinline__ float gelu_f(float n) {
    float t = 0.7978845608028654f * (n + 0.044715f * n*n*n);
    return 0.5f * n * (1.f + tanhf(t));
}

// ---------------- setup kernels ----------------
__global__ void expand_kernel(const float* __restrict__ latent,
                              const float* __restrict__ W,
                              const float* __restrict__ b)
{
    int h = threadIdx.x;
    float s = 0.f;
    for (int l = 0; l < HDIM; l++) s += latent[l] * W[l*HDIM + h];
    s += b[h];
    g_x0[h] = s > 0.f ? s : 0.01f * s;
}

__global__ void broadcast_kernel()
{
    size_t n = (size_t)L_SEQ * HDIM / 4;
    const float4* src = (const float4*)g_x0;
    float4* dst = (float4*)g_x;
    for (size_t i = (size_t)blockIdx.x*blockDim.x + threadIdx.x; i < n;
         i += (size_t)gridDim.x*blockDim.x)
        dst[i] = src[i & (HDIM/4 - 1)];
}

__global__ void setup_params(const float* __restrict__ Lre, const float* __restrict__ Lim,
                             const float* __restrict__ Bre, const float* __restrict__ Bim,
                             const float* __restrict__ Cre, const float* __restrict__ Cim,
                             const float* __restrict__ log_step)
{
    int layer = blockIdx.x;
    int p = threadIdx.x;                 // 128 threads
    float step = expf(log_step[layer*PDIM + p]);
    float lr = Lre[layer*PDIM + p], li = Lim[layer*PDIM + p];
    float er  = expf(lr*step);
    float lbr = er * cosf(li*step);
    float lbi = er * sinf(li*step);
    g_lam[layer][p] = make_float2(lbr, lbi);
    float tr = lbr, ti = lbi;
    #pragma unroll
    for (int i = 0; i < 7; i++) { float nr2 = tr*tr - ti*ti; ti = 2.f*tr*ti; tr = nr2; }
    g_lamT[layer][p] = make_float2(tr, ti);
    float nr = lbr - 1.f, ni = lbi;
    float den = lr*lr + li*li;
    float fr = (nr*lr + ni*li) / den;
    float fi = (ni*lr - nr*li) / den;
    float fmag = sqrtf(fr*fr + fi*fi);
    float s = exp2f(rintf(-log2f(fmag)));   // exact power of two ~ 1/|f|
    g_sinv[layer][p] = 1.f / s;
    float frs = fr * s, fis = fi * s;
    const float* brp = Bre + ((size_t)layer*PDIM + p)*HDIM;
    const float* bip = Bim + ((size_t)layer*PDIM + p)*HDIM;
    for (int h = 0; h < HDIM; h++) {
        float br = brp[h], bi = bip[h];
        g_Wbt[layer][p*HDIM + h]        = __float2half_rn(frs*br - fis*bi);
        g_Wbt[layer][(PDIM+p)*HDIM + h] = __float2half_rn(frs*bi + fis*br);
        g_Wct[layer][h*HDIM + p]        = __float2half_rn( 2.f * Cre[((size_t)layer*HDIM + h)*PDIM + p]);
        g_Wct[layer][h*HDIM + PDIM + p] = __float2half_rn(-2.f * Cim[((size_t)layer*HDIM + h)*PDIM + p]);
    }
}

// one kernel converting W1, W2 (all layers) and W_out (transpose + fp16)
__global__ void convert_all(const float* __restrict__ W1, const float* __restrict__ W2,
                            const float* __restrict__ Wout)
{
    const int total1 = NLAYERS*HDIM*HDIM;
    const int total  = 2*total1 + 128*HDIM;
    for (int idx = blockIdx.x*blockDim.x + threadIdx.x; idx < total;
         idx += gridDim.x*blockDim.x) {
        if (idx < total1) {
            int l = idx / (HDIM*HDIM), r = idx - l*(HDIM*HDIM);
            int n = r / HDIM, k = r - n*HDIM;
            g_W1t[l][r] = __float2half_rn(W1[(size_t)l*HDIM*HDIM + k*HDIM + n]);
        } else if (idx < 2*total1) {
            int j = idx - total1;
            int l = j / (HDIM*HDIM), r = j - l*(HDIM*HDIM);
            int n = r / HDIM, k = r - n*HDIM;
            g_W2t[l][r] = __float2half_rn(W2[(size_t)l*HDIM*HDIM + k*HDIM + n]);
        } else {
            int j = idx - 2*total1;
            int n = j >> 8, k = j & 255;
            g_Wot[j] = (n < 64) ? __float2half_rn(Wout[k*64 + n]) : __float2half_rn(0.f);
        }
    }
}

// ---------------- LayerNorm (warp per row, float4 loads) -> fp16 (prenorm only) ----------------
__global__ void ln_act_kernel(const float* __restrict__ X, __half* __restrict__ Y,
                              const float* __restrict__ scale, const float* __restrict__ bias)
{
    int row  = blockIdx.x * (blockDim.x >> 5) + (threadIdx.x >> 5);
    int lane = threadIdx.x & 31;
    int c0 = lane * 8;
    const float* x = X + (size_t)row * HDIM;
    float4 a = *(const float4*)(x + c0);
    float4 b = *(const float4*)(x + c0 + 4);
    float v[8] = {a.x, a.y, a.z, a.w, b.x, b.y, b.z, b.w};
    float s = 0.f, s2 = 0.f;
    #pragma unroll
    for (int i = 0; i < 8; i++) { s += v[i]; s2 += v[i]*v[i]; }
    #pragma unroll
    for (int o = 16; o; o >>= 1) {
        s  += __shfl_xor_sync(0xffffffffu, s,  o);
        s2 += __shfl_xor_sync(0xffffffffu, s2, o);
    }
    float mu  = s  * (1.f/HDIM);
    float var = s2 * (1.f/HDIM) - mu*mu;
    float rs  = rsqrtf(var + 1e-6f);
    float4 sc0 = *(const float4*)(scale + c0);
    float4 sc1 = *(const float4*)(scale + c0 + 4);
    float4 bi0 = *(const float4*)(bias + c0);
    float4 bi1 = *(const float4*)(bias + c0 + 4);
    float scv[8] = {sc0.x, sc0.y, sc0.z, sc0.w, sc1.x, sc1.y, sc1.z, sc1.w};
    float biv[8] = {bi0.x, bi0.y, bi0.z, bi0.w, bi1.x, bi1.y, bi1.z, bi1.w};
    __half out[8];
    #pragma unroll
    for (int i = 0; i < 8; i++)
        out[i] = __float2half_rn((v[i] - mu) * rs * scv[i] + biv[i]);
    *(uint4*)(Y + (size_t)row*HDIM + c0) = *(uint4*)out;
}

// ---------------- chunked diagonal complex scan (on scaled Bu) ----------------
__global__ void scanA_kernel(const float* __restrict__ Bu, int layer)
{
    int c = blockIdx.x, p = threadIdx.x;
    float2 lam = g_lam[layer][p];
    float xr = 0.f, xi = 0.f;
    const float* b = Bu + (size_t)c * TCHUNK * HDIM;
    for (int t = 0; t < TCHUNK; t++) {
        float br = b[t*HDIM + p], bi = b[t*HDIM + PDIM + p];
        float nr = lam.x*xr - lam.y*xi + br;
        float ni = lam.x*xi + lam.y*xr + bi;
        xr = nr; xi = ni;
    }
    g_E[c*PDIM + p] = make_float2(xr, xi);
}

// scanC with inline chunk-prefix; output descaled by 1/s_p then fp16-rounded
__global__ void scanC_kernel(const float* __restrict__ Bu, __half* __restrict__ XS, int layer)
{
    int c = blockIdx.x, p = threadIdx.x;
    float2 lamT = g_lamT[layer][p];
    float2 lam  = g_lam[layer][p];
    float inv   = g_sinv[layer][p];
    float xr = 0.f, xi = 0.f;
    for (int j = 0; j < c; j++) {
        float2 e = g_E[j*PDIM + p];
        float nr = lamT.x*xr - lamT.y*xi + e.x;
        float ni = lamT.x*xi + lamT.y*xr + e.y;
        xr = nr; xi = ni;
    }
    const float* b = Bu + (size_t)c * TCHUNK * HDIM;
    __half* o = XS + (size_t)c * TCHUNK * HDIM;
    for (int t = 0; t < TCHUNK; t++) {
        float br = b[t*HDIM + p], bi = b[t*HDIM + PDIM + p];
        float nr = lam.x*xr - lam.y*xi + br;
        float ni = lam.x*xi + lam.y*xr + bi;
        xr = nr; xi = ni;
        o[t*HDIM + p]        = __float2half_rn(xr * inv);
        o[t*HDIM + PDIM + p] = __float2half_rn(xi * inv);
    }
}

// ---------------- fp16 mma GEMM common ----------------
#define SPAD 40                       // smem row stride in halves (80B, 16B-aligned)
#define BUFSZ (128*SPAD*2)            // 10240 B per 128-row operand buffer
#define SMEM_G4 (4*BUFSZ)             // plain: [A,B] x 2 bufs
#define SMEM_G6 (6*BUFSZ)             // GLU:  [A,B1,B2] x 2 bufs
#define DLN_ABUF  BUFSZ               // 10240 (A: 128 rows)
#define DLN_BBUF  (256*SPAD*2)        // 20480 (B: 256 rows)
#define DLN_STAGE (DLN_ABUF + DLN_BBUF)
#define SMEM_DLN  (2*DLN_STAGE)       // 61440

struct LaneAddr { int a_off, b_off; };
__device__ __forceinline__ LaneAddr lane_addr(int lane, int wm, int wn) {
    LaneAddr la;
    int a_r = lane & 15, a_c = (lane >> 4) * 8;
    int b_q = lane >> 3, b_r = lane & 7;
    int b_n_add = (b_q >> 1) * 8 + b_r;
    int b_k_add = (b_q & 1) * 8;
    la.a_off = (wm + a_r)*SPAD + a_c;
    la.b_off = (wn + b_n_add)*SPAD + b_k_add;
    return la;
}

// C[m0:+128, n0:+128] = A[m0:,K=256] * B^T[n0:,K=256]  (B stored [N][K])
// 256 threads, 8 warps (2M x 4N), warp tile 64x32, 2 CTAs/SM
__global__ __launch_bounds__(256, 2) void mma_gemm(
    const __half* __restrict__ A, const __half* __restrict__ B,
    float* __restrict__ C, int ldc, int nvalid,
    const float* __restrict__ bias)
{
    extern __shared__ __align__(16) char smem[];
    uint32_t sb = smem_u32(smem);
    int tid = threadIdx.x;
    int wid = tid >> 5, lane = tid & 31;
    int m0 = blockIdx.y * 128;
    int n0 = blockIdx.x * 128;
    int wm = (wid >> 2) * 64;
    int wn = (wid & 3) * 32;

    float acc[4][4][4];
    #pragma unroll
    for (int i = 0; i < 4; i++)
        #pragma unroll
        for (int j = 0; j < 4; j++)
            #pragma unroll
            for (int q = 0; q < 4; q++) acc[i][j][q] = 0.f;

    #define STAGE(k0, buf) do { \
        uint32_t ab = sb + (buf)*2*BUFSZ; \
        uint32_t bb = ab + BUFSZ; \
        _Pragma("unroll") \
        for (int i = 0; i < 2; i++) { \
            int idx = tid + i*256; \
            int r = idx >> 2, cg = (idx & 3) * 8; \
            uint32_t so = (uint32_t)((r*SPAD + cg) * 2); \
            cp16(ab + so, A + (size_t)(m0 + r)*HDIM + (k0) + cg); \
            cp16(bb + so, B + (size_t)(n0 + r)*HDIM + (k0) + cg); \
        } \
        CP_COMMIT(); } while (0)

    LaneAddr la = lane_addr(lane, wm, wn);

    STAGE(0, 0);
    for (int kc = 0; kc < 8; kc++) {
        if (kc < 7) STAGE((kc+1)*32, (kc+1) & 1);
        if (kc < 7) CP_WAIT1(); else CP_WAIT0();
        __syncthreads();
        uint32_t bbuf = sb + (kc & 1)*2*BUFSZ;
        uint32_t aA = bbuf, aB = bbuf + BUFSZ;
        #pragma unroll
        for (int ks = 0; ks < 2; ks++) {
            uint32_t bh[2][4];
            #pragma unroll
            for (int nf2 = 0; nf2 < 2; nf2++) {
                uint32_t boff = (uint32_t)((la.b_off + nf2*16*SPAD + ks*16) * 2);
                ldm4(bh[nf2], aB + boff);
            }
            uint32_t ah[4][4];
            #pragma unroll
            for (int mf = 0; mf < 4; mf++) {
                uint32_t aoff = (uint32_t)((la.a_off + mf*16*SPAD + ks*16) * 2);
                ldm4(ah[mf], aA + aoff);
            }
            #pragma unroll
            for (int mf = 0; mf < 4; mf++)
                #pragma unroll
                for (int nf = 0; nf < 4; nf++)
                    mma_f16(acc[mf][nf], ah[mf], &bh[nf >> 1][(nf & 1)*2]);
        }
        __syncthreads();
    }
    #undef STAGE

    int tr = lane >> 2, tc = (lane & 3) * 2;
    #pragma unroll
    for (int mf = 0; mf < 4; mf++) {
        #pragma unroll
        for (int nf = 0; nf < 4; nf++) {
            int col = n0 + wn + nf*8 + tc;
            if (col < nvalid) {
                #pragma unroll
                for (int hrow = 0; hrow < 2; hrow++) {
                    int m = m0 + wm + mf*16 + tr + hrow*8;
                    float v0 = acc[mf][nf][hrow*2+0];
                    float v1 = acc[mf][nf][hrow*2+1];
                    if (bias) { v0 += bias[col]; v1 += bias[col+1]; }
                    *(float2*)(C + (size_t)m*ldc + col) = make_float2(v0, v1);
                }
            }
        }
    }
}

// ---- fused t1 GEMM + h*D + LayerNorm + gelu -> h (fp16). CTA tile 128x256, no t1 write ----
__global__ __launch_bounds__(256) void gemm_d_ln(
    const __half* __restrict__ A,      // xs
    const __half* __restrict__ B,      // Wct [256][256]
    const __half* __restrict__ U,      // h (for D term)
    const float* __restrict__ Dv,
    const float* __restrict__ scale, const float* __restrict__ bias,
    __half* __restrict__ Y)            // h out
{
    extern __shared__ __align__(16) char smem[];
    uint32_t sb = smem_u32(smem);
    int tid = threadIdx.x;
    int wid = tid >> 5, lane = tid & 31;
    int m0 = blockIdx.x * 128;
    int wm = (wid >> 2) * 64;    // 0 or 64
    int wn = (wid & 3) * 64;     // 0,64,128,192

    float acc[4][8][4];
    #pragma unroll
    for (int i = 0; i < 4; i++)
        #pragma unroll
        for (int j = 0; j < 8; j++)
            #pragma unroll
            for (int q = 0; q < 4; q++) acc[i][j][q] = 0.f;

    #define STAGED(k0, buf) do { \
        uint32_t ab = sb + (buf)*DLN_STAGE; \
        uint32_t bb = ab + DLN_ABUF; \
        _Pragma("unroll") \
        for (int i = 0; i < 6; i++) { \
            int idx = tid + i*256; \
            if (idx < 512) { \
                int r = idx >> 2, cg = (idx & 3) * 8; \
                cp16(ab + (uint32_t)((r*SPAD + cg)*2), A + (size_t)(m0 + r)*HDIM + (k0) + cg); \
            } else { \
                int j = idx - 512; \
                int r = j >> 2, cg = (j & 3) * 8; \
                cp16(bb + (uint32_t)((r*SPAD + cg)*2), B + (size_t)r*HDIM + (k0) + cg); \
            } \
        } \
        CP_COMMIT(); } while (0)

    LaneAddr la = lane_addr(lane, wm, wn);

    STAGED(0, 0);
    for (int kc = 0; kc < 8; kc++) {
        if (kc < 7) STAGED((kc+1)*32, (kc+1) & 1);
        if (kc < 7) CP_WAIT1(); else CP_WAIT0();
        __syncthreads();
        uint32_t ab = sb + (kc & 1)*DLN_STAGE;
        uint32_t bbuf = ab + DLN_ABUF;
        #pragma unroll
        for (int ks = 0; ks < 2; ks++) {
            uint32_t bh[4][4];
            #pragma unroll
            for (int nf2 = 0; nf2 < 4; nf2++) {
                uint32_t boff = (uint32_t)((la.b_off + nf2*16*SPAD + ks*16) * 2);
                ldm4(bh[nf2], bbuf + boff);
            }
            uint32_t ah[4][4];
            #pragma unroll
            for (int mf = 0; mf < 4; mf++) {
                uint32_t aoff = (uint32_t)((la.a_off + mf*16*SPAD + ks*16) * 2);
                ldm4(ah[mf], ab + aoff);
            }
            #pragma unroll
            for (int mf = 0; mf < 4; mf++)
                #pragma unroll
                for (int nf = 0; nf < 8; nf++)
                    mma_f16(acc[mf][nf], ah[mf], &bh[nf >> 1][(nf & 1)*2]);
        }
        __syncthreads();
    }
    #undef STAGED

    // ---- epilogue: v = acc + U*Dv ; row LN stats ; gelu ; fp16 store ----
    int tr = lane >> 2, tc = (lane & 3) * 2;
    float psum[8], psq[8];
    #pragma unroll
    for (int r = 0; r < 8; r++) { psum[r] = 0.f; psq[r] = 0.f; }

    #pragma unroll
    for (int mf = 0; mf < 4; mf++) {
        #pragma unroll
        for (int hrow = 0; hrow < 2; hrow++) {
            int ml = wm + mf*16 + tr + hrow*8;
            int ridx = mf*2 + hrow;
            #pragma unroll
            for (int nf = 0; nf < 8; nf++) {
                int col = wn + nf*8 + tc;
                size_t ub = (size_t)(m0 + ml)*HDIM + col;
                float v0 = acc[mf][nf][hrow*2+0] + __half2float(U[ub])   * Dv[col];
                float v1 = acc[mf][nf][hrow*2+1] + __half2float(U[ub+1]) * Dv[col+1];
                acc[mf][nf][hrow*2+0] = v0;
                acc[mf][nf][hrow*2+1] = v1;
                psum[ridx] += v0 + v1;
                psq[ridx]  += v0*v0 + v1*v1;
            }
        }
    }
    // reduce across 4 lanes sharing a row (lane bits 0-1)
    #pragma unroll
    for (int r = 0; r < 8; r++) {
        psum[r] += __shfl_xor_sync(0xffffffffu, psum[r], 1);
        psq[r]  += __shfl_xor_sync(0xffffffffu, psq[r],  1);
        psum[r] += __shfl_xor_sync(0xffffffffu, psum[r], 2);
        psq[r]  += __shfl_xor_sync(0xffffffffu, psq[r],  2);
    }
    float* red_sum = (float*)smem;           // [128][4]
    float* red_sq  = (float*)smem + 512;     // [128][4]
    float2* stats  = (float2*)((float*)smem + 1024);  // [128]
    int wn_idx = wid & 3;
    if ((lane & 3) == 0) {
        #pragma unroll
        for (int mf = 0; mf < 4; mf++)
            #pragma unroll
            for (int hrow = 0; hrow < 2; hrow++) {
                int ml = wm + mf*16 + tr + hrow*8;
                int ridx = mf*2 + hrow;
                red_sum[ml*4 + wn_idx] = psum[ridx];
                red_sq [ml*4 + wn_idx] = psq[ridx];
            }
    }
    __syncthreads();
    if (tid < 128) {
        float s = red_sum[tid*4] + red_sum[tid*4+1] + red_sum[tid*4+2] + red_sum[tid*4+3];
        float q = red_sq [tid*4] + red_sq [tid*4+1] + red_sq [tid*4+2] + red_sq [tid*4+3];
        float mu  = s * (1.f/HDIM);
        float var = q * (1.f/HDIM) - mu*mu;
        stats[tid] = make_float2(mu, rsqrtf(var + 1e-6f));
    }
    __syncthreads();
    #pragma unroll
    for (int mf = 0; mf < 4; mf++) {
        #pragma unroll
        for (int hrow = 0; hrow < 2; hrow++) {
            int ml = wm + mf*16 + tr + hrow*8;
            float2 st = stats[ml];
            #pragma unroll
            for (int nf = 0; nf < 8; nf++) {
                int col = wn + nf*8 + tc;
                float n0 = (acc[mf][nf][hrow*2+0] - st.x) * st.y * scale[col]   + bias[col];
                float n1 = (acc[mf][nf][hrow*2+1] - st.x) * st.y * scale[col+1] + bias[col+1];
                __half2 hv = __halves2half2(__float2half_rn(gelu_f(n0)),
                                            __float2half_rn(gelu_f(n1)));
                *(__half2*)(Y + (size_t)(m0 + ml)*HDIM + col) = hv;
            }
        }
    }
}

// ---- fused GLU GEMM pair: x += (A@W1^T+b1) * sigmoid(A@W2^T+b2); optional fp16 copy ----
__global__ __launch_bounds__(256) void mma_gemm_glu(
    const __half* __restrict__ A,
    const __half* __restrict__ B1, const __half* __restrict__ B2,
    const float* __restrict__ b1, const float* __restrict__ b2,
    float* __restrict__ X, __half* __restrict__ Xr, int emit_round)
{
    extern __shared__ __align__(16) char smem[];
    uint32_t sb = smem_u32(smem);
    int tid = threadIdx.x;
    int wid = tid >> 5, lane = tid & 31;
    int m0 = blockIdx.y * 128;
    int n0 = blockIdx.x * 128;
    int wm = (wid >> 2) * 64;
    int wn = (wid & 3) * 32;

    float acc1[4][4][4], acc2[4][4][4];
    #pragma unroll
    for (int i = 0; i < 4; i++)
        #pragma unroll
        for (int j = 0; j < 4; j++)
            #pragma unroll
            for (int q = 0; q < 4; q++) { acc1[i][j][q] = 0.f; acc2[i][j][q] = 0.f; }

    #define STAGE6(k0, buf) do { \
        uint32_t ab  = sb + (buf)*3*BUFSZ; \
        uint32_t bb1 = ab + BUFSZ; \
        uint32_t bb2 = ab + 2*BUFSZ; \
        _Pragma("unroll") \
        for (int i = 0; i < 2; i++) { \
            int idx = tid + i*256; \
            int r = idx >> 2, cg = (idx & 3) * 8; \
            uint32_t so = (uint32_t)((r*SPAD + cg) * 2); \
            cp16(ab  + so, A  + (size_t)(m0 + r)*HDIM + (k0) + cg); \
            cp16(bb1 + so, B1 + (size_t)(n0 + r)*HDIM + (k0) + cg); \
            cp16(bb2 + so, B2 + (size_t)(n0 + r)*HDIM + (k0) + cg); \
        } \
        CP_COMMIT(); } while (0)

    LaneAddr la = lane_addr(lane, wm, wn);

    STAGE6(0, 0);
    for (int kc = 0; kc < 8; kc++) {
        if (kc < 7) STAGE6((kc+1)*32, (kc+1) & 1);
        if (kc < 7) CP_WAIT1(); else CP_WAIT0();
        __syncthreads();
        uint32_t ab = sb + (kc & 1)*3*BUFSZ;
        #pragma unroll
        for (int ks = 0; ks < 2; ks++) {
            uint32_t ah[4][4];
            #pragma unroll
            for (int mf = 0; mf < 4; mf++) {
                uint32_t aoff = (uint32_t)((la.a_off + mf*16*SPAD + ks*16) * 2);
                ldm4(ah[mf], ab + aoff);
            }
            #pragma unroll
            for (int mat = 0; mat < 2; mat++) {
                uint32_t aB = ab + (1 + mat)*BUFSZ;
                uint32_t bh[2][4];
                #pragma unroll
                for (int nf2 = 0; nf2 < 2; nf2++) {
                    uint32_t boff = (uint32_t)((la.b_off + nf2*16*SPAD + ks*16) * 2);
                    ldm4(bh[nf2], aB + boff);
                }
                #pragma unroll
                for (int mf = 0; mf < 4; mf++)
                    #pragma unroll
                    for (int nf = 0; nf < 4; nf++)
                        mma_f16(mat ? acc2[mf][nf] : acc1[mf][nf],
                                ah[mf], &bh[nf >> 1][(nf & 1)*2]);
            }
        }
        __syncthreads();
    }
    #undef STAGE6

    int tr = lane >> 2, tc = (lane & 3) * 2;
    #pragma unroll
    for (int mf = 0; mf < 4; mf++) {
        #pragma unroll
        for (int nf = 0; nf < 4; nf++) {
            int col = n0 + wn + nf*8 + tc;
            #pragma unroll
            for (int hrow = 0; hrow < 2; hrow++) {
                int m = m0 + wm + mf*16 + tr + hrow*8;
                size_t xi = (size_t)m*HDIM + col;
                float u0 = acc1[mf][nf][hrow*2+0] + b1[col];
                float u1 = acc1[mf][nf][hrow*2+1] + b1[col+1];
                float w0 = acc2[mf][nf][hrow*2+0] + b2[col];
                float w1 = acc2[mf][nf][hrow*2+1] + b2[col+1];
                float2 xv = *(float2*)(X + xi);
                xv.x += u0 / (1.f + expf(-w0));
                xv.y += u1 / (1.f + expf(-w1));
                *(float2*)(X + xi) = xv;
                if (emit_round) {
                    Xr[xi]   = __float2half_rn(xv.x);
                    Xr[xi+1] = __float2half_rn(xv.y);
                }
            }
        }
    }
}

// ---------------- host launch ----------------
extern "C" void kernel_launch(void* const* d_in, const int* in_sizes, int n_in,
                              void* d_out, int out_size)
{
    const float* latent     = (const float*)d_in[0];
    const float* W_expand   = (const float*)d_in[1];
    const float* b_expand   = (const float*)d_in[2];
    const float* norm_scale = (const float*)d_in[3];
    const float* norm_bias  = (const float*)d_in[4];
    const float* Lambda_re  = (const float*)d_in[5];
    const float* Lambda_im  = (const float*)d_in[6];
    const float* B_re       = (const float*)d_in[7];
    const float* B_im       = (const float*)d_in[8];
    const float* C_re       = (const float*)d_in[9];
    const float* C_im       = (const float*)d_in[10];
    const float* Dmat       = (const float*)d_in[11];
    const float* log_step   = (const float*)d_in[12];
    const float* W1         = (const float*)d_in[13];
    const float* b1         = (const float*)d_in[14];
    const float* W2         = (const float*)d_in[15];
    const float* b2         = (const float*)d_in[16];
    const float* W_out      = (const float*)d_in[17];
    const float* b_out      = (const float*)d_in[18];
    float* out = (float*)d_out;

    cudaFuncSetAttribute(mma_gemm,     cudaFuncAttributeMaxDynamicSharedMemorySize, SMEM_G4);
    cudaFuncSetAttribute(mma_gemm_glu, cudaFuncAttributeMaxDynamicSharedMemorySize, SMEM_G6);
    cudaFuncSetAttribute(gemm_d_ln,    cudaFuncAttributeMaxDynamicSharedMemorySize, SMEM_DLN);

    float *p_x, *p_bu;
    __half *p_h, *p_xs, *p_xh;
    __half *p_Wbt, *p_Wct, *p_W1t, *p_W2t, *p_Wot;
    cudaGetSymbolAddress((void**)&p_x,   g_x);
    cudaGetSymbolAddress((void**)&p_bu,  g_bu);
    cudaGetSymbolAddress((void**)&p_h,   g_h);
    cudaGetSymbolAddress((void**)&p_xs,  g_xs);
    cudaGetSymbolAddress((void**)&p_xh,  g_xh);
    cudaGetSymbolAddress((void**)&p_Wbt, g_Wbt);
    cudaGetSymbolAddress((void**)&p_Wct, g_Wct);
    cudaGetSymbolAddress((void**)&p_W1t, g_W1t);
    cudaGetSymbolAddress((void**)&p_W2t, g_W2t);
    cudaGetSymbolAddress((void**)&p_Wot, g_Wot);

    // setup
    expand_kernel<<<1, HDIM>>>(latent, W_expand, b_expand);
    broadcast_kernel<<<1024, 256>>>();
    setup_params<<<NLAYERS, PDIM>>>(Lambda_re, Lambda_im, B_re, B_im, C_re, C_im, log_step);
    convert_all<<<2176, 256>>>(W1, W2, W_out);

    dim3 gblk(256);
    dim3 ggrid(2, L_SEQ/128);    // (N tiles, M tiles) for 128x128 kernels
    dim3 dgrid(L_SEQ/128);       // full-row kernel

    for (int i = 0; i < NLAYERS; i++) {
        const float* sc = norm_scale + i*HDIM;
        const float* bi = norm_bias  + i*HDIM;
        size_t wo = (size_t)i*HDIM*HDIM;
        // 1. pre-norm: h = LN(x) -> fp16
        ln_act_kernel<<<L_SEQ/8, 256>>>(p_x, p_h, sc, bi);
        // 2. Bu' = h @ Wb'  (row-scaled)
        mma_gemm<<<ggrid, gblk, SMEM_G4>>>(p_h, p_Wbt + wo, p_bu, HDIM, HDIM, nullptr);
        // 3. scan on scaled Bu; output descaled fp16
        scanA_kernel<<<NCHUNK, PDIM>>>(p_bu, i);
        scanC_kernel<<<NCHUNK, PDIM>>>(p_bu, p_xs, i);
        // 4. h = gelu(LN(xs @ Wc + h*D))  -- fused, t1 never materialized
        gemm_d_ln<<<dgrid, gblk, SMEM_DLN>>>(p_xs, p_Wct + wo, p_h, Dmat + i*HDIM,
                                             sc, bi, p_h);
        // 5. fused GLU pair + gate + residual (+ fp16 x copy on last layer)
        mma_gemm_glu<<<ggrid, gblk, SMEM_G6>>>(p_h, p_W1t + wo, p_W2t + wo,
                                               b1 + i*HDIM, b2 + i*HDIM,
                                               p_x, p_xh, i == NLAYERS-1 ? 1 : 0);
    }
    // output head: out = x @ W_out + b_out  (N=64, padded B to 128 rows)
    dim3 hgrid(1, L_SEQ/128);
    mma_gemm<<<hgrid, gblk, SMEM_G4>>>(p_xh, p_Wot, out, 64, 64, b_out);
}